// round 9
// baseline (speedup 1.0000x reference)
#include <cuda_runtime.h>
#include <cuda_bf16.h>
#include <math.h>

#define K_FR 8
#define B_SZ 8
#define CIN  512
#define COUT 256
#define H_   28
#define W_   28
#define HW   784
#define C4V  1024

// ---------------- scratch (device globals; no allocation at runtime) --------
__device__ __align__(16) float g_pf  [K_FR * B_SZ * COUT * HW];
__device__ __align__(16) float g_x   [B_SZ * COUT * HW];
__device__ __align__(16) float g_x2  [B_SZ * COUT * HW];
__device__ __align__(16) float g_o1  [B_SZ * COUT * HW];
__device__ __align__(16) float g_h   [B_SZ * C4V * HW];
__device__ __align__(16) float g_aS  [B_SZ * HW * HW];
__device__ __align__(16) float g_aC  [B_SZ * COUT * COUT];
__device__ __align__(16) float g_col [B_SZ * COUT * 9 * HW];
__device__ __align__(16) float g_cat [B_SZ * 2 * COUT * HW];
__device__ float g_bnA [4 * COUT];
__device__ float g_bnB [4 * COUT];

// ---------------- 3xBF16 tensor-core GEMM, 2-deep register pipeline ---------
// a*b ~= aH*bH + aH*bL + aL*bH with bf16 hi/lo split (residual ~2^-16), fp32 acc.
// mma.m16n8k16.bf16 covers K=16 per instruction.
// smem row layout (per k-tile of 16): 8 k-pairs as bf16x2 words, interleaved
//   group 4p = {hi(p), hi(p+4), lo(p), lo(p+4)}  -> fragment = one LDS.128.
// Row stride RSTR=20 uints. Double-buffered smem; register staging is TWO
// k-tiles deep so global-load latency hides under one full compute iteration.
// TA: A stored [K,M]; else [M,K].  TB: B stored [N,K]; else [K,N].
// epilogue: v = acc*scale[m]+bias[m]; relu; v = v*gamma + resid[m,n]
// Requires Kd % 16 == 0 (all call sites: 256/512/784/1024/2304).

__device__ __forceinline__ unsigned pack2(float f0, float f1) {   // f0->low, f1->high
    unsigned r;
    asm("cvt.rn.bf16x2.f32 %0, %1, %2;" : "=r"(r) : "f"(f1), "f"(f0));
    return r;
}
__device__ __forceinline__ void split2(float f0, float f1, unsigned& hi, unsigned& lo) {
    hi = pack2(f0, f1);
    float h0 = __uint_as_float(hi << 16);
    float h1 = __uint_as_float(hi & 0xffff0000u);
    lo = pack2(f0 - h0, f1 - h1);
}
__device__ __forceinline__ void mma_bf16(float4& d, const unsigned a[4], const unsigned b[2]) {
    asm volatile(
        "mma.sync.aligned.m16n8k16.row.col.f32.bf16.bf16.f32 "
        "{%0,%1,%2,%3}, {%4,%5,%6,%7}, {%8,%9}, {%0,%1,%2,%3};"
        : "+f"(d.x), "+f"(d.y), "+f"(d.z), "+f"(d.w)
        : "r"(a[0]), "r"(a[1]), "r"(a[2]), "r"(a[3]), "r"(b[0]), "r"(b[1]));
}

#define RSTR 20   // smem row stride in uints
#define BN   128

__device__ __forceinline__ int posH(int p) { return 4 * (p & 3) + (p >> 2); }

template <int TBM, bool TA, bool TB, int MAXB>
__global__ void __launch_bounds__(256, MAXB) gemm_bf(
    const float* __restrict__ A, const float* __restrict__ Bm, float* __restrict__ C,
    int M, int N, int Kd, int lda, int ldb,
    long aS, int aDiv, long bS, long cS,
    const float* __restrict__ scaleC, const float* __restrict__ biasC, long biS,
    int relu, const float* __restrict__ gammaPtr,
    const float* __restrict__ resid, long rS)
{
    extern __shared__ unsigned sm[];
    unsigned* As = sm;                       // [2][TBM][RSTR]
    unsigned* Bs = sm + 2 * TBM * RSTR;      // [2][BN ][RSTR]

    const int z = blockIdx.z;
    A  += (long)(z / aDiv) * aS;
    Bm += (long)z * bS;
    C  += (long)z * cS;
    if (biasC) biasC += (long)(z / aDiv) * biS;
    if (resid) resid += (long)z * rS;

    const int tid  = threadIdx.x;
    const int lane = tid & 31, warp = tid >> 5;
    constexpr int MI = TBM / 32;            // 2 or 4
    constexpr int NJ = 4;
    constexpr int UA = TBM / 32;            // A pairs per thread
    constexpr int UB = 4;                   // B pairs per thread
    constexpr int LBM = (TBM == 128) ? 7 : 6;
    const int wm = (warp >> 2) * (TBM / 2);
    const int wn = (warp & 3) * 32;
    const int m0 = blockIdx.y * TBM, n0 = blockIdx.x * BN;

    float4 acc[MI][NJ];
    #pragma unroll
    for (int i = 0; i < MI; ++i)
        #pragma unroll
        for (int j = 0; j < NJ; ++j)
            acc[i][j] = make_float4(0.f, 0.f, 0.f, 0.f);

    float2 vaR[2][UA], vbR[2][UB];

    auto loadA = [&](float2* va, int k0) {
        if (!TA) {   // A [M,K]: 8 threads per row, float2 (k-pair) each
            #pragma unroll
            for (int t = 0; t < UA; ++t) {
                int i = tid + t * 256;
                int p = i & 7, m = i >> 3;
                int gm = m0 + m;
                va[t] = (gm < M) ? *(const float2*)&A[(long)gm * lda + k0 + 2 * p]
                                 : make_float2(0.f, 0.f);
            }
        } else {     // A [K,M]: coalesced across m, two strided rows per pair
            int m = tid & (TBM - 1), psel = tid >> LBM;
            int gm = m0 + m;
            #pragma unroll
            for (int t = 0; t < UA; ++t) {
                int p = psel * UA + t;
                float f0 = 0.f, f1 = 0.f;
                if (gm < M) {
                    f0 = A[(long)(k0 + 2 * p) * lda + gm];
                    f1 = A[(long)(k0 + 2 * p + 1) * lda + gm];
                }
                va[t] = make_float2(f0, f1);
            }
        }
    };
    auto loadB = [&](float2* vb, int k0) {
        if (TB) {    // B [N,K]: 8 threads per row, float2 each
            #pragma unroll
            for (int t = 0; t < UB; ++t) {
                int i = tid + t * 256;
                int p = i & 7, n = i >> 3;
                int gn = n0 + n;
                vb[t] = (gn < N) ? *(const float2*)&Bm[(long)gn * ldb + k0 + 2 * p]
                                 : make_float2(0.f, 0.f);
            }
        } else {     // B [K,N]: coalesced across n, two strided rows per pair
            int n = tid & 127, psel = tid >> 7;
            int gn = n0 + n;
            #pragma unroll
            for (int t = 0; t < UB; ++t) {
                int p = psel * UB + t;
                float f0 = 0.f, f1 = 0.f;
                if (gn < N) {
                    f0 = Bm[(long)(k0 + 2 * p) * ldb + gn];
                    f1 = Bm[(long)(k0 + 2 * p + 1) * ldb + gn];
                }
                vb[t] = make_float2(f0, f1);
            }
        }
    };
    auto storeA = [&](const float2* va, int buf) {
        if (!TA) {
            #pragma unroll
            for (int t = 0; t < UA; ++t) {
                int i = tid + t * 256;
                int p = i & 7, m = i >> 3;
                unsigned hi, lo;
                split2(va[t].x, va[t].y, hi, lo);
                unsigned* base = &As[(long)(buf * TBM + m) * RSTR];
                int ph = posH(p);
                base[ph]     = hi;
                base[ph + 2] = lo;
            }
        } else {
            int m = tid & (TBM - 1), psel = tid >> LBM;
            #pragma unroll
            for (int t = 0; t < UA; ++t) {
                int p = psel * UA + t;
                unsigned hi, lo;
                split2(va[t].x, va[t].y, hi, lo);
                unsigned* base = &As[(long)(buf * TBM + m) * RSTR];
                int ph = posH(p);
                base[ph]     = hi;
                base[ph + 2] = lo;
            }
        }
    };
    auto storeB = [&](const float2* vb, int buf) {
        if (TB) {
            #pragma unroll
            for (int t = 0; t < UB; ++t) {
                int i = tid + t * 256;
                int p = i & 7, n = i >> 3;
                unsigned hi, lo;
                split2(vb[t].x, vb[t].y, hi, lo);
                unsigned* base = &Bs[(long)(buf * BN + n) * RSTR];
                int ph = posH(p);
                base[ph]     = hi;
                base[ph + 2] = lo;
            }
        } else {
            int n = tid & 127, psel = tid >> 7;
            #pragma unroll
            for (int t = 0; t < UB; ++t) {
                int p = psel * UB + t;
                unsigned hi, lo;
                split2(vb[t].x, vb[t].y, hi, lo);
                unsigned* base = &Bs[(long)(buf * BN + n) * RSTR];
                int ph = posH(p);
                base[ph]     = hi;
                base[ph + 2] = lo;
            }
        }
    };
    auto compute = [&](int buf) {
        uint4 a0[MI], a1[MI], bv[NJ];
        #pragma unroll
        for (int i = 0; i < MI; ++i) {
            int r = wm + i * 16 + (lane >> 2);
            a0[i] = *(const uint4*)&As[(long)(buf * TBM + r) * RSTR + ((lane & 3) << 2)];
            a1[i] = *(const uint4*)&As[(long)(buf * TBM + r + 8) * RSTR + ((lane & 3) << 2)];
        }
        #pragma unroll
        for (int j = 0; j < NJ; ++j) {
            int c = wn + j * 8 + (lane >> 2);
            bv[j] = *(const uint4*)&Bs[(long)(buf * BN + c) * RSTR + ((lane & 3) << 2)];
        }
        unsigned aH[MI][4], aL[MI][4], bH[NJ][2], bL[NJ][2];
        #pragma unroll
        for (int i = 0; i < MI; ++i) {
            aH[i][0] = a0[i].x; aH[i][1] = a1[i].x; aH[i][2] = a0[i].y; aH[i][3] = a1[i].y;
            aL[i][0] = a0[i].z; aL[i][1] = a1[i].z; aL[i][2] = a0[i].w; aL[i][3] = a1[i].w;
        }
        #pragma unroll
        for (int j = 0; j < NJ; ++j) {
            bH[j][0] = bv[j].x; bH[j][1] = bv[j].y;
            bL[j][0] = bv[j].z; bL[j][1] = bv[j].w;
        }
        #pragma unroll
        for (int j = 0; j < NJ; ++j)
            #pragma unroll
            for (int i = 0; i < MI; ++i)
                mma_bf16(acc[i][j], aH[i], bH[j]);   // hi*hi
        #pragma unroll
        for (int j = 0; j < NJ; ++j)
            #pragma unroll
            for (int i = 0; i < MI; ++i)
                mma_bf16(acc[i][j], aH[i], bL[j]);   // hi*lo
        #pragma unroll
        for (int j = 0; j < NJ; ++j)
            #pragma unroll
            for (int i = 0; i < MI; ++i)
                mma_bf16(acc[i][j], aL[i], bH[j]);   // lo*hi
    };

    // -------- pipeline: regs 2 tiles deep, smem double-buffered --------
    const int nt = Kd >> 4;
    loadA(vaR[0], 0); loadB(vbR[0], 0);
    storeA(vaR[0], 0); storeB(vbR[0], 0);
    if (nt > 1) { loadA(vaR[1], 16); loadB(vbR[1], 16); }
    __syncthreads();

    int buf = 0;
    for (int t = 0; t < nt; ++t) {
        if (t + 1 < nt) {
            // store tile t+1 (loaded one iteration ago) into the free buffer
            storeA(vaR[(t + 1) & 1], buf ^ 1);
            storeB(vbR[(t + 1) & 1], buf ^ 1);
            // issue loads for tile t+2 (consumed next iteration)
            if (t + 2 < nt) { loadA(vaR[t & 1], (t + 2) << 4); loadB(vbR[t & 1], (t + 2) << 4); }
        }
        compute(buf);
        if (t + 1 < nt) {
            __syncthreads();
            buf ^= 1;
        }
    }

    const float gmv = gammaPtr ? *gammaPtr : 1.f;
    #pragma unroll
    for (int i = 0; i < MI; ++i) {
        int r0 = m0 + wm + i * 16 + (lane >> 2);
        int r1 = r0 + 8;
        float sc0 = 1.f, bi0 = 0.f, sc1 = 1.f, bi1 = 0.f;
        if (scaleC) { if (r0 < M) sc0 = scaleC[r0]; if (r1 < M) sc1 = scaleC[r1]; }
        if (biasC)  { if (r0 < M) bi0 = biasC[r0];  if (r1 < M) bi1 = biasC[r1]; }
        #pragma unroll
        for (int j = 0; j < NJ; ++j) {
            int c = n0 + wn + j * 8 + ((lane & 3) << 1);
            float4 v = acc[i][j];
            if (r0 < M) {
                float x0 = v.x * sc0 + bi0, x1 = v.y * sc0 + bi0;
                if (relu) { x0 = fmaxf(x0, 0.f); x1 = fmaxf(x1, 0.f); }
                if (resid) {
                    if (c < N)     x0 = x0 * gmv + resid[(long)r0 * N + c];
                    if (c + 1 < N) x1 = x1 * gmv + resid[(long)r0 * N + c + 1];
                }
                if (c < N)     C[(long)r0 * N + c]     = x0;
                if (c + 1 < N) C[(long)r0 * N + c + 1] = x1;
            }
            if (r1 < M) {
                float y0 = v.z * sc1 + bi1, y1 = v.w * sc1 + bi1;
                if (relu) { y0 = fmaxf(y0, 0.f); y1 = fmaxf(y1, 0.f); }
                if (resid) {
                    if (c < N)     y0 = y0 * gmv + resid[(long)r1 * N + c];
                    if (c + 1 < N) y1 = y1 * gmv + resid[(long)r1 * N + c + 1];
                }
                if (c < N)     C[(long)r1 * N + c]     = y0;
                if (c + 1 < N) C[(long)r1 * N + c + 1] = y1;
            }
        }
    }
}

// ---------------- pointwise kernels -----------------------------------------
__global__ void tshuffle_kernel(const float* __restrict__ pf,
                                const float* __restrict__ gw,
                                const float* __restrict__ gb,
                                float* __restrict__ out)
{
    int idx = blockIdx.x * blockDim.x + threadIdx.x;
    if (idx >= B_SZ * COUT * HW) return;
    int c = (idx / HW) % COUT;
    float s = gb[c];
    #pragma unroll
    for (int k = 0; k < K_FR; ++k)
        s = fmaf(pf[(long)k * (B_SZ * COUT * HW) + idx], gw[c * K_FR + k], s);
    out[idx] = s;
}

// computes all 4 BN (slot = blockIdx.x): scale/bias into g_bnA/g_bnB[slot]
__global__ void bnprep4_kernel(const float* __restrict__ p0,
                               const float* __restrict__ p1,
                               const float* __restrict__ p2,
                               const float* __restrict__ p3,
                               float* __restrict__ a, float* __restrict__ b)
{
    int c = threadIdx.x;
    int slot = blockIdx.x;
    const float* p = (slot == 0) ? p0 : (slot == 1) ? p1 : (slot == 2) ? p2 : p3;
    float g = p[c], be = p[COUT + c], m = p[2 * COUT + c], v = p[3 * COUT + c];
    float s = g * rsqrtf(v + 1e-5f);
    a[slot * COUT + c] = s;
    b[slot * COUT + c] = be - m * s;
}

__global__ void im2col_kernel(const float* __restrict__ x, float* __restrict__ col)
{
    long idx = (long)blockIdx.x * blockDim.x + threadIdx.x;
    const long total = (long)B_SZ * COUT * 9 * HW;
    if (idx >= total) return;
    int n = (int)(idx % HW);
    long r = idx / HW;
    int t = (int)(r % 9);  r /= 9;
    int ci = (int)(r % COUT);
    int b = (int)(r / COUT);
    int h = n / W_, w = n % W_;
    int hh = h + t / 3 - 1, ww = w + t % 3 - 1;
    float v = 0.f;
    if (hh >= 0 && hh < H_ && ww >= 0 && ww < W_)
        v = x[((long)b * COUT + ci) * HW + hh * W_ + ww];
    col[idx] = v;
}

__global__ void softmax_kernel(float* __restrict__ S, int len, float scale)
{
    float* p = S + (long)blockIdx.x * len;
    __shared__ float red[256];
    int tid = threadIdx.x;
    float mx = -1e30f;
    for (int j = tid; j < len; j += 256) mx = fmaxf(mx, p[j] * scale);
    red[tid] = mx; __syncthreads();
    for (int s = 128; s > 0; s >>= 1) {
        if (tid < s) red[tid] = fmaxf(red[tid], red[tid + s]);
        __syncthreads();
    }
    mx = red[0]; __syncthreads();
    float sum = 0.f;
    for (int j = tid; j < len; j += 256) {
        float e = expf(p[j] * scale - mx);
        p[j] = e; sum += e;
    }
    red[tid] = sum; __syncthreads();
    for (int s = 128; s > 0; s >>= 1) {
        if (tid < s) red[tid] += red[tid + s];
        __syncthreads();
    }
    float inv = 1.f / red[0];
    for (int j = tid; j < len; j += 256) p[j] *= inv;
}

__global__ void concat_kernel(const float* __restrict__ kf,
                              const float* __restrict__ x,
                              float* __restrict__ cat)
{
    long idx = (long)blockIdx.x * blockDim.x + threadIdx.x;
    const long total = (long)B_SZ * 2 * COUT * HW;
    if (idx >= total) return;
    int n = (int)(idx % HW);
    long r = idx / HW;
    int c = (int)(r % (2 * COUT));
    int b = (int)(r / (2 * COUT));
    cat[idx] = (c < COUT) ? kf[((long)b * COUT + c) * HW + n]
                          : x[((long)b * COUT + (c - COUT)) * HW + n];
}

// ---------------- host-side helpers -----------------------------------------
static const int SMB_BIG   = (2 * 128 + 2 * 128) * RSTR * 4;   // 40960
static const int SMB_SMALL = (2 * 64 + 2 * 128) * RSTR * 4;    // 30720

// big: 128x128 tile (1 CTA); small: 64x128 tile (2 CTAs)
// mode: 0 = NN, 1 = TN (A transposed), 2 = NT (B transposed)
static void launch_gemm(int big, int mode,
                        const float* A, const float* B, float* C,
                        int M, int N, int Kd, int lda, int ldb,
                        long aS, int aDiv, long bS, long cS,
                        const float* sc, const float* bi, long biS,
                        int relu, const float* gp,
                        const float* res, long rS, int Z)
{
    dim3 block(256);
    if (big) {
        dim3 grid((N + 127) / 128, (M + 127) / 128, Z);
        if (mode == 0) {
            cudaFuncSetAttribute(gemm_bf<128,false,false,1>,
                                 cudaFuncAttributeMaxDynamicSharedMemorySize, SMB_BIG);
            gemm_bf<128,false,false,1><<<grid, block, SMB_BIG>>>(A, B, C, M, N, Kd, lda, ldb,
                aS, aDiv, bS, cS, sc, bi, biS, relu, gp, res, rS);
        } else {  // mode 1
            cudaFuncSetAttribute(gemm_bf<128,true,false,1>,
                                 cudaFuncAttributeMaxDynamicSharedMemorySize, SMB_BIG);
            gemm_bf<128,true,false,1><<<grid, block, SMB_BIG>>>(A, B, C, M, N, Kd, lda, ldb,
                aS, aDiv, bS, cS, sc, bi, biS, relu, gp, res, rS);
        }
    } else {
        dim3 grid((N + 127) / 128, (M + 63) / 64, Z);
        if (mode == 0) {
            cudaFuncSetAttribute(gemm_bf<64,false,false,2>,
                                 cudaFuncAttributeMaxDynamicSharedMemorySize, SMB_SMALL);
            gemm_bf<64,false,false,2><<<grid, block, SMB_SMALL>>>(A, B, C, M, N, Kd, lda, ldb,
                aS, aDiv, bS, cS, sc, bi, biS, relu, gp, res, rS);
        } else {  // mode 2
            cudaFuncSetAttribute(gemm_bf<64,false,true,2>,
                                 cudaFuncAttributeMaxDynamicSharedMemorySize, SMB_SMALL);
            gemm_bf<64,false,true,2><<<grid, block, SMB_SMALL>>>(A, B, C, M, N, Kd, lda, ldb,
                aS, aDiv, bS, cS, sc, bi, biS, relu, gp, res, rS);
        }
    }
}

extern "C" void kernel_launch(void* const* d_in, const int* in_sizes, int n_in,
                              void* d_out, int out_size)
{
    const float* feats    = (const float*)d_in[0];
    const float* proj_w   = (const float*)d_in[1];
    const float* proj_b   = (const float*)d_in[2];
    const float* ts_gw    = (const float*)d_in[3];
    const float* ts_gb    = (const float*)d_in[4];
    const float* ts_w3    = (const float*)d_in[5];
    const float* ts_bn    = (const float*)d_in[6];
    const float* ssam_w1  = (const float*)d_in[7];
    const float* ssam_b1  = (const float*)d_in[8];
    const float* ssam_w2  = (const float*)d_in[9];
    const float* ssam_b2  = (const float*)d_in[10];
    const float* ssam_g   = (const float*)d_in[11];
    const float* csam_w1  = (const float*)d_in[12];
    const float* csam_b1  = (const float*)d_in[13];
    const float* csam_w2  = (const float*)d_in[14];
    const float* csam_b2  = (const float*)d_in[15];
    const float* fuse_w1  = (const float*)d_in[16];
    const float* fuse_bn1 = (const float*)d_in[17];
    const float* fuse_w2  = (const float*)d_in[18];
    const float* fuse_bn2 = (const float*)d_in[19];
    const float* fcsam_w1 = (const float*)d_in[20];
    const float* fcsam_b1 = (const float*)d_in[21];
    const float* fcsam_w2 = (const float*)d_in[22];
    const float* fcsam_b2 = (const float*)d_in[23];
    const float* fuse_w4  = (const float*)d_in[24];
    const float* fuse_bn4 = (const float*)d_in[25];
    float* out = (float*)d_out;

    float *pf, *x, *x2, *o1, *h, *aS_, *aC_, *col, *cat, *bnA, *bnB;
    cudaGetSymbolAddress((void**)&pf,  g_pf);
    cudaGetSymbolAddress((void**)&x,   g_x);
    cudaGetSymbolAddress((void**)&x2,  g_x2);
    cudaGetSymbolAddress((void**)&o1,  g_o1);
    cudaGetSymbolAddress((void**)&h,   g_h);
    cudaGetSymbolAddress((void**)&aS_, g_aS);
    cudaGetSymbolAddress((void**)&aC_, g_aC);
    cudaGetSymbolAddress((void**)&col, g_col);
    cudaGetSymbolAddress((void**)&cat, g_cat);
    cudaGetSymbolAddress((void**)&bnA, g_bnA);
    cudaGetSymbolAddress((void**)&bnB, g_bnB);

    const long SP  = (long)COUT * HW;
    const long SPH = (long)C4V * HW;
    const long SPS = (long)HW * HW;
    const long SPC = (long)COUT * COUT;
    const long SPCOL = (long)COUT * 9 * HW;
    const long SPCAT = (long)2 * COUT * HW;

    // 0. all BN scale/bias pairs up front (slots: 0=ts, 1=fuse1, 2=fuse2, 3=fuse4)
    bnprep4_kernel<<<4, 256>>>(ts_bn, fuse_bn1, fuse_bn2, fuse_bn4, bnA, bnB);

    // 1. per-frame 1x1 projection
    launch_gemm(1, 0, proj_w, feats, pf, COUT, HW, CIN, CIN, HW,
                (long)COUT * CIN, B_SZ, (long)CIN * HW, SP,
                nullptr, proj_b, COUT, 0, nullptr, nullptr, 0, K_FR * B_SZ);

    // 2. temporal shuffle + grouped 1x1 -> x
    {
        int total = B_SZ * COUT * HW;
        tshuffle_kernel<<<(total + 255) / 256, 256>>>(pf, ts_gw, ts_gb, x);
    }

    // 3. 3x3 conv + BN -> x2
    {
        long total = (long)B_SZ * SPCOL;
        im2col_kernel<<<(int)((total + 255) / 256), 256>>>(x, col);
    }
    launch_gemm(0, 0, ts_w3, col, x2, COUT, HW, COUT * 9, COUT * 9, HW,
                0, 1, SPCOL, SP, bnA + 0 * COUT, bnB + 0 * COUT, 0, 0, nullptr, nullptr, 0, B_SZ);

    // 4. spatial self-attention (input x2, output x)
    launch_gemm(1, 1, x2, x2, aS_, HW, HW, COUT, HW, HW,
                SP, 1, SP, SPS, nullptr, nullptr, 0, 0, nullptr, nullptr, 0, B_SZ);
    softmax_kernel<<<B_SZ * HW, 256>>>(aS_, HW, 0.0625f);
    launch_gemm(0, 2, x2, aS_, o1, COUT, HW, HW, HW, HW,
                SP, 1, SPS, SP, nullptr, nullptr, 0, 0, nullptr, nullptr, 0, B_SZ);
    launch_gemm(1, 0, ssam_w1, o1, h, C4V, HW, COUT, COUT, HW,
                0, 1, SP, SPH, nullptr, ssam_b1, 0, 1, nullptr, nullptr, 0, B_SZ);
    launch_gemm(0, 0, ssam_w2, h, x, COUT, HW, C4V, C4V, HW,
                0, 1, SPH, SP, nullptr, ssam_b2, 0, 0, ssam_g, x2, SP, B_SZ);

    // 5. channel self-attention (input x, output x2)
    launch_gemm(0, 2, x, x, aC_, COUT, COUT, HW, HW, HW,
                SP, 1, SP, SPC, nullptr, nullptr, 0, 0, nullptr, nullptr, 0, B_SZ);
    softmax_kernel<<<B_SZ * COUT, 256>>>(aC_, COUT, 0.0625f);
    launch_gemm(0, 0, aC_, x, o1, COUT, HW, COUT, COUT, HW,
                SPC, 1, SP, SP, nullptr, nullptr, 0, 0, nullptr, nullptr, 0, B_SZ);
    launch_gemm(1, 0, csam_w1, o1, h, C4V, HW, COUT, COUT, HW,
                0, 1, SP, SPH, nullptr, csam_b1, 0, 1, nullptr, nullptr, 0, B_SZ);
    launch_gemm(0, 0, csam_w2, h, x2, COUT, HW, C4V, C4V, HW,
                0, 1, SPH, SP, nullptr, csam_b2, 0, 0, nullptr, x, SP, B_SZ);

    // 6. fuse: concat keyframe feat (pf[K-1]) with x2
    {
        long total = (long)B_SZ * SPCAT;
        concat_kernel<<<(int)((total + 255) / 256), 256>>>(
            pf + (long)(K_FR - 1) * B_SZ * SP, x2, cat);
    }
    launch_gemm(0, 0, fuse_w1, cat, x, COUT, HW, 2 * COUT, 2 * COUT, HW,
                0, 1, SPCAT, SP, bnA + 1 * COUT, bnB + 1 * COUT, 0, 1, nullptr, nullptr, 0, B_SZ);

    // 7. 3x3 conv + BN + relu -> x2
    {
        long total = (long)B_SZ * SPCOL;
        im2col_kernel<<<(int)((total + 255) / 256), 256>>>(x, col);
    }
    launch_gemm(0, 0, fuse_w2, col, x2, COUT, HW, COUT * 9, COUT * 9, HW,
                0, 1, SPCOL, SP, bnA + 2 * COUT, bnB + 2 * COUT, 0, 1, nullptr, nullptr, 0, B_SZ);

    // 8. channel self-attention (input x2, output x)
    launch_gemm(0, 2, x2, x2, aC_, COUT, COUT, HW, HW, HW,
                SP, 1, SP, SPC, nullptr, nullptr, 0, 0, nullptr, nullptr, 0, B_SZ);
    softmax_kernel<<<B_SZ * COUT, 256>>>(aC_, COUT, 0.0625f);
    launch_gemm(0, 0, aC_, x2, o1, COUT, HW, COUT, COUT, HW,
                SPC, 1, SP, SP, nullptr, nullptr, 0, 0, nullptr, nullptr, 0, B_SZ);
    launch_gemm(1, 0, fcsam_w1, o1, h, C4V, HW, COUT, COUT, HW,
                0, 1, SP, SPH, nullptr, fcsam_b1, 0, 1, nullptr, nullptr, 0, B_SZ);
    launch_gemm(0, 0, fcsam_w2, h, x, COUT, HW, C4V, C4V, HW,
                0, 1, SPH, SP, nullptr, fcsam_b2, 0, 0, nullptr, x2, SP, B_SZ);

    // 9. final 3x3 conv + BN + relu -> d_out
    {
        long total = (long)B_SZ * SPCOL;
        im2col_kernel<<<(int)((total + 255) / 256), 256>>>(x, col);
    }
    launch_gemm(0, 0, fuse_w4, col, out, COUT, HW, COUT * 9, COUT * 9, HW,
                0, 1, SPCOL, SP, bnA + 3 * COUT, bnB + 3 * COUT, 0, 1, nullptr, nullptr, 0, B_SZ);
}

// round 10
// speedup vs baseline: 1.5357x; 1.5357x over previous
#include <cuda_runtime.h>
#include <cuda_bf16.h>
#include <math.h>

#define K_FR 8
#define B_SZ 8
#define CIN  512
#define COUT 256
#define H_   28
#define W_   28
#define HW   784
#define C4V  1024

// ---------------- scratch (device globals; no allocation at runtime) --------
__device__ __align__(16) float g_pf  [K_FR * B_SZ * COUT * HW];
__device__ __align__(16) float g_x   [B_SZ * COUT * HW];
__device__ __align__(16) float g_x2  [B_SZ * COUT * HW];
__device__ __align__(16) float g_o1  [B_SZ * COUT * HW];
__device__ __align__(16) float g_h   [B_SZ * C4V * HW];
__device__ __align__(16) float g_aS  [B_SZ * HW * HW];
__device__ __align__(16) float g_aC  [B_SZ * COUT * COUT];
__device__ __align__(16) float g_col [B_SZ * COUT * 9 * HW];
__device__ __align__(16) float g_cat [B_SZ * 2 * COUT * HW];
__device__ float g_bnA [4 * COUT];
__device__ float g_bnB [4 * COUT];

// ---------------- 3xBF16 tensor-core GEMM -----------------------------------
// a*b ~= aH*bH + aH*bL + aL*bH with bf16 hi/lo split (residual ~2^-16), fp32 acc.
// mma.m16n8k16.bf16 covers K=16 per instruction.
// smem row layout (per k-tile of 16): 8 k-pairs as bf16x2 words, interleaved
//   group 4p = {hi(p), hi(p+4), lo(p), lo(p+4)}  -> fragment = one LDS.128.
// Row stride RSTR=20 uints. Double-buffered smem.
// PIPE2 (big tile only): register staging TWO k-tiles deep using two NAMED
// register sets (all indices compile-time -> stays in registers, no LMEM).
// TA: A stored [K,M]; else [M,K].  TB: B stored [N,K]; else [K,N].
// epilogue: v = acc*scale[m]+bias[m]; relu; v = v*gamma + resid[m,n]
// Requires Kd % 16 == 0 (all call sites: 256/512/784/1024/2304).

__device__ __forceinline__ unsigned pack2(float f0, float f1) {   // f0->low, f1->high
    unsigned r;
    asm("cvt.rn.bf16x2.f32 %0, %1, %2;" : "=r"(r) : "f"(f1), "f"(f0));
    return r;
}
__device__ __forceinline__ void split2(float f0, float f1, unsigned& hi, unsigned& lo) {
    hi = pack2(f0, f1);
    float h0 = __uint_as_float(hi << 16);
    float h1 = __uint_as_float(hi & 0xffff0000u);
    lo = pack2(f0 - h0, f1 - h1);
}
__device__ __forceinline__ void mma_bf16(float4& d, const unsigned a[4], const unsigned b[2]) {
    asm volatile(
        "mma.sync.aligned.m16n8k16.row.col.f32.bf16.bf16.f32 "
        "{%0,%1,%2,%3}, {%4,%5,%6,%7}, {%8,%9}, {%0,%1,%2,%3};"
        : "+f"(d.x), "+f"(d.y), "+f"(d.z), "+f"(d.w)
        : "r"(a[0]), "r"(a[1]), "r"(a[2]), "r"(a[3]), "r"(b[0]), "r"(b[1]));
}

#define RSTR 20   // smem row stride in uints
#define BN   128

__device__ __forceinline__ int posH(int p) { return 4 * (p & 3) + (p >> 2); }

template <int TBM, bool TA, bool TB, int MAXB, bool PIPE2>
__global__ void __launch_bounds__(256, MAXB) gemm_bf(
    const float* __restrict__ A, const float* __restrict__ Bm, float* __restrict__ C,
    int M, int N, int Kd, int lda, int ldb,
    long aS, int aDiv, long bS, long cS,
    const float* __restrict__ scaleC, const float* __restrict__ biasC, long biS,
    int relu, const float* __restrict__ gammaPtr,
    const float* __restrict__ resid, long rS)
{
    extern __shared__ unsigned sm[];
    unsigned* As = sm;                       // [2][TBM][RSTR]
    unsigned* Bs = sm + 2 * TBM * RSTR;      // [2][BN ][RSTR]

    const int z = blockIdx.z;
    A  += (long)(z / aDiv) * aS;
    Bm += (long)z * bS;
    C  += (long)z * cS;
    if (biasC) biasC += (long)(z / aDiv) * biS;
    if (resid) resid += (long)z * rS;

    const int tid  = threadIdx.x;
    const int lane = tid & 31, warp = tid >> 5;
    constexpr int MI = TBM / 32;            // 2 or 4
    constexpr int NJ = 4;
    constexpr int UA = TBM / 32;            // A pairs per thread
    constexpr int UB = 4;                   // B pairs per thread
    constexpr int LBM = (TBM == 128) ? 7 : 6;
    const int wm = (warp >> 2) * (TBM / 2);
    const int wn = (warp & 3) * 32;
    const int m0 = blockIdx.y * TBM, n0 = blockIdx.x * BN;

    float4 acc[MI][NJ];
    #pragma unroll
    for (int i = 0; i < MI; ++i)
        #pragma unroll
        for (int j = 0; j < NJ; ++j)
            acc[i][j] = make_float4(0.f, 0.f, 0.f, 0.f);

    auto loadA = [&](float2* va, int k0) {
        if (!TA) {   // A [M,K]: 8 threads per row, float2 (k-pair) each
            #pragma unroll
            for (int t = 0; t < UA; ++t) {
                int i = tid + t * 256;
                int p = i & 7, m = i >> 3;
                int gm = m0 + m;
                va[t] = (gm < M) ? *(const float2*)&A[(long)gm * lda + k0 + 2 * p]
                                 : make_float2(0.f, 0.f);
            }
        } else {     // A [K,M]: coalesced across m, two strided rows per pair
            int m = tid & (TBM - 1), psel = tid >> LBM;
            int gm = m0 + m;
            #pragma unroll
            for (int t = 0; t < UA; ++t) {
                int p = psel * UA + t;
                float f0 = 0.f, f1 = 0.f;
                if (gm < M) {
                    f0 = A[(long)(k0 + 2 * p) * lda + gm];
                    f1 = A[(long)(k0 + 2 * p + 1) * lda + gm];
                }
                va[t] = make_float2(f0, f1);
            }
        }
    };
    auto loadB = [&](float2* vb, int k0) {
        if (TB) {    // B [N,K]: 8 threads per row, float2 each
            #pragma unroll
            for (int t = 0; t < UB; ++t) {
                int i = tid + t * 256;
                int p = i & 7, n = i >> 3;
                int gn = n0 + n;
                vb[t] = (gn < N) ? *(const float2*)&Bm[(long)gn * ldb + k0 + 2 * p]
                                 : make_float2(0.f, 0.f);
            }
        } else {     // B [K,N]: coalesced across n, two strided rows per pair
            int n = tid & 127, psel = tid >> 7;
            int gn = n0 + n;
            #pragma unroll
            for (int t = 0; t < UB; ++t) {
                int p = psel * UB + t;
                float f0 = 0.f, f1 = 0.f;
                if (gn < N) {
                    f0 = Bm[(long)(k0 + 2 * p) * ldb + gn];
                    f1 = Bm[(long)(k0 + 2 * p + 1) * ldb + gn];
                }
                vb[t] = make_float2(f0, f1);
            }
        }
    };
    auto storeA = [&](const float2* va, int buf) {
        if (!TA) {
            #pragma unroll
            for (int t = 0; t < UA; ++t) {
                int i = tid + t * 256;
                int p = i & 7, m = i >> 3;
                unsigned hi, lo;
                split2(va[t].x, va[t].y, hi, lo);
                unsigned* base = &As[(long)(buf * TBM + m) * RSTR];
                int ph = posH(p);
                base[ph]     = hi;
                base[ph + 2] = lo;
            }
        } else {
            int m = tid & (TBM - 1), psel = tid >> LBM;
            #pragma unroll
            for (int t = 0; t < UA; ++t) {
                int p = psel * UA + t;
                unsigned hi, lo;
                split2(va[t].x, va[t].y, hi, lo);
                unsigned* base = &As[(long)(buf * TBM + m) * RSTR];
                int ph = posH(p);
                base[ph]     = hi;
                base[ph + 2] = lo;
            }
        }
    };
    auto storeB = [&](const float2* vb, int buf) {
        if (TB) {
            #pragma unroll
            for (int t = 0; t < UB; ++t) {
                int i = tid + t * 256;
                int p = i & 7, n = i >> 3;
                unsigned hi, lo;
                split2(vb[t].x, vb[t].y, hi, lo);
                unsigned* base = &Bs[(long)(buf * BN + n) * RSTR];
                int ph = posH(p);
                base[ph]     = hi;
                base[ph + 2] = lo;
            }
        } else {
            int n = tid & 127, psel = tid >> 7;
            #pragma unroll
            for (int t = 0; t < UB; ++t) {
                int p = psel * UB + t;
                unsigned hi, lo;
                split2(vb[t].x, vb[t].y, hi, lo);
                unsigned* base = &Bs[(long)(buf * BN + n) * RSTR];
                int ph = posH(p);
                base[ph]     = hi;
                base[ph + 2] = lo;
            }
        }
    };
    auto compute = [&](int buf) {
        uint4 a0[MI], a1[MI], bv[NJ];
        #pragma unroll
        for (int i = 0; i < MI; ++i) {
            int r = wm + i * 16 + (lane >> 2);
            a0[i] = *(const uint4*)&As[(long)(buf * TBM + r) * RSTR + ((lane & 3) << 2)];
            a1[i] = *(const uint4*)&As[(long)(buf * TBM + r + 8) * RSTR + ((lane & 3) << 2)];
        }
        #pragma unroll
        for (int j = 0; j < NJ; ++j) {
            int c = wn + j * 8 + (lane >> 2);
            bv[j] = *(const uint4*)&Bs[(long)(buf * BN + c) * RSTR + ((lane & 3) << 2)];
        }
        unsigned aH[MI][4], aL[MI][4], bH[NJ][2], bL[NJ][2];
        #pragma unroll
        for (int i = 0; i < MI; ++i) {
            aH[i][0] = a0[i].x; aH[i][1] = a1[i].x; aH[i][2] = a0[i].y; aH[i][3] = a1[i].y;
            aL[i][0] = a0[i].z; aL[i][1] = a1[i].z; aL[i][2] = a0[i].w; aL[i][3] = a1[i].w;
        }
        #pragma unroll
        for (int j = 0; j < NJ; ++j) {
            bH[j][0] = bv[j].x; bH[j][1] = bv[j].y;
            bL[j][0] = bv[j].z; bL[j][1] = bv[j].w;
        }
        #pragma unroll
        for (int j = 0; j < NJ; ++j)
            #pragma unroll
            for (int i = 0; i < MI; ++i)
                mma_bf16(acc[i][j], aH[i], bH[j]);   // hi*hi
        #pragma unroll
        for (int j = 0; j < NJ; ++j)
            #pragma unroll
            for (int i = 0; i < MI; ++i)
                mma_bf16(acc[i][j], aH[i], bL[j]);   // hi*lo
        #pragma unroll
        for (int j = 0; j < NJ; ++j)
            #pragma unroll
            for (int i = 0; i < MI; ++i)
                mma_bf16(acc[i][j], aL[i], bH[j]);   // lo*hi
    };

    const int nt = Kd >> 4;
    int buf = 0;

    if constexpr (PIPE2) {
        // 2-deep register pipeline, NAMED register sets (no runtime indexing).
        float2 va0[UA], vb0[UB], va1[UA], vb1[UB];
        loadA(va0, 0); loadB(vb0, 0);
        storeA(va0, 0); storeB(vb0, 0);
        if (nt > 1) { loadA(va0, 16); loadB(vb0, 16); }   // tile1 -> set0
        __syncthreads();
        int t = 0;
        while (true) {
            // even phase: pending tile t+1 sits in set0
            if (t + 1 < nt) {
                storeA(va0, buf ^ 1); storeB(vb0, buf ^ 1);
                if (t + 2 < nt) { loadA(va1, (t + 2) << 4); loadB(vb1, (t + 2) << 4); }
            }
            compute(buf);
            if (++t >= nt) break;
            __syncthreads(); buf ^= 1;
            // odd phase: pending tile t+1 sits in set1
            if (t + 1 < nt) {
                storeA(va1, buf ^ 1); storeB(vb1, buf ^ 1);
                if (t + 2 < nt) { loadA(va0, (t + 2) << 4); loadB(vb0, (t + 2) << 4); }
            }
            compute(buf);
            if (++t >= nt) break;
            __syncthreads(); buf ^= 1;
        }
    } else {
        // R8 loop: loads for next tile issued before compute (partial overlap).
        float2 va[UA], vb[UB];
        loadA(va, 0); loadB(vb, 0);
        storeA(va, 0); storeB(vb, 0);
        __syncthreads();
        for (int k0 = 0; k0 < Kd; k0 += 16) {
            bool more = (k0 + 16) < Kd;
            if (more) { loadA(va, k0 + 16); loadB(vb, k0 + 16); }
            compute(buf);
            if (more) {
                storeA(va, buf ^ 1); storeB(vb, buf ^ 1);
                __syncthreads();
                buf ^= 1;
            }
        }
    }

    const float gmv = gammaPtr ? *gammaPtr : 1.f;
    #pragma unroll
    for (int i = 0; i < MI; ++i) {
        int r0 = m0 + wm + i * 16 + (lane >> 2);
        int r1 = r0 + 8;
        float sc0 = 1.f, bi0 = 0.f, sc1 = 1.f, bi1 = 0.f;
        if (scaleC) { if (r0 < M) sc0 = scaleC[r0]; if (r1 < M) sc1 = scaleC[r1]; }
        if (biasC)  { if (r0 < M) bi0 = biasC[r0];  if (r1 < M) bi1 = biasC[r1]; }
        #pragma unroll
        for (int j = 0; j < NJ; ++j) {
            int c = n0 + wn + j * 8 + ((lane & 3) << 1);
            float4 v = acc[i][j];
            if (r0 < M) {
                float x0 = v.x * sc0 + bi0, x1 = v.y * sc0 + bi0;
                if (relu) { x0 = fmaxf(x0, 0.f); x1 = fmaxf(x1, 0.f); }
                if (resid) {
                    if (c < N)     x0 = x0 * gmv + resid[(long)r0 * N + c];
                    if (c + 1 < N) x1 = x1 * gmv + resid[(long)r0 * N + c + 1];
                }
                if (c < N)     C[(long)r0 * N + c]     = x0;
                if (c + 1 < N) C[(long)r0 * N + c + 1] = x1;
            }
            if (r1 < M) {
                float y0 = v.z * sc1 + bi1, y1 = v.w * sc1 + bi1;
                if (relu) { y0 = fmaxf(y0, 0.f); y1 = fmaxf(y1, 0.f); }
                if (resid) {
                    if (c < N)     y0 = y0 * gmv + resid[(long)r1 * N + c];
                    if (c + 1 < N) y1 = y1 * gmv + resid[(long)r1 * N + c + 1];
                }
                if (c < N)     C[(long)r1 * N + c]     = y0;
                if (c + 1 < N) C[(long)r1 * N + c + 1] = y1;
            }
        }
    }
}

// ---------------- pointwise kernels -----------------------------------------
__global__ void tshuffle_kernel(const float* __restrict__ pf,
                                const float* __restrict__ gw,
                                const float* __restrict__ gb,
                                float* __restrict__ out)
{
    int idx = blockIdx.x * blockDim.x + threadIdx.x;
    if (idx >= B_SZ * COUT * HW) return;
    int c = (idx / HW) % COUT;
    float s = gb[c];
    #pragma unroll
    for (int k = 0; k < K_FR; ++k)
        s = fmaf(pf[(long)k * (B_SZ * COUT * HW) + idx], gw[c * K_FR + k], s);
    out[idx] = s;
}

// computes all 4 BN (slot = blockIdx.x): scale/bias into g_bnA/g_bnB[slot]
__global__ void bnprep4_kernel(const float* __restrict__ p0,
                               const float* __restrict__ p1,
                               const float* __restrict__ p2,
                               const float* __restrict__ p3,
                               float* __restrict__ a, float* __restrict__ b)
{
    int c = threadIdx.x;
    int slot = blockIdx.x;
    const float* p = (slot == 0) ? p0 : (slot == 1) ? p1 : (slot == 2) ? p2 : p3;
    float g = p[c], be = p[COUT + c], m = p[2 * COUT + c], v = p[3 * COUT + c];
    float s = g * rsqrtf(v + 1e-5f);
    a[slot * COUT + c] = s;
    b[slot * COUT + c] = be - m * s;
}

__global__ void im2col_kernel(const float* __restrict__ x, float* __restrict__ col)
{
    long idx = (long)blockIdx.x * blockDim.x + threadIdx.x;
    const long total = (long)B_SZ * COUT * 9 * HW;
    if (idx >= total) return;
    int n = (int)(idx % HW);
    long r = idx / HW;
    int t = (int)(r % 9);  r /= 9;
    int ci = (int)(r % COUT);
    int b = (int)(r / COUT);
    int h = n / W_, w = n % W_;
    int hh = h + t / 3 - 1, ww = w + t % 3 - 1;
    float v = 0.f;
    if (hh >= 0 && hh < H_ && ww >= 0 && ww < W_)
        v = x[((long)b * COUT + ci) * HW + hh * W_ + ww];
    col[idx] = v;
}

__global__ void softmax_kernel(float* __restrict__ S, int len, float scale)
{
    float* p = S + (long)blockIdx.x * len;
    __shared__ float red[256];
    int tid = threadIdx.x;
    float mx = -1e30f;
    for (int j = tid; j < len; j += 256) mx = fmaxf(mx, p[j] * scale);
    red[tid] = mx; __syncthreads();
    for (int s = 128; s > 0; s >>= 1) {
        if (tid < s) red[tid] = fmaxf(red[tid], red[tid + s]);
        __syncthreads();
    }
    mx = red[0]; __syncthreads();
    float sum = 0.f;
    for (int j = tid; j < len; j += 256) {
        float e = expf(p[j] * scale - mx);
        p[j] = e; sum += e;
    }
    red[tid] = sum; __syncthreads();
    for (int s = 128; s > 0; s >>= 1) {
        if (tid < s) red[tid] += red[tid + s];
        __syncthreads();
    }
    float inv = 1.f / red[0];
    for (int j = tid; j < len; j += 256) p[j] *= inv;
}

__global__ void concat_kernel(const float* __restrict__ kf,
                              const float* __restrict__ x,
                              float* __restrict__ cat)
{
    long idx = (long)blockIdx.x * blockDim.x + threadIdx.x;
    const long total = (long)B_SZ * 2 * COUT * HW;
    if (idx >= total) return;
    int n = (int)(idx % HW);
    long r = idx / HW;
    int c = (int)(r % (2 * COUT));
    int b = (int)(r / (2 * COUT));
    cat[idx] = (c < COUT) ? kf[((long)b * COUT + c) * HW + n]
                          : x[((long)b * COUT + (c - COUT)) * HW + n];
}

// ---------------- host-side helpers -----------------------------------------
static const int SMB_BIG   = (2 * 128 + 2 * 128) * RSTR * 4;   // 40960
static const int SMB_SMALL = (2 * 64 + 2 * 128) * RSTR * 4;    // 30720

// big: 128x128 tile (1 CTA, 2-deep pipeline); small: 64x128 tile (2 CTAs)
// mode: 0 = NN, 1 = TN (A transposed), 2 = NT (B transposed)
static void launch_gemm(int big, int mode,
                        const float* A, const float* B, float* C,
                        int M, int N, int Kd, int lda, int ldb,
                        long aS, int aDiv, long bS, long cS,
                        const float* sc, const float* bi, long biS,
                        int relu, const float* gp,
                        const float* res, long rS, int Z)
{
    dim3 block(256);
    if (big) {
        dim3 grid((N + 127) / 128, (M + 127) / 128, Z);
        if (mode == 0) {
            cudaFuncSetAttribute(gemm_bf<128,false,false,1,true>,
                                 cudaFuncAttributeMaxDynamicSharedMemorySize, SMB_BIG);
            gemm_bf<128,false,false,1,true><<<grid, block, SMB_BIG>>>(A, B, C, M, N, Kd, lda, ldb,
                aS, aDiv, bS, cS, sc, bi, biS, relu, gp, res, rS);
        } else {  // mode 1
            cudaFuncSetAttribute(gemm_bf<128,true,false,1,true>,
                                 cudaFuncAttributeMaxDynamicSharedMemorySize, SMB_BIG);
            gemm_bf<128,true,false,1,true><<<grid, block, SMB_BIG>>>(A, B, C, M, N, Kd, lda, ldb,
                aS, aDiv, bS, cS, sc, bi, biS, relu, gp, res, rS);
        }
    } else {
        dim3 grid((N + 127) / 128, (M + 63) / 64, Z);
        if (mode == 0) {
            cudaFuncSetAttribute(gemm_bf<64,false,false,2,false>,
                                 cudaFuncAttributeMaxDynamicSharedMemorySize, SMB_SMALL);
            gemm_bf<64,false,false,2,false><<<grid, block, SMB_SMALL>>>(A, B, C, M, N, Kd, lda, ldb,
                aS, aDiv, bS, cS, sc, bi, biS, relu, gp, res, rS);
        } else {  // mode 2
            cudaFuncSetAttribute(gemm_bf<64,false,true,2,false>,
                                 cudaFuncAttributeMaxDynamicSharedMemorySize, SMB_SMALL);
            gemm_bf<64,false,true,2,false><<<grid, block, SMB_SMALL>>>(A, B, C, M, N, Kd, lda, ldb,
                aS, aDiv, bS, cS, sc, bi, biS, relu, gp, res, rS);
        }
    }
}

extern "C" void kernel_launch(void* const* d_in, const int* in_sizes, int n_in,
                              void* d_out, int out_size)
{
    const float* feats    = (const float*)d_in[0];
    const float* proj_w   = (const float*)d_in[1];
    const float* proj_b   = (const float*)d_in[2];
    const float* ts_gw    = (const float*)d_in[3];
    const float* ts_gb    = (const float*)d_in[4];
    const float* ts_w3    = (const float*)d_in[5];
    const float* ts_bn    = (const float*)d_in[6];
    const float* ssam_w1  = (const float*)d_in[7];
    const float* ssam_b1  = (const float*)d_in[8];
    const float* ssam_w2  = (const float*)d_in[9];
    const float* ssam_b2  = (const float*)d_in[10];
    const float* ssam_g   = (const float*)d_in[11];
    const float* csam_w1  = (const float*)d_in[12];
    const float* csam_b1  = (const float*)d_in[13];
    const float* csam_w2  = (const float*)d_in[14];
    const float* csam_b2  = (const float*)d_in[15];
    const float* fuse_w1  = (const float*)d_in[16];
    const float* fuse_bn1 = (const float*)d_in[17];
    const float* fuse_w2  = (const float*)d_in[18];
    const float* fuse_bn2 = (const float*)d_in[19];
    const float* fcsam_w1 = (const float*)d_in[20];
    const float* fcsam_b1 = (const float*)d_in[21];
    const float* fcsam_w2 = (const float*)d_in[22];
    const float* fcsam_b2 = (const float*)d_in[23];
    const float* fuse_w4  = (const float*)d_in[24];
    const float* fuse_bn4 = (const float*)d_in[25];
    float* out = (float*)d_out;

    float *pf, *x, *x2, *o1, *h, *aS_, *aC_, *col, *cat, *bnA, *bnB;
    cudaGetSymbolAddress((void**)&pf,  g_pf);
    cudaGetSymbolAddress((void**)&x,   g_x);
    cudaGetSymbolAddress((void**)&x2,  g_x2);
    cudaGetSymbolAddress((void**)&o1,  g_o1);
    cudaGetSymbolAddress((void**)&h,   g_h);
    cudaGetSymbolAddress((void**)&aS_, g_aS);
    cudaGetSymbolAddress((void**)&aC_, g_aC);
    cudaGetSymbolAddress((void**)&col, g_col);
    cudaGetSymbolAddress((void**)&cat, g_cat);
    cudaGetSymbolAddress((void**)&bnA, g_bnA);
    cudaGetSymbolAddress((void**)&bnB, g_bnB);

    const long SP  = (long)COUT * HW;
    const long SPH = (long)C4V * HW;
    const long SPS = (long)HW * HW;
    const long SPC = (long)COUT * COUT;
    const long SPCOL = (long)COUT * 9 * HW;
    const long SPCAT = (long)2 * COUT * HW;

    // 0. all BN scale/bias pairs up front (slots: 0=ts, 1=fuse1, 2=fuse2, 3=fuse4)
    bnprep4_kernel<<<4, 256>>>(ts_bn, fuse_bn1, fuse_bn2, fuse_bn4, bnA, bnB);

    // 1. per-frame 1x1 projection
    launch_gemm(1, 0, proj_w, feats, pf, COUT, HW, CIN, CIN, HW,
                (long)COUT * CIN, B_SZ, (long)CIN * HW, SP,
                nullptr, proj_b, COUT, 0, nullptr, nullptr, 0, K_FR * B_SZ);

    // 2. temporal shuffle + grouped 1x1 -> x
    {
        int total = B_SZ * COUT * HW;
        tshuffle_kernel<<<(total + 255) / 256, 256>>>(pf, ts_gw, ts_gb, x);
    }

    // 3. 3x3 conv + BN -> x2
    {
        long total = (long)B_SZ * SPCOL;
        im2col_kernel<<<(int)((total + 255) / 256), 256>>>(x, col);
    }
    launch_gemm(0, 0, ts_w3, col, x2, COUT, HW, COUT * 9, COUT * 9, HW,
                0, 1, SPCOL, SP, bnA + 0 * COUT, bnB + 0 * COUT, 0, 0, nullptr, nullptr, 0, B_SZ);

    // 4. spatial self-attention (input x2, output x)
    launch_gemm(1, 1, x2, x2, aS_, HW, HW, COUT, HW, HW,
                SP, 1, SP, SPS, nullptr, nullptr, 0, 0, nullptr, nullptr, 0, B_SZ);
    softmax_kernel<<<B_SZ * HW, 256>>>(aS_, HW, 0.0625f);
    launch_gemm(0, 2, x2, aS_, o1, COUT, HW, HW, HW, HW,
                SP, 1, SPS, SP, nullptr, nullptr, 0, 0, nullptr, nullptr, 0, B_SZ);
    launch_gemm(1, 0, ssam_w1, o1, h, C4V, HW, COUT, COUT, HW,
                0, 1, SP, SPH, nullptr, ssam_b1, 0, 1, nullptr, nullptr, 0, B_SZ);
    launch_gemm(0, 0, ssam_w2, h, x, COUT, HW, C4V, C4V, HW,
                0, 1, SPH, SP, nullptr, ssam_b2, 0, 0, ssam_g, x2, SP, B_SZ);

    // 5. channel self-attention (input x, output x2)
    launch_gemm(0, 2, x, x, aC_, COUT, COUT, HW, HW, HW,
                SP, 1, SP, SPC, nullptr, nullptr, 0, 0, nullptr, nullptr, 0, B_SZ);
    softmax_kernel<<<B_SZ * COUT, 256>>>(aC_, COUT, 0.0625f);
    launch_gemm(0, 0, aC_, x, o1, COUT, HW, COUT, COUT, HW,
                SPC, 1, SP, SP, nullptr, nullptr, 0, 0, nullptr, nullptr, 0, B_SZ);
    launch_gemm(1, 0, csam_w1, o1, h, C4V, HW, COUT, COUT, HW,
                0, 1, SP, SPH, nullptr, csam_b1, 0, 1, nullptr, nullptr, 0, B_SZ);
    launch_gemm(0, 0, csam_w2, h, x2, COUT, HW, C4V, C4V, HW,
                0, 1, SPH, SP, nullptr, csam_b2, 0, 0, nullptr, x, SP, B_SZ);

    // 6. fuse: concat keyframe feat (pf[K-1]) with x2
    {
        long total = (long)B_SZ * SPCAT;
        concat_kernel<<<(int)((total + 255) / 256), 256>>>(
            pf + (long)(K_FR - 1) * B_SZ * SP, x2, cat);
    }
    launch_gemm(0, 0, fuse_w1, cat, x, COUT, HW, 2 * COUT, 2 * COUT, HW,
                0, 1, SPCAT, SP, bnA + 1 * COUT, bnB + 1 * COUT, 0, 1, nullptr, nullptr, 0, B_SZ);

    // 7. 3x3 conv + BN + relu -> x2
    {
        long total = (long)B_SZ * SPCOL;
        im2col_kernel<<<(int)((total + 255) / 256), 256>>>(x, col);
    }
    launch_gemm(0, 0, fuse_w2, col, x2, COUT, HW, COUT * 9, COUT * 9, HW,
                0, 1, SPCOL, SP, bnA + 2 * COUT, bnB + 2 * COUT, 0, 1, nullptr, nullptr, 0, B_SZ);

    // 8. channel self-attention (input x2, output x)
    launch_gemm(0, 2, x2, x2, aC_, COUT, COUT, HW, HW, HW,
                SP, 1, SP, SPC, nullptr, nullptr, 0, 0, nullptr, nullptr, 0, B_SZ);
    softmax_kernel<<<B_SZ * COUT, 256>>>(aC_, COUT, 0.0625f);
    launch_gemm(0, 0, aC_, x2, o1, COUT, HW, COUT, COUT, HW,
                SPC, 1, SP, SP, nullptr, nullptr, 0, 0, nullptr, nullptr, 0, B_SZ);
    launch_gemm(1, 0, fcsam_w1, o1, h, C4V, HW, COUT, COUT, HW,
                0, 1, SP, SPH, nullptr, fcsam_b1, 0, 1, nullptr, nullptr, 0, B_SZ);
    launch_gemm(0, 0, fcsam_w2, h, x, COUT, HW, C4V, C4V, HW,
                0, 1, SPH, SP, nullptr, fcsam_b2, 0, 0, nullptr, x2, SP, B_SZ);

    // 9. final 3x3 conv + BN + relu -> d_out
    {
        long total = (long)B_SZ * SPCOL;
        im2col_kernel<<<(int)((total + 255) / 256), 256>>>(x, col);
    }
    launch_gemm(0, 0, fuse_w4, col, out, COUT, HW, COUT * 9, COUT * 9, HW,
                0, 1, SPCOL, SP, bnA + 3 * COUT, bnB + 3 * COUT, 0, 1, nullptr, nullptr, 0, B_SZ);
}

// round 11
// speedup vs baseline: 1.5943x; 1.0382x over previous
#include <cuda_runtime.h>
#include <cuda_bf16.h>
#include <math.h>

#define K_FR 8
#define B_SZ 8
#define CIN  512
#define COUT 256
#define H_   28
#define W_   28
#define HW   784
#define C4V  1024

// ---------------- scratch (device globals; no allocation at runtime) --------
__device__ __align__(16) float g_pf  [K_FR * B_SZ * COUT * HW];
__device__ __align__(16) float g_x   [B_SZ * COUT * HW];
__device__ __align__(16) float g_x2  [B_SZ * COUT * HW];
__device__ __align__(16) float g_o1  [B_SZ * COUT * HW];
__device__ __align__(16) float g_h   [B_SZ * C4V * HW];
__device__ __align__(16) float g_aS  [B_SZ * HW * HW];
__device__ __align__(16) float g_aC  [B_SZ * COUT * COUT];
__device__ __align__(16) float g_cat [B_SZ * 2 * COUT * HW];
__device__ float g_bnA [4 * COUT];
__device__ float g_bnB [4 * COUT];

// ---------------- 3xBF16 tensor-core GEMM (R8 mainloop) ---------------------
// a*b ~= aH*bH + aH*bL + aL*bH with bf16 hi/lo split (residual ~2^-16), fp32 acc.
// mma.m16n8k16.bf16; smem row: 8 k-pairs as bf16x2 words, group 4p =
// {hi(p), hi(p+4), lo(p), lo(p+4)} -> fragment = one LDS.128. RSTR=20 uints.
// TA: A stored [K,M]; else [M,K].  TB: B stored [N,K]; else [K,N].
// CONV: implicit 3x3 im2col with k = t*256 + ci (t = k0>>8 CONSTANT per
//       16-wide k-tile -> per-tile-uniform (dh,dw) + bounds; weight read uses
//       the inverse permutation (k&255)*9 + (k>>8)).
// epilogue: v = acc*scale[m]+bias[m]; relu; v = v*gamma + resid[m,n]
// Requires Kd % 16 == 0 (256/512/784/1024/2304).

__device__ __forceinline__ unsigned pack2(float f0, float f1) {   // f0->low, f1->high
    unsigned r;
    asm("cvt.rn.bf16x2.f32 %0, %1, %2;" : "=r"(r) : "f"(f1), "f"(f0));
    return r;
}
__device__ __forceinline__ void split2(float f0, float f1, unsigned& hi, unsigned& lo) {
    hi = pack2(f0, f1);
    float h0 = __uint_as_float(hi << 16);
    float h1 = __uint_as_float(hi & 0xffff0000u);
    lo = pack2(f0 - h0, f1 - h1);
}
__device__ __forceinline__ void mma_bf16(float4& d, const unsigned a[4], const unsigned b[2]) {
    asm volatile(
        "mma.sync.aligned.m16n8k16.row.col.f32.bf16.bf16.f32 "
        "{%0,%1,%2,%3}, {%4,%5,%6,%7}, {%8,%9}, {%0,%1,%2,%3};"
        : "+f"(d.x), "+f"(d.y), "+f"(d.z), "+f"(d.w)
        : "r"(a[0]), "r"(a[1]), "r"(a[2]), "r"(a[3]), "r"(b[0]), "r"(b[1]));
}

#define RSTR 20   // smem row stride in uints
#define BN   128

__device__ __forceinline__ int posH(int p) { return 4 * (p & 3) + (p >> 2); }

template <int TBM, bool TA, bool TB, int MAXB, bool CONV>
__global__ void __launch_bounds__(256, MAXB) gemm_bf(
    const float* __restrict__ A, const float* __restrict__ Bm, float* __restrict__ C,
    int M, int N, int Kd, int lda, int ldb,
    long aS, int aDiv, long bS, long cS,
    const float* __restrict__ scaleC, const float* __restrict__ biasC, long biS,
    int relu, const float* __restrict__ gammaPtr,
    const float* __restrict__ resid, long rS)
{
    extern __shared__ unsigned sm[];
    unsigned* As = sm;                       // [2][TBM][RSTR]
    unsigned* Bs = sm + 2 * TBM * RSTR;      // [2][BN ][RSTR]

    const int z = blockIdx.z;
    A  += (long)(z / aDiv) * aS;
    Bm += (long)z * bS;
    C  += (long)z * cS;
    if (biasC) biasC += (long)(z / aDiv) * biS;
    if (resid) resid += (long)z * rS;

    const int tid  = threadIdx.x;
    const int lane = tid & 31, warp = tid >> 5;
    constexpr int MI = TBM / 32;            // 2 or 4
    constexpr int NJ = 4;
    constexpr int UA = TBM / 32;            // A pairs per thread
    constexpr int UB = 4;                   // B pairs per thread
    constexpr int LBM = (TBM == 128) ? 7 : 6;
    const int wm = (warp >> 2) * (TBM / 2);
    const int wn = (warp & 3) * 32;
    const int m0 = blockIdx.y * TBM, n0 = blockIdx.x * BN;

    float4 acc[MI][NJ];
    #pragma unroll
    for (int i = 0; i < MI; ++i)
        #pragma unroll
        for (int j = 0; j < NJ; ++j)
            acc[i][j] = make_float4(0.f, 0.f, 0.f, 0.f);

    float2 va[UA], vb[UB];

    auto loadA = [&](int k0) {
        if (CONV) {   // weights [M][ci*9+t], consumed with k = t*256+ci
            #pragma unroll
            for (int t = 0; t < UA; ++t) {
                int i = tid + t * 256;
                int p = i & 7, m = i >> 3;
                int gm = m0 + m;
                int k = k0 + 2 * p;
                int ci = k & 255, tq = k >> 8;
                float f0 = 0.f, f1 = 0.f;
                if (gm < M) {
                    long idx = (long)gm * lda + ci * 9 + tq;
                    f0 = A[idx];
                    f1 = A[idx + 9];   // ci+1 (no carry: ci even, <=254 in-tile)
                }
                va[t] = make_float2(f0, f1);
            }
        } else if (!TA) {   // A [M,K]: 8 threads per row, float2 (k-pair) each
            #pragma unroll
            for (int t = 0; t < UA; ++t) {
                int i = tid + t * 256;
                int p = i & 7, m = i >> 3;
                int gm = m0 + m;
                va[t] = (gm < M) ? *(const float2*)&A[(long)gm * lda + k0 + 2 * p]
                                 : make_float2(0.f, 0.f);
            }
        } else {     // A [K,M]: coalesced across m, two strided rows per pair
            int m = tid & (TBM - 1), psel = tid >> LBM;
            int gm = m0 + m;
            #pragma unroll
            for (int t = 0; t < UA; ++t) {
                int p = psel * UA + t;
                float f0 = 0.f, f1 = 0.f;
                if (gm < M) {
                    f0 = A[(long)(k0 + 2 * p) * lda + gm];
                    f1 = A[(long)(k0 + 2 * p + 1) * lda + gm];
                }
                va[t] = make_float2(f0, f1);
            }
        }
    };
    auto loadB = [&](int k0) {
        if (CONV) {   // implicit im2col from x [C,H,W]; t = k0>>8 uniform per tile
            int t_ = k0 >> 8;
            int dh = t_ / 3 - 1, dw = t_ % 3 - 1;   // uniform (t_ same for all threads)
            int n = tid & 127, psel = tid >> 7;
            int gn = n0 + n;
            int h = gn / W_, w = gn - h * W_;
            int hh = h + dh, ww = w + dw;
            bool ok = (gn < N) && ((unsigned)hh < (unsigned)H_) && ((unsigned)ww < (unsigned)W_);
            long base = (long)(k0 & 255) * HW + hh * W_ + ww;
            #pragma unroll
            for (int t = 0; t < UB; ++t) {
                int p = psel * UB + t;
                float f0 = ok ? Bm[base + (long)(2 * p) * HW] : 0.f;
                float f1 = ok ? Bm[base + (long)(2 * p + 1) * HW] : 0.f;
                vb[t] = make_float2(f0, f1);
            }
        } else if (TB) {    // B [N,K]: 8 threads per row, float2 each
            #pragma unroll
            for (int t = 0; t < UB; ++t) {
                int i = tid + t * 256;
                int p = i & 7, n = i >> 3;
                int gn = n0 + n;
                vb[t] = (gn < N) ? *(const float2*)&Bm[(long)gn * ldb + k0 + 2 * p]
                                 : make_float2(0.f, 0.f);
            }
        } else {     // B [K,N]: coalesced across n, two strided rows per pair
            int n = tid & 127, psel = tid >> 7;
            int gn = n0 + n;
            #pragma unroll
            for (int t = 0; t < UB; ++t) {
                int p = psel * UB + t;
                float f0 = 0.f, f1 = 0.f;
                if (gn < N) {
                    f0 = Bm[(long)(k0 + 2 * p) * ldb + gn];
                    f1 = Bm[(long)(k0 + 2 * p + 1) * ldb + gn];
                }
                vb[t] = make_float2(f0, f1);
            }
        }
    };
    auto storeA = [&](int buf) {
        if (CONV || !TA) {
            #pragma unroll
            for (int t = 0; t < UA; ++t) {
                int i = tid + t * 256;
                int p = i & 7, m = i >> 3;
                unsigned hi, lo;
                split2(va[t].x, va[t].y, hi, lo);
                unsigned* base = &As[(long)(buf * TBM + m) * RSTR];
                int ph = posH(p);
                base[ph]     = hi;
                base[ph + 2] = lo;
            }
        } else {
            int m = tid & (TBM - 1), psel = tid >> LBM;
            #pragma unroll
            for (int t = 0; t < UA; ++t) {
                int p = psel * UA + t;
                unsigned hi, lo;
                split2(va[t].x, va[t].y, hi, lo);
                unsigned* base = &As[(long)(buf * TBM + m) * RSTR];
                int ph = posH(p);
                base[ph]     = hi;
                base[ph + 2] = lo;
            }
        }
    };
    auto storeB = [&](int buf) {
        if (!CONV && TB) {
            #pragma unroll
            for (int t = 0; t < UB; ++t) {
                int i = tid + t * 256;
                int p = i & 7, n = i >> 3;
                unsigned hi, lo;
                split2(vb[t].x, vb[t].y, hi, lo);
                unsigned* base = &Bs[(long)(buf * BN + n) * RSTR];
                int ph = posH(p);
                base[ph]     = hi;
                base[ph + 2] = lo;
            }
        } else {
            int n = tid & 127, psel = tid >> 7;
            #pragma unroll
            for (int t = 0; t < UB; ++t) {
                int p = psel * UB + t;
                unsigned hi, lo;
                split2(vb[t].x, vb[t].y, hi, lo);
                unsigned* base = &Bs[(long)(buf * BN + n) * RSTR];
                int ph = posH(p);
                base[ph]     = hi;
                base[ph + 2] = lo;
            }
        }
    };
    auto compute = [&](int buf) {
        uint4 a0[MI], a1[MI], bv[NJ];
        #pragma unroll
        for (int i = 0; i < MI; ++i) {
            int r = wm + i * 16 + (lane >> 2);
            a0[i] = *(const uint4*)&As[(long)(buf * TBM + r) * RSTR + ((lane & 3) << 2)];
            a1[i] = *(const uint4*)&As[(long)(buf * TBM + r + 8) * RSTR + ((lane & 3) << 2)];
        }
        #pragma unroll
        for (int j = 0; j < NJ; ++j) {
            int c = wn + j * 8 + (lane >> 2);
            bv[j] = *(const uint4*)&Bs[(long)(buf * BN + c) * RSTR + ((lane & 3) << 2)];
        }
        unsigned aH[MI][4], aL[MI][4], bH[NJ][2], bL[NJ][2];
        #pragma unroll
        for (int i = 0; i < MI; ++i) {
            aH[i][0] = a0[i].x; aH[i][1] = a1[i].x; aH[i][2] = a0[i].y; aH[i][3] = a1[i].y;
            aL[i][0] = a0[i].z; aL[i][1] = a1[i].z; aL[i][2] = a0[i].w; aL[i][3] = a1[i].w;
        }
        #pragma unroll
        for (int j = 0; j < NJ; ++j) {
            bH[j][0] = bv[j].x; bH[j][1] = bv[j].y;
            bL[j][0] = bv[j].z; bL[j][1] = bv[j].w;
        }
        #pragma unroll
        for (int j = 0; j < NJ; ++j)
            #pragma unroll
            for (int i = 0; i < MI; ++i)
                mma_bf16(acc[i][j], aH[i], bH[j]);   // hi*hi
        #pragma unroll
        for (int j = 0; j < NJ; ++j)
            #pragma unroll
            for (int i = 0; i < MI; ++i)
                mma_bf16(acc[i][j], aH[i], bL[j]);   // hi*lo
        #pragma unroll
        for (int j = 0; j < NJ; ++j)
            #pragma unroll
            for (int i = 0; i < MI; ++i)
                mma_bf16(acc[i][j], aL[i], bH[j]);   // lo*hi
    };

    // -------- R8 mainloop: next-tile loads issued before compute --------
    int buf = 0;
    loadA(0); loadB(0);
    storeA(0); storeB(0);
    __syncthreads();

    for (int k0 = 0; k0 < Kd; k0 += 16) {
        bool more = (k0 + 16) < Kd;
        if (more) { loadA(k0 + 16); loadB(k0 + 16); }
        compute(buf);
        if (more) {
            storeA(buf ^ 1); storeB(buf ^ 1);
            __syncthreads();
            buf ^= 1;
        }
    }

    const float gmv = gammaPtr ? *gammaPtr : 1.f;
    #pragma unroll
    for (int i = 0; i < MI; ++i) {
        int r0 = m0 + wm + i * 16 + (lane >> 2);
        int r1 = r0 + 8;
        float sc0 = 1.f, bi0 = 0.f, sc1 = 1.f, bi1 = 0.f;
        if (scaleC) { if (r0 < M) sc0 = scaleC[r0]; if (r1 < M) sc1 = scaleC[r1]; }
        if (biasC)  { if (r0 < M) bi0 = biasC[r0];  if (r1 < M) bi1 = biasC[r1]; }
        #pragma unroll
        for (int j = 0; j < NJ; ++j) {
            int c = n0 + wn + j * 8 + ((lane & 3) << 1);
            float4 v = acc[i][j];
            if (r0 < M) {
                float x0 = v.x * sc0 + bi0, x1 = v.y * sc0 + bi0;
                if (relu) { x0 = fmaxf(x0, 0.f); x1 = fmaxf(x1, 0.f); }
                if (resid) {
                    if (c < N)     x0 = x0 * gmv + resid[(long)r0 * N + c];
                    if (c + 1 < N) x1 = x1 * gmv + resid[(long)r0 * N + c + 1];
                }
                if (c < N)     C[(long)r0 * N + c]     = x0;
                if (c + 1 < N) C[(long)r0 * N + c + 1] = x1;
            }
            if (r1 < M) {
                float y0 = v.z * sc1 + bi1, y1 = v.w * sc1 + bi1;
                if (relu) { y0 = fmaxf(y0, 0.f); y1 = fmaxf(y1, 0.f); }
                if (resid) {
                    if (c < N)     y0 = y0 * gmv + resid[(long)r1 * N + c];
                    if (c + 1 < N) y1 = y1 * gmv + resid[(long)r1 * N + c + 1];
                }
                if (c < N)     C[(long)r1 * N + c]     = y0;
                if (c + 1 < N) C[(long)r1 * N + c + 1] = y1;
            }
        }
    }
}

// ---------------- pointwise kernels -----------------------------------------
__global__ void tshuffle_kernel(const float* __restrict__ pf,
                                const float* __restrict__ gw,
                                const float* __restrict__ gb,
                                float* __restrict__ out)
{
    int idx = blockIdx.x * blockDim.x + threadIdx.x;
    if (idx >= B_SZ * COUT * HW) return;
    int c = (idx / HW) % COUT;
    float s = gb[c];
    #pragma unroll
    for (int k = 0; k < K_FR; ++k)
        s = fmaf(pf[(long)k * (B_SZ * COUT * HW) + idx], gw[c * K_FR + k], s);
    out[idx] = s;
}

// computes all 4 BN (slot = blockIdx.x): scale/bias into g_bnA/g_bnB[slot]
__global__ void bnprep4_kernel(const float* __restrict__ p0,
                               const float* __restrict__ p1,
                               const float* __restrict__ p2,
                               const float* __restrict__ p3,
                               float* __restrict__ a, float* __restrict__ b)
{
    int c = threadIdx.x;
    int slot = blockIdx.x;
    const float* p = (slot == 0) ? p0 : (slot == 1) ? p1 : (slot == 2) ? p2 : p3;
    float g = p[c], be = p[COUT + c], m = p[2 * COUT + c], v = p[3 * COUT + c];
    float s = g * rsqrtf(v + 1e-5f);
    a[slot * COUT + c] = s;
    b[slot * COUT + c] = be - m * s;
}

__global__ void softmax_kernel(float* __restrict__ S, int len, float scale)
{
    float* p = S + (long)blockIdx.x * len;
    __shared__ float red[256];
    int tid = threadIdx.x;
    float mx = -1e30f;
    for (int j = tid; j < len; j += 256) mx = fmaxf(mx, p[j] * scale);
    red[tid] = mx; __syncthreads();
    for (int s = 128; s > 0; s >>= 1) {
        if (tid < s) red[tid] = fmaxf(red[tid], red[tid + s]);
        __syncthreads();
    }
    mx = red[0]; __syncthreads();
    float sum = 0.f;
    for (int j = tid; j < len; j += 256) {
        float e = expf(p[j] * scale - mx);
        p[j] = e; sum += e;
    }
    red[tid] = sum; __syncthreads();
    for (int s = 128; s > 0; s >>= 1) {
        if (tid < s) red[tid] += red[tid + s];
        __syncthreads();
    }
    float inv = 1.f / red[0];
    for (int j = tid; j < len; j += 256) p[j] *= inv;
}

__global__ void concat_kernel(const float* __restrict__ kf,
                              const float* __restrict__ x,
                              float* __restrict__ cat)
{
    long idx = (long)blockIdx.x * blockDim.x + threadIdx.x;
    const long total = (long)B_SZ * 2 * COUT * HW;
    if (idx >= total) return;
    int n = (int)(idx % HW);
    long r = idx / HW;
    int c = (int)(r % (2 * COUT));
    int b = (int)(r / (2 * COUT));
    cat[idx] = (c < COUT) ? kf[((long)b * COUT + c) * HW + n]
                          : x[((long)b * COUT + (c - COUT)) * HW + n];
}

// ---------------- host-side helpers -----------------------------------------
static const int SMB_BIG   = (2 * 128 + 2 * 128) * RSTR * 4;   // 40960
static const int SMB_SMALL = (2 * 64 + 2 * 128) * RSTR * 4;    // 30720

// big: 128x128 tile (1 CTA); small: 64x128 tile (2 CTAs)
// mode: 0 = NN, 1 = TN (A transposed), 2 = NT (B transposed), 3 = CONV (small tile)
static void launch_gemm(int big, int mode,
                        const float* A, const float* B, float* C,
                        int M, int N, int Kd, int lda, int ldb,
                        long aS, int aDiv, long bS, long cS,
                        const float* sc, const float* bi, long biS,
                        int relu, const float* gp,
                        const float* res, long rS, int Z)
{
    dim3 block(256);
    if (mode == 3) {
        dim3 grid((N + 127) / 128, (M + 63) / 64, Z);
        cudaFuncSetAttribute(gemm_bf<64,false,false,2,true>,
                             cudaFuncAttributeMaxDynamicSharedMemorySize, SMB_SMALL);
        gemm_bf<64,false,false,2,true><<<grid, block, SMB_SMALL>>>(A, B, C, M, N, Kd, lda, ldb,
            aS, aDiv, bS, cS, sc, bi, biS, relu, gp, res, rS);
        return;
    }
    if (big) {
        dim3 grid((N + 127) / 128, (M + 127) / 128, Z);
        if (mode == 0) {
            cudaFuncSetAttribute(gemm_bf<128,false,false,1,false>,
                                 cudaFuncAttributeMaxDynamicSharedMemorySize, SMB_BIG);
            gemm_bf<128,false,false,1,false><<<grid, block, SMB_BIG>>>(A, B, C, M, N, Kd, lda, ldb,
                aS, aDiv, bS, cS, sc, bi, biS, relu, gp, res, rS);
        } else {  // mode 1
            cudaFuncSetAttribute(gemm_bf<128,true,false,1,false>,
                                 cudaFuncAttributeMaxDynamicSharedMemorySize, SMB_BIG);
            gemm_bf<128,true,false,1,false><<<grid, block, SMB_BIG>>>(A, B, C, M, N, Kd, lda, ldb,
                aS, aDiv, bS, cS, sc, bi, biS, relu, gp, res, rS);
        }
    } else {
        dim3 grid((N + 127) / 128, (M + 63) / 64, Z);
        if (mode == 0) {
            cudaFuncSetAttribute(gemm_bf<64,false,false,2,false>,
                                 cudaFuncAttributeMaxDynamicSharedMemorySize, SMB_SMALL);
            gemm_bf<64,false,false,2,false><<<grid, block, SMB_SMALL>>>(A, B, C, M, N, Kd, lda, ldb,
                aS, aDiv, bS, cS, sc, bi, biS, relu, gp, res, rS);
        } else {  // mode 2
            cudaFuncSetAttribute(gemm_bf<64,false,true,2,false>,
                                 cudaFuncAttributeMaxDynamicSharedMemorySize, SMB_SMALL);
            gemm_bf<64,false,true,2,false><<<grid, block, SMB_SMALL>>>(A, B, C, M, N, Kd, lda, ldb,
                aS, aDiv, bS, cS, sc, bi, biS, relu, gp, res, rS);
        }
    }
}

extern "C" void kernel_launch(void* const* d_in, const int* in_sizes, int n_in,
                              void* d_out, int out_size)
{
    const float* feats    = (const float*)d_in[0];
    const float* proj_w   = (const float*)d_in[1];
    const float* proj_b   = (const float*)d_in[2];
    const float* ts_gw    = (const float*)d_in[3];
    const float* ts_gb    = (const float*)d_in[4];
    const float* ts_w3    = (const float*)d_in[5];
    const float* ts_bn    = (const float*)d_in[6];
    const float* ssam_w1  = (const float*)d_in[7];
    const float* ssam_b1  = (const float*)d_in[8];
    const float* ssam_w2  = (const float*)d_in[9];
    const float* ssam_b2  = (const float*)d_in[10];
    const float* ssam_g   = (const float*)d_in[11];
    const float* csam_w1  = (const float*)d_in[12];
    const float* csam_b1  = (const float*)d_in[13];
    const float* csam_w2  = (const float*)d_in[14];
    const float* csam_b2  = (const float*)d_in[15];
    const float* fuse_w1  = (const float*)d_in[16];
    const float* fuse_bn1 = (const float*)d_in[17];
    const float* fuse_w2  = (const float*)d_in[18];
    const float* fuse_bn2 = (const float*)d_in[19];
    const float* fcsam_w1 = (const float*)d_in[20];
    const float* fcsam_b1 = (const float*)d_in[21];
    const float* fcsam_w2 = (const float*)d_in[22];
    const float* fcsam_b2 = (const float*)d_in[23];
    const float* fuse_w4  = (const float*)d_in[24];
    const float* fuse_bn4 = (const float*)d_in[25];
    float* out = (float*)d_out;

    float *pf, *x, *x2, *o1, *h, *aS_, *aC_, *cat, *bnA, *bnB;
    cudaGetSymbolAddress((void**)&pf,  g_pf);
    cudaGetSymbolAddress((void**)&x,   g_x);
    cudaGetSymbolAddress((void**)&x2,  g_x2);
    cudaGetSymbolAddress((void**)&o1,  g_o1);
    cudaGetSymbolAddress((void**)&h,   g_h);
    cudaGetSymbolAddress((void**)&aS_, g_aS);
    cudaGetSymbolAddress((void**)&aC_, g_aC);
    cudaGetSymbolAddress((void**)&cat, g_cat);
    cudaGetSymbolAddress((void**)&bnA, g_bnA);
    cudaGetSymbolAddress((void**)&bnB, g_bnB);

    const long SP  = (long)COUT * HW;
    const long SPH = (long)C4V * HW;
    const long SPS = (long)HW * HW;
    const long SPC = (long)COUT * COUT;
    const long SPCAT = (long)2 * COUT * HW;

    // 0. all BN scale/bias pairs up front (slots: 0=ts, 1=fuse1, 2=fuse2, 3=fuse4)
    bnprep4_kernel<<<4, 256>>>(ts_bn, fuse_bn1, fuse_bn2, fuse_bn4, bnA, bnB);

    // 1. per-frame 1x1 projection
    launch_gemm(1, 0, proj_w, feats, pf, COUT, HW, CIN, CIN, HW,
                (long)COUT * CIN, B_SZ, (long)CIN * HW, SP,
                nullptr, proj_b, COUT, 0, nullptr, nullptr, 0, K_FR * B_SZ);

    // 2. temporal shuffle + grouped 1x1 -> x
    {
        int total = B_SZ * COUT * HW;
        tshuffle_kernel<<<(total + 255) / 256, 256>>>(pf, ts_gw, ts_gb, x);
    }

    // 3. 3x3 conv (implicit im2col, k = t*256+ci) + BN -> x2
    launch_gemm(0, 3, ts_w3, x, x2, COUT, HW, COUT * 9, COUT * 9, 0,
                0, 1, SP, SP, bnA + 0 * COUT, bnB + 0 * COUT, 0, 0, nullptr, nullptr, 0, B_SZ);

    // 4. spatial self-attention (input x2, output x)
    launch_gemm(1, 1, x2, x2, aS_, HW, HW, COUT, HW, HW,
                SP, 1, SP, SPS, nullptr, nullptr, 0, 0, nullptr, nullptr, 0, B_SZ);
    softmax_kernel<<<B_SZ * HW, 256>>>(aS_, HW, 0.0625f);
    launch_gemm(0, 2, x2, aS_, o1, COUT, HW, HW, HW, HW,
                SP, 1, SPS, SP, nullptr, nullptr, 0, 0, nullptr, nullptr, 0, B_SZ);
    launch_gemm(1, 0, ssam_w1, o1, h, C4V, HW, COUT, COUT, HW,
                0, 1, SP, SPH, nullptr, ssam_b1, 0, 1, nullptr, nullptr, 0, B_SZ);
    launch_gemm(0, 0, ssam_w2, h, x, COUT, HW, C4V, C4V, HW,
                0, 1, SPH, SP, nullptr, ssam_b2, 0, 0, ssam_g, x2, SP, B_SZ);

    // 5. channel self-attention (input x, output x2)
    launch_gemm(0, 2, x, x, aC_, COUT, COUT, HW, HW, HW,
                SP, 1, SP, SPC, nullptr, nullptr, 0, 0, nullptr, nullptr, 0, B_SZ);
    softmax_kernel<<<B_SZ * COUT, 256>>>(aC_, COUT, 0.0625f);
    launch_gemm(0, 0, aC_, x, o1, COUT, HW, COUT, COUT, HW,
                SPC, 1, SP, SP, nullptr, nullptr, 0, 0, nullptr, nullptr, 0, B_SZ);
    launch_gemm(1, 0, csam_w1, o1, h, C4V, HW, COUT, COUT, HW,
                0, 1, SP, SPH, nullptr, csam_b1, 0, 1, nullptr, nullptr, 0, B_SZ);
    launch_gemm(0, 0, csam_w2, h, x2, COUT, HW, C4V, C4V, HW,
                0, 1, SPH, SP, nullptr, csam_b2, 0, 0, nullptr, x, SP, B_SZ);

    // 6. fuse: concat keyframe feat (pf[K-1]) with x2
    {
        long total = (long)B_SZ * SPCAT;
        concat_kernel<<<(int)((total + 255) / 256), 256>>>(
            pf + (long)(K_FR - 1) * B_SZ * SP, x2, cat);
    }
    launch_gemm(0, 0, fuse_w1, cat, x, COUT, HW, 2 * COUT, 2 * COUT, HW,
                0, 1, SPCAT, SP, bnA + 1 * COUT, bnB + 1 * COUT, 0, 1, nullptr, nullptr, 0, B_SZ);

    // 7. 3x3 conv (implicit) + BN + relu -> x2
    launch_gemm(0, 3, fuse_w2, x, x2, COUT, HW, COUT * 9, COUT * 9, 0,
                0, 1, SP, SP, bnA + 2 * COUT, bnB + 2 * COUT, 0, 1, nullptr, nullptr, 0, B_SZ);

    // 8. channel self-attention (input x2, output x)
    launch_gemm(0, 2, x2, x2, aC_, COUT, COUT, HW, HW, HW,
                SP, 1, SP, SPC, nullptr, nullptr, 0, 0, nullptr, nullptr, 0, B_SZ);
    softmax_kernel<<<B_SZ * COUT, 256>>>(aC_, COUT, 0.0625f);
    launch_gemm(0, 0, aC_, x2, o1, COUT, HW, COUT, COUT, HW,
                SPC, 1, SP, SP, nullptr, nullptr, 0, 0, nullptr, nullptr, 0, B_SZ);
    launch_gemm(1, 0, fcsam_w1, o1, h, C4V, HW, COUT, COUT, HW,
                0, 1, SP, SPH, nullptr, fcsam_b1, 0, 1, nullptr, nullptr, 0, B_SZ);
    launch_gemm(0, 0, fcsam_w2, h, x, COUT, HW, C4V, C4V, HW,
                0, 1, SPH, SP, nullptr, fcsam_b2, 0, 0, nullptr, x2, SP, B_SZ);

    // 9. final 3x3 conv (implicit) + BN + relu -> d_out
    launch_gemm(0, 3, fuse_w4, x, out, COUT, HW, COUT * 9, COUT * 9, 0,
                0, 1, SP, SP, bnA + 3 * COUT, bnB + 3 * COUT, 0, 1, nullptr, nullptr, 0, B_SZ);
}

// round 12
// speedup vs baseline: 1.8540x; 1.1629x over previous
#include <cuda_runtime.h>
#include <cuda_bf16.h>
#include <math.h>

#define K_FR 8
#define B_SZ 8
#define CIN  512
#define COUT 256
#define H_   28
#define W_   28
#define HW   784
#define C4V  1024
#define NKT  144          // conv k-tiles: 2304/16
#define NPAD 896          // padded pixel rows per k-tile (7*128)

// ---------------- scratch (device globals; no allocation at runtime) --------
__device__ __align__(16) float g_pf  [K_FR * B_SZ * COUT * HW];
__device__ __align__(16) float g_x   [B_SZ * COUT * HW];
__device__ __align__(16) float g_x2  [B_SZ * COUT * HW];
__device__ __align__(16) float g_o1  [B_SZ * COUT * HW];
__device__ __align__(16) float g_h   [B_SZ * C4V * HW];
__device__ __align__(16) float g_aS  [B_SZ * HW * HW];
__device__ __align__(16) float g_aC  [B_SZ * COUT * COUT];
__device__ __align__(16) float g_cat [B_SZ * 2 * COUT * HW];
__device__ __align__(16) unsigned g_colP [(long)B_SZ * NKT * NPAD * 16];  // 66MB, zero-init
__device__ float g_bnA [4 * COUT];
__device__ float g_bnB [4 * COUT];

// ---------------- 3xBF16 tensor-core GEMM (R8 mainloop) ---------------------
// a*b ~= aH*bH + aH*bL + aL*bH with bf16 hi/lo split (residual ~2^-16), fp32 acc.
// mma.m16n8k16.bf16; smem row: 8 k-pairs as bf16x2 words, group 4p =
// {hi(p), hi(p+4), lo(p), lo(p+4)} -> fragment = one LDS.128.
// A stride RSTR=20 uints; B stride 20, or 16 in CONVP mode.
// TA: A stored [K,M]; else [M,K].  TB: B stored [N,K]; else [K,N].
// CONVP: B comes PRE-PACKED from im2colpack_kernel ([kt][row<NPAD][16 uints],
//        already in final smem row format) -> loadB/storeB are a pure copy.
// epilogue: v = acc*scale[m]+bias[m]; relu; v = v*gamma + resid[m,n]
// Requires Kd % 16 == 0 (256/512/784/1024/2304).

__device__ __forceinline__ unsigned pack2(float f0, float f1) {   // f0->low, f1->high
    unsigned r;
    asm("cvt.rn.bf16x2.f32 %0, %1, %2;" : "=r"(r) : "f"(f1), "f"(f0));
    return r;
}
__device__ __forceinline__ void split2(float f0, float f1, unsigned& hi, unsigned& lo) {
    hi = pack2(f0, f1);
    float h0 = __uint_as_float(hi << 16);
    float h1 = __uint_as_float(hi & 0xffff0000u);
    lo = pack2(f0 - h0, f1 - h1);
}
__device__ __forceinline__ void mma_bf16(float4& d, const unsigned a[4], const unsigned b[2]) {
    asm volatile(
        "mma.sync.aligned.m16n8k16.row.col.f32.bf16.bf16.f32 "
        "{%0,%1,%2,%3}, {%4,%5,%6,%7}, {%8,%9}, {%0,%1,%2,%3};"
        : "+f"(d.x), "+f"(d.y), "+f"(d.z), "+f"(d.w)
        : "r"(a[0]), "r"(a[1]), "r"(a[2]), "r"(a[3]), "r"(b[0]), "r"(b[1]));
}

#define RSTR 20   // smem row stride in uints (fp32-staged tiles)
#define BN   128

__device__ __forceinline__ int posH(int p) { return 4 * (p & 3) + (p >> 2); }

template <int TBM, bool TA, bool TB, int MAXB, bool CONVP>
__global__ void __launch_bounds__(256, MAXB) gemm_bf(
    const float* __restrict__ A, const float* __restrict__ Bm, float* __restrict__ C,
    int M, int N, int Kd, int lda, int ldb,
    long aS, int aDiv, long bS, long cS,
    const float* __restrict__ scaleC, const float* __restrict__ biasC, long biS,
    int relu, const float* __restrict__ gammaPtr,
    const float* __restrict__ resid, long rS)
{
    constexpr int RSB = CONVP ? 16 : RSTR;
    extern __shared__ unsigned sm[];
    unsigned* As = sm;                       // [2][TBM][RSTR]
    unsigned* Bs = sm + 2 * TBM * RSTR;      // [2][BN ][RSB]

    const int z = blockIdx.z;
    A  += (long)(z / aDiv) * aS;
    Bm += (long)z * bS;
    C  += (long)z * cS;
    if (biasC) biasC += (long)(z / aDiv) * biS;
    if (resid) resid += (long)z * rS;

    const int tid  = threadIdx.x;
    const int lane = tid & 31, warp = tid >> 5;
    constexpr int MI = TBM / 32;            // 2 or 4
    constexpr int NJ = 4;
    constexpr int UA = TBM / 32;            // A pairs per thread
    constexpr int UB = 4;                   // B pairs per thread
    constexpr int LBM = (TBM == 128) ? 7 : 6;
    const int wm = (warp >> 2) * (TBM / 2);
    const int wn = (warp & 3) * 32;
    const int m0 = blockIdx.y * TBM, n0 = blockIdx.x * BN;

    float4 acc[MI][NJ];
    #pragma unroll
    for (int i = 0; i < MI; ++i)
        #pragma unroll
        for (int j = 0; j < NJ; ++j)
            acc[i][j] = make_float4(0.f, 0.f, 0.f, 0.f);

    float2 va[UA], vb[UB];
    uint4 vbP[2];   // CONVP staging (pure copy)

    auto loadA = [&](int k0) {
        if (CONVP || !TA) {   // A [M,K]: 8 threads per row, float2 (k-pair) each
            #pragma unroll
            for (int t = 0; t < UA; ++t) {
                int i = tid + t * 256;
                int p = i & 7, m = i >> 3;
                int gm = m0 + m;
                va[t] = (gm < M) ? *(const float2*)&A[(long)gm * lda + k0 + 2 * p]
                                 : make_float2(0.f, 0.f);
            }
        } else {     // A [K,M]: coalesced across m, two strided rows per pair
            int m = tid & (TBM - 1), psel = tid >> LBM;
            int gm = m0 + m;
            #pragma unroll
            for (int t = 0; t < UA; ++t) {
                int p = psel * UA + t;
                float f0 = 0.f, f1 = 0.f;
                if (gm < M) {
                    f0 = A[(long)(k0 + 2 * p) * lda + gm];
                    f1 = A[(long)(k0 + 2 * p + 1) * lda + gm];
                }
                va[t] = make_float2(f0, f1);
            }
        }
    };
    auto loadB = [&](int k0) {
        if (CONVP) {  // packed rows: [kt][row][16 uints]; copy 2 uint4 per thread
            const uint4* bp = reinterpret_cast<const uint4*>(Bm);
            long base = ((long)(k0 >> 4) * NPAD + n0) * 4;
            vbP[0] = bp[base + tid];
            vbP[1] = bp[base + tid + 256];
        } else if (TB) {    // B [N,K]: 8 threads per row, float2 each
            #pragma unroll
            for (int t = 0; t < UB; ++t) {
                int i = tid + t * 256;
                int p = i & 7, n = i >> 3;
                int gn = n0 + n;
                vb[t] = (gn < N) ? *(const float2*)&Bm[(long)gn * ldb + k0 + 2 * p]
                                 : make_float2(0.f, 0.f);
            }
        } else {     // B [K,N]: coalesced across n, two strided rows per pair
            int n = tid & 127, psel = tid >> 7;
            int gn = n0 + n;
            #pragma unroll
            for (int t = 0; t < UB; ++t) {
                int p = psel * UB + t;
                float f0 = 0.f, f1 = 0.f;
                if (gn < N) {
                    f0 = Bm[(long)(k0 + 2 * p) * ldb + gn];
                    f1 = Bm[(long)(k0 + 2 * p + 1) * ldb + gn];
                }
                vb[t] = make_float2(f0, f1);
            }
        }
    };
    auto storeA = [&](int buf) {
        if (CONVP || !TA) {
            #pragma unroll
            for (int t = 0; t < UA; ++t) {
                int i = tid + t * 256;
                int p = i & 7, m = i >> 3;
                unsigned hi, lo;
                split2(va[t].x, va[t].y, hi, lo);
                unsigned* base = &As[(long)(buf * TBM + m) * RSTR];
                int ph = posH(p);
                base[ph]     = hi;
                base[ph + 2] = lo;
            }
        } else {
            int m = tid & (TBM - 1), psel = tid >> LBM;
            #pragma unroll
            for (int t = 0; t < UA; ++t) {
                int p = psel * UA + t;
                unsigned hi, lo;
                split2(va[t].x, va[t].y, hi, lo);
                unsigned* base = &As[(long)(buf * TBM + m) * RSTR];
                int ph = posH(p);
                base[ph]     = hi;
                base[ph + 2] = lo;
            }
        }
    };
    auto storeB = [&](int buf) {
        if (CONVP) {  // identity copy: addr word = 4*tid -> conflict-free STS.128
            *(uint4*)&Bs[(long)(buf * BN + (tid >> 2)) * RSB + (tid & 3) * 4] = vbP[0];
            *(uint4*)&Bs[(long)(buf * BN + (tid >> 2) + 64) * RSB + (tid & 3) * 4] = vbP[1];
        } else if (TB) {
            #pragma unroll
            for (int t = 0; t < UB; ++t) {
                int i = tid + t * 256;
                int p = i & 7, n = i >> 3;
                unsigned hi, lo;
                split2(vb[t].x, vb[t].y, hi, lo);
                unsigned* base = &Bs[(long)(buf * BN + n) * RSB];
                int ph = posH(p);
                base[ph]     = hi;
                base[ph + 2] = lo;
            }
        } else {
            int n = tid & 127, psel = tid >> 7;
            #pragma unroll
            for (int t = 0; t < UB; ++t) {
                int p = psel * UB + t;
                unsigned hi, lo;
                split2(vb[t].x, vb[t].y, hi, lo);
                unsigned* base = &Bs[(long)(buf * BN + n) * RSB];
                int ph = posH(p);
                base[ph]     = hi;
                base[ph + 2] = lo;
            }
        }
    };
    auto compute = [&](int buf) {
        uint4 a0[MI], a1[MI], bv[NJ];
        #pragma unroll
        for (int i = 0; i < MI; ++i) {
            int r = wm + i * 16 + (lane >> 2);
            a0[i] = *(const uint4*)&As[(long)(buf * TBM + r) * RSTR + ((lane & 3) << 2)];
            a1[i] = *(const uint4*)&As[(long)(buf * TBM + r + 8) * RSTR + ((lane & 3) << 2)];
        }
        #pragma unroll
        for (int j = 0; j < NJ; ++j) {
            int c = wn + j * 8 + (lane >> 2);
            bv[j] = *(const uint4*)&Bs[(long)(buf * BN + c) * RSB + ((lane & 3) << 2)];
        }
        unsigned aH[MI][4], aL[MI][4], bH[NJ][2], bL[NJ][2];
        #pragma unroll
        for (int i = 0; i < MI; ++i) {
            aH[i][0] = a0[i].x; aH[i][1] = a1[i].x; aH[i][2] = a0[i].y; aH[i][3] = a1[i].y;
            aL[i][0] = a0[i].z; aL[i][1] = a1[i].z; aL[i][2] = a0[i].w; aL[i][3] = a1[i].w;
        }
        #pragma unroll
        for (int j = 0; j < NJ; ++j) {
            bH[j][0] = bv[j].x; bH[j][1] = bv[j].y;
            bL[j][0] = bv[j].z; bL[j][1] = bv[j].w;
        }
        #pragma unroll
        for (int j = 0; j < NJ; ++j)
            #pragma unroll
            for (int i = 0; i < MI; ++i)
                mma_bf16(acc[i][j], aH[i], bH[j]);   // hi*hi
        #pragma unroll
        for (int j = 0; j < NJ; ++j)
            #pragma unroll
            for (int i = 0; i < MI; ++i)
                mma_bf16(acc[i][j], aH[i], bL[j]);   // hi*lo
        #pragma unroll
        for (int j = 0; j < NJ; ++j)
            #pragma unroll
            for (int i = 0; i < MI; ++i)
                mma_bf16(acc[i][j], aL[i], bH[j]);   // lo*hi
    };

    // -------- R8 mainloop: next-tile loads issued before compute --------
    int buf = 0;
    loadA(0); loadB(0);
    storeA(0); storeB(0);
    __syncthreads();

    for (int k0 = 0; k0 < Kd; k0 += 16) {
        bool more = (k0 + 16) < Kd;
        if (more) { loadA(k0 + 16); loadB(k0 + 16); }
        compute(buf);
        if (more) {
            storeA(buf ^ 1); storeB(buf ^ 1);
            __syncthreads();
            buf ^= 1;
        }
    }

    const float gmv = gammaPtr ? *gammaPtr : 1.f;
    #pragma unroll
    for (int i = 0; i < MI; ++i) {
        int r0 = m0 + wm + i * 16 + (lane >> 2);
        int r1 = r0 + 8;
        float sc0 = 1.f, bi0 = 0.f, sc1 = 1.f, bi1 = 0.f;
        if (scaleC) { if (r0 < M) sc0 = scaleC[r0]; if (r1 < M) sc1 = scaleC[r1]; }
        if (biasC)  { if (r0 < M) bi0 = biasC[r0];  if (r1 < M) bi1 = biasC[r1]; }
        #pragma unroll
        for (int j = 0; j < NJ; ++j) {
            int c = n0 + wn + j * 8 + ((lane & 3) << 1);
            float4 v = acc[i][j];
            if (r0 < M) {
                float x0 = v.x * sc0 + bi0, x1 = v.y * sc0 + bi0;
                if (relu) { x0 = fmaxf(x0, 0.f); x1 = fmaxf(x1, 0.f); }
                if (resid) {
                    if (c < N)     x0 = x0 * gmv + resid[(long)r0 * N + c];
                    if (c + 1 < N) x1 = x1 * gmv + resid[(long)r0 * N + c + 1];
                }
                if (c < N)     C[(long)r0 * N + c]     = x0;
                if (c + 1 < N) C[(long)r0 * N + c + 1] = x1;
            }
            if (r1 < M) {
                float y0 = v.z * sc1 + bi1, y1 = v.w * sc1 + bi1;
                if (relu) { y0 = fmaxf(y0, 0.f); y1 = fmaxf(y1, 0.f); }
                if (resid) {
                    if (c < N)     y0 = y0 * gmv + resid[(long)r1 * N + c];
                    if (c + 1 < N) y1 = y1 * gmv + resid[(long)r1 * N + c + 1];
                }
                if (c < N)     C[(long)r1 * N + c]     = y0;
                if (c + 1 < N) C[(long)r1 * N + c + 1] = y1;
            }
        }
    }
}

// ---------------- pointwise kernels -----------------------------------------
__global__ void tshuffle_kernel(const float* __restrict__ pf,
                                const float* __restrict__ gw,
                                const float* __restrict__ gb,
                                float* __restrict__ out)
{
    int idx = blockIdx.x * blockDim.x + threadIdx.x;
    if (idx >= B_SZ * COUT * HW) return;
    int c = (idx / HW) % COUT;
    float s = gb[c];
    #pragma unroll
    for (int k = 0; k < K_FR; ++k)
        s = fmaf(pf[(long)k * (B_SZ * COUT * HW) + idx], gw[c * K_FR + k], s);
    out[idx] = s;
}

// computes all 4 BN (slot = blockIdx.x): scale/bias into g_bnA/g_bnB[slot]
__global__ void bnprep4_kernel(const float* __restrict__ p0,
                               const float* __restrict__ p1,
                               const float* __restrict__ p2,
                               const float* __restrict__ p3,
                               float* __restrict__ a, float* __restrict__ b)
{
    int c = threadIdx.x;
    int slot = blockIdx.x;
    const float* p = (slot == 0) ? p0 : (slot == 1) ? p1 : (slot == 2) ? p2 : p3;
    float g = p[c], be = p[COUT + c], m = p[2 * COUT + c], v = p[3 * COUT + c];
    float s = g * rsqrtf(v + 1e-5f);
    a[slot * COUT + c] = s;
    b[slot * COUT + c] = be - m * s;
}

// im2col + bf16 hi/lo split + pack into final smem-row format.
// Output row (z, kt, n): 16 uints, position posH(p)=hi(pair p), +2=lo(pair p),
// pair p covers col-k's (kt*16+2p, kt*16+2p+1), k = ci*9 + t (same order as
// classic im2col, so accumulation order matches the fp32-col path exactly).
__global__ void im2colpack_kernel(const float* __restrict__ x, unsigned* __restrict__ colP)
{
    long idx = (long)blockIdx.x * blockDim.x + threadIdx.x;
    const long total = (long)B_SZ * NKT * HW;
    if (idx >= total) return;
    int n  = (int)(idx % HW);
    long r = idx / HW;
    int kt = (int)(r % NKT);
    int z  = (int)(r / NKT);
    const float* xb = x + (long)z * COUT * HW;
    int h = n / W_, w = n % W_;

    unsigned rr[16];
    #pragma unroll
    for (int p = 0; p < 8; ++p) {
        int k0 = kt * 16 + 2 * p;
        float f0, f1;
        {
            int ci = k0 / 9, tq = k0 - ci * 9;
            int hh = h + tq / 3 - 1, ww = w + tq % 3 - 1;
            f0 = ((unsigned)hh < H_ && (unsigned)ww < W_) ? xb[(long)ci * HW + hh * W_ + ww] : 0.f;
        }
        {
            int k1 = k0 + 1;
            int ci = k1 / 9, tq = k1 - ci * 9;
            int hh = h + tq / 3 - 1, ww = w + tq % 3 - 1;
            f1 = ((unsigned)hh < H_ && (unsigned)ww < W_) ? xb[(long)ci * HW + hh * W_ + ww] : 0.f;
        }
        unsigned hi, lo;
        split2(f0, f1, hi, lo);
        int ph = posH(p);
        rr[ph]     = hi;
        rr[ph + 2] = lo;
    }
    unsigned* dst = colP + ((long)(z * NKT + kt) * NPAD + n) * 16;
    *(uint4*)(dst + 0)  = *(const uint4*)(rr + 0);
    *(uint4*)(dst + 4)  = *(const uint4*)(rr + 4);
    *(uint4*)(dst + 8)  = *(const uint4*)(rr + 8);
    *(uint4*)(dst + 12) = *(const uint4*)(rr + 12);
}

__global__ void softmax_kernel(float* __restrict__ S, int len, float scale)
{
    float* p = S + (long)blockIdx.x * len;
    __shared__ float red[256];
    int tid = threadIdx.x;
    float mx = -1e30f;
    for (int j = tid; j < len; j += 256) mx = fmaxf(mx, p[j] * scale);
    red[tid] = mx; __syncthreads();
    for (int s = 128; s > 0; s >>= 1) {
        if (tid < s) red[tid] = fmaxf(red[tid], red[tid + s]);
        __syncthreads();
    }
    mx = red[0]; __syncthreads();
    float sum = 0.f;
    for (int j = tid; j < len; j += 256) {
        float e = expf(p[j] * scale - mx);
        p[j] = e; sum += e;
    }
    red[tid] = sum; __syncthreads();
    for (int s = 128; s > 0; s >>= 1) {
        if (tid < s) red[tid] += red[tid + s];
        __syncthreads();
    }
    float inv = 1.f / red[0];
    for (int j = tid; j < len; j += 256) p[j] *= inv;
}

__global__ void concat_kernel(const float* __restrict__ kf,
                              const float* __restrict__ x,
                              float* __restrict__ cat)
{
    long idx = (long)blockIdx.x * blockDim.x + threadIdx.x;
    const long total = (long)B_SZ * 2 * COUT * HW;
    if (idx >= total) return;
    int n = (int)(idx % HW);
    long r = idx / HW;
    int c = (int)(r % (2 * COUT));
    int b = (int)(r / (2 * COUT));
    cat[idx] = (c < COUT) ? kf[((long)b * COUT + c) * HW + n]
                          : x[((long)b * COUT + (c - COUT)) * HW + n];
}

// ---------------- host-side helpers -----------------------------------------
static const int SMB_BIG   = (2 * 128 * RSTR + 2 * 128 * RSTR) * 4;   // 40960
static const int SMB_SMALL = (2 * 64 * RSTR + 2 * 128 * RSTR) * 4;    // 30720
static const int SMB_CONVP = (2 * 64 * RSTR + 2 * 128 * 16) * 4;      // 26624

// big: 128x128 tile (1 CTA); small: 64x128 tile (2 CTAs)
// mode: 0 = NN, 1 = TN (A transposed), 2 = NT (B transposed), 3 = CONVP (packed B)
static void launch_gemm(int big, int mode,
                        const float* A, const float* B, float* C,
                        int M, int N, int Kd, int lda, int ldb,
                        long aS, int aDiv, long bS, long cS,
                        const float* sc, const float* bi, long biS,
                        int relu, const float* gp,
                        const float* res, long rS, int Z)
{
    dim3 block(256);
    if (mode == 3) {
        dim3 grid((N + 127) / 128, (M + 63) / 64, Z);
        cudaFuncSetAttribute(gemm_bf<64,false,false,2,true>,
                             cudaFuncAttributeMaxDynamicSharedMemorySize, SMB_CONVP);
        gemm_bf<64,false,false,2,true><<<grid, block, SMB_CONVP>>>(A, B, C, M, N, Kd, lda, ldb,
            aS, aDiv, bS, cS, sc, bi, biS, relu, gp, res, rS);
        return;
    }
    if (big) {
        dim3 grid((N + 127) / 128, (M + 127) / 128, Z);
        if (mode == 0) {
            cudaFuncSetAttribute(gemm_bf<128,false,false,1,false>,
                                 cudaFuncAttributeMaxDynamicSharedMemorySize, SMB_BIG);
            gemm_bf<128,false,false,1,false><<<grid, block, SMB_BIG>>>(A, B, C, M, N, Kd, lda, ldb,
                aS, aDiv, bS, cS, sc, bi, biS, relu, gp, res, rS);
        } else {  // mode 1
            cudaFuncSetAttribute(gemm_bf<128,true,false,1,false>,
                                 cudaFuncAttributeMaxDynamicSharedMemorySize, SMB_BIG);
            gemm_bf<128,true,false,1,false><<<grid, block, SMB_BIG>>>(A, B, C, M, N, Kd, lda, ldb,
                aS, aDiv, bS, cS, sc, bi, biS, relu, gp, res, rS);
        }
    } else {
        dim3 grid((N + 127) / 128, (M + 63) / 64, Z);
        if (mode == 0) {
            cudaFuncSetAttribute(gemm_bf<64,false,false,2,false>,
                                 cudaFuncAttributeMaxDynamicSharedMemorySize, SMB_SMALL);
            gemm_bf<64,false,false,2,false><<<grid, block, SMB_SMALL>>>(A, B, C, M, N, Kd, lda, ldb,
                aS, aDiv, bS, cS, sc, bi, biS, relu, gp, res, rS);
        } else {  // mode 2
            cudaFuncSetAttribute(gemm_bf<64,false,true,2,false>,
                                 cudaFuncAttributeMaxDynamicSharedMemorySize, SMB_SMALL);
            gemm_bf<64,false,true,2,false><<<grid, block, SMB_SMALL>>>(A, B, C, M, N, Kd, lda, ldb,
                aS, aDiv, bS, cS, sc, bi, biS, relu, gp, res, rS);
        }
    }
}

extern "C" void kernel_launch(void* const* d_in, const int* in_sizes, int n_in,
                              void* d_out, int out_size)
{
    const float* feats    = (const float*)d_in[0];
    const float* proj_w   = (const float*)d_in[1];
    const float* proj_b   = (const float*)d_in[2];
    const float* ts_gw    = (const float*)d_in[3];
    const float* ts_gb    = (const float*)d_in[4];
    const float* ts_w3    = (const float*)d_in[5];
    const float* ts_bn    = (const float*)d_in[6];
    const float* ssam_w1  = (const float*)d_in[7];
    const float* ssam_b1  = (const float*)d_in[8];
    const float* ssam_w2  = (const float*)d_in[9];
    const float* ssam_b2  = (const float*)d_in[10];
    const float* ssam_g   = (const float*)d_in[11];
    const float* csam_w1  = (const float*)d_in[12];
    const float* csam_b1  = (const float*)d_in[13];
    const float* csam_w2  = (const float*)d_in[14];
    const float* csam_b2  = (const float*)d_in[15];
    const float* fuse_w1  = (const float*)d_in[16];
    const float* fuse_bn1 = (const float*)d_in[17];
    const float* fuse_w2  = (const float*)d_in[18];
    const float* fuse_bn2 = (const float*)d_in[19];
    const float* fcsam_w1 = (const float*)d_in[20];
    const float* fcsam_b1 = (const float*)d_in[21];
    const float* fcsam_w2 = (const float*)d_in[22];
    const float* fcsam_b2 = (const float*)d_in[23];
    const float* fuse_w4  = (const float*)d_in[24];
    const float* fuse_bn4 = (const float*)d_in[25];
    float* out = (float*)d_out;

    float *pf, *x, *x2, *o1, *h, *aS_, *aC_, *cat, *bnA, *bnB;
    unsigned* colP;
    cudaGetSymbolAddress((void**)&pf,   g_pf);
    cudaGetSymbolAddress((void**)&x,    g_x);
    cudaGetSymbolAddress((void**)&x2,   g_x2);
    cudaGetSymbolAddress((void**)&o1,   g_o1);
    cudaGetSymbolAddress((void**)&h,    g_h);
    cudaGetSymbolAddress((void**)&aS_,  g_aS);
    cudaGetSymbolAddress((void**)&aC_,  g_aC);
    cudaGetSymbolAddress((void**)&cat,  g_cat);
    cudaGetSymbolAddress((void**)&colP, g_colP);
    cudaGetSymbolAddress((void**)&bnA,  g_bnA);
    cudaGetSymbolAddress((void**)&bnB,  g_bnB);

    const long SP  = (long)COUT * HW;
    const long SPH = (long)C4V * HW;
    const long SPS = (long)HW * HW;
    const long SPC = (long)COUT * COUT;
    const long SPCAT = (long)2 * COUT * HW;
    const long SPCP  = (long)NKT * NPAD * 16;   // packed col plane (in 4B units)
    const long PACKTOT = (long)B_SZ * NKT * HW;

    // 0. all BN scale/bias pairs up front (slots: 0=ts, 1=fuse1, 2=fuse2, 3=fuse4)
    bnprep4_kernel<<<4, 256>>>(ts_bn, fuse_bn1, fuse_bn2, fuse_bn4, bnA, bnB);

    // 1. per-frame 1x1 projection
    launch_gemm(1, 0, proj_w, feats, pf, COUT, HW, CIN, CIN, HW,
                (long)COUT * CIN, B_SZ, (long)CIN * HW, SP,
                nullptr, proj_b, COUT, 0, nullptr, nullptr, 0, K_FR * B_SZ);

    // 2. temporal shuffle + grouped 1x1 -> x
    {
        int total = B_SZ * COUT * HW;
        tshuffle_kernel<<<(total + 255) / 256, 256>>>(pf, ts_gw, ts_gb, x);
    }

    // 3. 3x3 conv + BN -> x2  (packed im2col)
    im2colpack_kernel<<<(int)((PACKTOT + 255) / 256), 256>>>(x, colP);
    launch_gemm(0, 3, ts_w3, (const float*)colP, x2, COUT, HW, COUT * 9, COUT * 9, 0,
                0, 1, SPCP, SP, bnA + 0 * COUT, bnB + 0 * COUT, 0, 0, nullptr, nullptr, 0, B_SZ);

    // 4. spatial self-attention (input x2, output x)
    launch_gemm(1, 1, x2, x2, aS_, HW, HW, COUT, HW, HW,
                SP, 1, SP, SPS, nullptr, nullptr, 0, 0, nullptr, nullptr, 0, B_SZ);
    softmax_kernel<<<B_SZ * HW, 256>>>(aS_, HW, 0.0625f);
    launch_gemm(0, 2, x2, aS_, o1, COUT, HW, HW, HW, HW,
                SP, 1, SPS, SP, nullptr, nullptr, 0, 0, nullptr, nullptr, 0, B_SZ);
    launch_gemm(1, 0, ssam_w1, o1, h, C4V, HW, COUT, COUT, HW,
                0, 1, SP, SPH, nullptr, ssam_b1, 0, 1, nullptr, nullptr, 0, B_SZ);
    launch_gemm(0, 0, ssam_w2, h, x, COUT, HW, C4V, C4V, HW,
                0, 1, SPH, SP, nullptr, ssam_b2, 0, 0, ssam_g, x2, SP, B_SZ);

    // 5. channel self-attention (input x, output x2)
    launch_gemm(0, 2, x, x, aC_, COUT, COUT, HW, HW, HW,
                SP, 1, SP, SPC, nullptr, nullptr, 0, 0, nullptr, nullptr, 0, B_SZ);
    softmax_kernel<<<B_SZ * COUT, 256>>>(aC_, COUT, 0.0625f);
    launch_gemm(0, 0, aC_, x, o1, COUT, HW, COUT, COUT, HW,
                SPC, 1, SP, SP, nullptr, nullptr, 0, 0, nullptr, nullptr, 0, B_SZ);
    launch_gemm(1, 0, csam_w1, o1, h, C4V, HW, COUT, COUT, HW,
                0, 1, SP, SPH, nullptr, csam_b1, 0, 1, nullptr, nullptr, 0, B_SZ);
    launch_gemm(0, 0, csam_w2, h, x2, COUT, HW, C4V, C4V, HW,
                0, 1, SPH, SP, nullptr, csam_b2, 0, 0, nullptr, x, SP, B_SZ);

    // 6. fuse: concat keyframe feat (pf[K-1]) with x2
    {
        long total = (long)B_SZ * SPCAT;
        concat_kernel<<<(int)((total + 255) / 256), 256>>>(
            pf + (long)(K_FR - 1) * B_SZ * SP, x2, cat);
    }
    launch_gemm(0, 0, fuse_w1, cat, x, COUT, HW, 2 * COUT, 2 * COUT, HW,
                0, 1, SPCAT, SP, bnA + 1 * COUT, bnB + 1 * COUT, 0, 1, nullptr, nullptr, 0, B_SZ);

    // 7. 3x3 conv + BN + relu -> x2  (packed im2col)
    im2colpack_kernel<<<(int)((PACKTOT + 255) / 256), 256>>>(x, colP);
    launch_gemm(0, 3, fuse_w2, (const float*)colP, x2, COUT, HW, COUT * 9, COUT * 9, 0,
                0, 1, SPCP, SP, bnA + 2 * COUT, bnB + 2 * COUT, 0, 1, nullptr, nullptr, 0, B_SZ);

    // 8. channel self-attention (input x2, output x)
    launch_gemm(0, 2, x2, x2, aC_, COUT, COUT, HW, HW, HW,
                SP, 1, SP, SPC, nullptr, nullptr, 0, 0, nullptr, nullptr, 0, B_SZ);
    softmax_kernel<<<B_SZ * COUT, 256>>>(aC_, COUT, 0.0625f);
    launch_gemm(0, 0, aC_, x2, o1, COUT, HW, COUT, COUT, HW,
                SPC, 1, SP, SP, nullptr, nullptr, 0, 0, nullptr, nullptr, 0, B_SZ);
    launch_gemm(1, 0, fcsam_w1, o1, h, C4V, HW, COUT, COUT, HW,
                0, 1, SP, SPH, nullptr, fcsam_b1, 0, 1, nullptr, nullptr, 0, B_SZ);
    launch_gemm(0, 0, fcsam_w2, h, x, COUT, HW, C4V, C4V, HW,
                0, 1, SPH, SP, nullptr, fcsam_b2, 0, 0, nullptr, x2, SP, B_SZ);

    // 9. final 3x3 conv + BN + relu -> d_out  (packed im2col)
    im2colpack_kernel<<<(int)((PACKTOT + 255) / 256), 256>>>(x, colP);
    launch_gemm(0, 3, fuse_w4, (const float*)colP, out, COUT, HW, COUT * 9, COUT * 9, 0,
                0, 1, SPCP, SP, bnA + 3 * COUT, bnB + 3 * COUT, 0, 1, nullptr, nullptr, 0, B_SZ);
}

// round 13
// speedup vs baseline: 1.9491x; 1.0513x over previous
#include <cuda_runtime.h>
#include <cuda_bf16.h>
#include <math.h>

#define K_FR 8
#define B_SZ 8
#define CIN  512
#define COUT 256
#define H_   28
#define W_   28
#define HW   784
#define C4V  1024
#define NKT  144          // max k-tiles (conv: 2304/16)
#define NPAD 896          // padded pixel rows per k-tile (7*128)

// ---------------- scratch (device globals; no allocation at runtime) --------
__device__ __align__(16) float g_pf  [K_FR * B_SZ * COUT * HW];
__device__ __align__(16) float g_x   [B_SZ * COUT * HW];
__device__ __align__(16) float g_x2  [B_SZ * COUT * HW];
__device__ __align__(16) float g_o1  [B_SZ * COUT * HW];
__device__ __align__(16) float g_h   [B_SZ * C4V * HW];
__device__ __align__(16) float g_aS  [B_SZ * HW * HW];
__device__ __align__(16) float g_aC  [B_SZ * COUT * COUT];
__device__ __align__(16) unsigned g_colP [(long)B_SZ * NKT * NPAD * 16];  // 66MB, zero-init
__device__ float g_bnA [4 * COUT];
__device__ float g_bnB [4 * COUT];

// ---------------- 3xBF16 tensor-core GEMM (R8 mainloop) ---------------------
// a*b ~= aH*bH + aH*bL + aL*bH with bf16 hi/lo split (residual ~2^-16), fp32 acc.
// mma.m16n8k16.bf16; smem row: 8 k-pairs as bf16x2 words, group 4p =
// {hi(p), hi(p+4), lo(p), lo(p+4)} -> fragment = one LDS.128.
// A stride RSTR=20 uints; B stride 20, or 16 in CONVP mode.
// TA: A stored [K,M]; else [M,K].  TB: B stored [N,K]; else [K,N].
// CONVP: B comes PRE-PACKED ([kt][row<NPAD][16 uints], final smem row format)
//        -> loadB/storeB are a pure vector copy.
// epilogue: v = acc*scale[m]+bias[m]; relu; v = v*gamma + resid[m,n]
// Requires Kd % 16 == 0 (256/512/784/1024/2304).

__device__ __forceinline__ unsigned pack2(float f0, float f1) {   // f0->low, f1->high
    unsigned r;
    asm("cvt.rn.bf16x2.f32 %0, %1, %2;" : "=r"(r) : "f"(f1), "f"(f0));
    return r;
}
__device__ __forceinline__ void split2(float f0, float f1, unsigned& hi, unsigned& lo) {
    hi = pack2(f0, f1);
    float h0 = __uint_as_float(hi << 16);
    float h1 = __uint_as_float(hi & 0xffff0000u);
    lo = pack2(f0 - h0, f1 - h1);
}
__device__ __forceinline__ void mma_bf16(float4& d, const unsigned a[4], const unsigned b[2]) {
    asm volatile(
        "mma.sync.aligned.m16n8k16.row.col.f32.bf16.bf16.f32 "
        "{%0,%1,%2,%3}, {%4,%5,%6,%7}, {%8,%9}, {%0,%1,%2,%3};"
        : "+f"(d.x), "+f"(d.y), "+f"(d.z), "+f"(d.w)
        : "r"(a[0]), "r"(a[1]), "r"(a[2]), "r"(a[3]), "r"(b[0]), "r"(b[1]));
}

#define RSTR 20   // smem row stride in uints (fp32-staged tiles)
#define BN   128

__device__ __forceinline__ int posH(int p) { return 4 * (p & 3) + (p >> 2); }

template <int TBM, bool TA, bool TB, int MAXB, bool CONVP>
__global__ void __launch_bounds__(256, MAXB) gemm_bf(
    const float* __restrict__ A, const float* __restrict__ Bm, float* __restrict__ C,
    int M, int N, int Kd, int lda, int ldb,
    long aS, int aDiv, long bS, long cS,
    const float* __restrict__ scaleC, const float* __restrict__ biasC, long biS,
    int relu, const float* __restrict__ gammaPtr,
    const float* __restrict__ resid, long rS)
{
    constexpr int RSB = CONVP ? 16 : RSTR;
    extern __shared__ unsigned sm[];
    unsigned* As = sm;                       // [2][TBM][RSTR]
    unsigned* Bs = sm + 2 * TBM * RSTR;      // [2][BN ][RSB]

    const int z = blockIdx.z;
    A  += (long)(z / aDiv) * aS;
    Bm += (long)z * bS;
    C  += (long)z * cS;
    if (biasC) biasC += (long)(z / aDiv) * biS;
    if (resid) resid += (long)z * rS;

    const int tid  = threadIdx.x;
    const int lane = tid & 31, warp = tid >> 5;
    constexpr int MI = TBM / 32;            // 2 or 4
    constexpr int NJ = 4;
    constexpr int UA = TBM / 32;            // A pairs per thread
    constexpr int UB = 4;                   // B pairs per thread
    constexpr int LBM = (TBM == 128) ? 7 : 6;
    const int wm = (warp >> 2) * (TBM / 2);
    const int wn = (warp & 3) * 32;
    const int m0 = blockIdx.y * TBM, n0 = blockIdx.x * BN;

    float4 acc[MI][NJ];
    #pragma unroll
    for (int i = 0; i < MI; ++i)
        #pragma unroll
        for (int j = 0; j < NJ; ++j)
            acc[i][j] = make_float4(0.f, 0.f, 0.f, 0.f);

    float2 va[UA], vb[UB];
    uint4 vbP[2];   // CONVP staging (pure copy)

    auto loadA = [&](int k0) {
        if (CONVP || !TA) {   // A [M,K]: 8 threads per row, float2 (k-pair) each
            #pragma unroll
            for (int t = 0; t < UA; ++t) {
                int i = tid + t * 256;
                int p = i & 7, m = i >> 3;
                int gm = m0 + m;
                va[t] = (gm < M) ? *(const float2*)&A[(long)gm * lda + k0 + 2 * p]
                                 : make_float2(0.f, 0.f);
            }
        } else {     // A [K,M]: coalesced across m, two strided rows per pair
            int m = tid & (TBM - 1), psel = tid >> LBM;
            int gm = m0 + m;
            #pragma unroll
            for (int t = 0; t < UA; ++t) {
                int p = psel * UA + t;
                float f0 = 0.f, f1 = 0.f;
                if (gm < M) {
                    f0 = A[(long)(k0 + 2 * p) * lda + gm];
                    f1 = A[(long)(k0 + 2 * p + 1) * lda + gm];
                }
                va[t] = make_float2(f0, f1);
            }
        }
    };
    auto loadB = [&](int k0) {
        if (CONVP) {  // packed rows: [kt][row][16 uints]; copy 2 uint4 per thread
            const uint4* bp = reinterpret_cast<const uint4*>(Bm);
            long base = ((long)(k0 >> 4) * NPAD + n0) * 4;
            vbP[0] = bp[base + tid];
            vbP[1] = bp[base + tid + 256];
        } else if (TB) {    // B [N,K]: 8 threads per row, float2 each
            #pragma unroll
            for (int t = 0; t < UB; ++t) {
                int i = tid + t * 256;
                int p = i & 7, n = i >> 3;
                int gn = n0 + n;
                vb[t] = (gn < N) ? *(const float2*)&Bm[(long)gn * ldb + k0 + 2 * p]
                                 : make_float2(0.f, 0.f);
            }
        } else {     // B [K,N]: coalesced across n, two strided rows per pair
            int n = tid & 127, psel = tid >> 7;
            int gn = n0 + n;
            #pragma unroll
            for (int t = 0; t < UB; ++t) {
                int p = psel * UB + t;
                float f0 = 0.f, f1 = 0.f;
                if (gn < N) {
                    f0 = Bm[(long)(k0 + 2 * p) * ldb + gn];
                    f1 = Bm[(long)(k0 + 2 * p + 1) * ldb + gn];
                }
                vb[t] = make_float2(f0, f1);
            }
        }
    };
    auto storeA = [&](int buf) {
        if (CONVP || !TA) {
            #pragma unroll
            for (int t = 0; t < UA; ++t) {
                int i = tid + t * 256;
                int p = i & 7, m = i >> 3;
                unsigned hi, lo;
                split2(va[t].x, va[t].y, hi, lo);
                unsigned* base = &As[(long)(buf * TBM + m) * RSTR];
                int ph = posH(p);
                base[ph]     = hi;
                base[ph + 2] = lo;
            }
        } else {
            int m = tid & (TBM - 1), psel = tid >> LBM;
            #pragma unroll
            for (int t = 0; t < UA; ++t) {
                int p = psel * UA + t;
                unsigned hi, lo;
                split2(va[t].x, va[t].y, hi, lo);
                unsigned* base = &As[(long)(buf * TBM + m) * RSTR];
                int ph = posH(p);
                base[ph]     = hi;
                base[ph + 2] = lo;
            }
        }
    };
    auto storeB = [&](int buf) {
        if (CONVP) {  // identity copy: addr word = 4*tid -> conflict-free STS.128
            *(uint4*)&Bs[(long)(buf * BN + (tid >> 2)) * RSB + (tid & 3) * 4] = vbP[0];
            *(uint4*)&Bs[(long)(buf * BN + (tid >> 2) + 64) * RSB + (tid & 3) * 4] = vbP[1];
        } else if (TB) {
            #pragma unroll
            for (int t = 0; t < UB; ++t) {
                int i = tid + t * 256;
                int p = i & 7, n = i >> 3;
                unsigned hi, lo;
                split2(vb[t].x, vb[t].y, hi, lo);
                unsigned* base = &Bs[(long)(buf * BN + n) * RSB];
                int ph = posH(p);
                base[ph]     = hi;
                base[ph + 2] = lo;
            }
        } else {
            int n = tid & 127, psel = tid >> 7;
            #pragma unroll
            for (int t = 0; t < UB; ++t) {
                int p = psel * UB + t;
                unsigned hi, lo;
                split2(vb[t].x, vb[t].y, hi, lo);
                unsigned* base = &Bs[(long)(buf * BN + n) * RSB];
                int ph = posH(p);
                base[ph]     = hi;
                base[ph + 2] = lo;
            }
        }
    };
    auto compute = [&](int buf) {
        uint4 a0[MI], a1[MI], bv[NJ];
        #pragma unroll
        for (int i = 0; i < MI; ++i) {
            int r = wm + i * 16 + (lane >> 2);
            a0[i] = *(const uint4*)&As[(long)(buf * TBM + r) * RSTR + ((lane & 3) << 2)];
            a1[i] = *(const uint4*)&As[(long)(buf * TBM + r + 8) * RSTR + ((lane & 3) << 2)];
        }
        #pragma unroll
        for (int j = 0; j < NJ; ++j) {
            int c = wn + j * 8 + (lane >> 2);
            bv[j] = *(const uint4*)&Bs[(long)(buf * BN + c) * RSB + ((lane & 3) << 2)];
        }
        unsigned aH[MI][4], aL[MI][4], bH[NJ][2], bL[NJ][2];
        #pragma unroll
        for (int i = 0; i < MI; ++i) {
            aH[i][0] = a0[i].x; aH[i][1] = a1[i].x; aH[i][2] = a0[i].y; aH[i][3] = a1[i].y;
            aL[i][0] = a0[i].z; aL[i][1] = a1[i].z; aL[i][2] = a0[i].w; aL[i][3] = a1[i].w;
        }
        #pragma unroll
        for (int j = 0; j < NJ; ++j) {
            bH[j][0] = bv[j].x; bH[j][1] = bv[j].y;
            bL[j][0] = bv[j].z; bL[j][1] = bv[j].w;
        }
        #pragma unroll
        for (int j = 0; j < NJ; ++j)
            #pragma unroll
            for (int i = 0; i < MI; ++i)
                mma_bf16(acc[i][j], aH[i], bH[j]);   // hi*hi
        #pragma unroll
        for (int j = 0; j < NJ; ++j)
            #pragma unroll
            for (int i = 0; i < MI; ++i)
                mma_bf16(acc[i][j], aH[i], bL[j]);   // hi*lo
        #pragma unroll
        for (int j = 0; j < NJ; ++j)
            #pragma unroll
            for (int i = 0; i < MI; ++i)
                mma_bf16(acc[i][j], aL[i], bH[j]);   // lo*hi
    };

    // -------- R8 mainloop: next-tile loads issued before compute --------
    int buf = 0;
    loadA(0); loadB(0);
    storeA(0); storeB(0);
    __syncthreads();

    for (int k0 = 0; k0 < Kd; k0 += 16) {
        bool more = (k0 + 16) < Kd;
        if (more) { loadA(k0 + 16); loadB(k0 + 16); }
        compute(buf);
        if (more) {
            storeA(buf ^ 1); storeB(buf ^ 1);
            __syncthreads();
            buf ^= 1;
        }
    }

    const float gmv = gammaPtr ? *gammaPtr : 1.f;
    #pragma unroll
    for (int i = 0; i < MI; ++i) {
        int r0 = m0 + wm + i * 16 + (lane >> 2);
        int r1 = r0 + 8;
        float sc0 = 1.f, bi0 = 0.f, sc1 = 1.f, bi1 = 0.f;
        if (scaleC) { if (r0 < M) sc0 = scaleC[r0]; if (r1 < M) sc1 = scaleC[r1]; }
        if (biasC)  { if (r0 < M) bi0 = biasC[r0];  if (r1 < M) bi1 = biasC[r1]; }
        #pragma unroll
        for (int j = 0; j < NJ; ++j) {
            int c = n0 + wn + j * 8 + ((lane & 3) << 1);
            float4 v = acc[i][j];
            if (r0 < M) {
                float x0 = v.x * sc0 + bi0, x1 = v.y * sc0 + bi0;
                if (relu) { x0 = fmaxf(x0, 0.f); x1 = fmaxf(x1, 0.f); }
                if (resid) {
                    if (c < N)     x0 = x0 * gmv + resid[(long)r0 * N + c];
                    if (c + 1 < N) x1 = x1 * gmv + resid[(long)r0 * N + c + 1];
                }
                if (c < N)     C[(long)r0 * N + c]     = x0;
                if (c + 1 < N) C[(long)r0 * N + c + 1] = x1;
            }
            if (r1 < M) {
                float y0 = v.z * sc1 + bi1, y1 = v.w * sc1 + bi1;
                if (relu) { y0 = fmaxf(y0, 0.f); y1 = fmaxf(y1, 0.f); }
                if (resid) {
                    if (c < N)     y0 = y0 * gmv + resid[(long)r1 * N + c];
                    if (c + 1 < N) y1 = y1 * gmv + resid[(long)r1 * N + c + 1];
                }
                if (c < N)     C[(long)r1 * N + c]     = y0;
                if (c + 1 < N) C[(long)r1 * N + c + 1] = y1;
            }
        }
    }
}

// ---------------- pointwise kernels -----------------------------------------
__global__ void tshuffle_kernel(const float* __restrict__ pf,
                                const float* __restrict__ gw,
                                const float* __restrict__ gb,
                                float* __restrict__ out)
{
    int idx = blockIdx.x * blockDim.x + threadIdx.x;
    if (idx >= B_SZ * COUT * HW) return;
    int c = (idx / HW) % COUT;
    float s = gb[c];
    #pragma unroll
    for (int k = 0; k < K_FR; ++k)
        s = fmaf(pf[(long)k * (B_SZ * COUT * HW) + idx], gw[c * K_FR + k], s);
    out[idx] = s;
}

// computes all 4 BN (slot = blockIdx.x): scale/bias into g_bnA/g_bnB[slot]
__global__ void bnprep4_kernel(const float* __restrict__ p0,
                               const float* __restrict__ p1,
                               const float* __restrict__ p2,
                               const float* __restrict__ p3,
                               float* __restrict__ a, float* __restrict__ b)
{
    int c = threadIdx.x;
    int slot = blockIdx.x;
    const float* p = (slot == 0) ? p0 : (slot == 1) ? p1 : (slot == 2) ? p2 : p3;
    float g = p[c], be = p[COUT + c], m = p[2 * COUT + c], v = p[3 * COUT + c];
    float s = g * rsqrtf(v + 1e-5f);
    a[slot * COUT + c] = s;
    b[slot * COUT + c] = be - m * s;
}

// im2col + bf16 hi/lo split + pack into final smem-row format.
__global__ void im2colpack_kernel(const float* __restrict__ x, unsigned* __restrict__ colP)
{
    long idx = (long)blockIdx.x * blockDim.x + threadIdx.x;
    const long total = (long)B_SZ * NKT * HW;
    if (idx >= total) return;
    int n  = (int)(idx % HW);
    long r = idx / HW;
    int kt = (int)(r % NKT);
    int z  = (int)(r / NKT);
    const float* xb = x + (long)z * COUT * HW;
    int h = n / W_, w = n % W_;

    unsigned rr[16];
    #pragma unroll
    for (int p = 0; p < 8; ++p) {
        int k0 = kt * 16 + 2 * p;
        float f0, f1;
        {
            int ci = k0 / 9, tq = k0 - ci * 9;
            int hh = h + tq / 3 - 1, ww = w + tq % 3 - 1;
            f0 = ((unsigned)hh < H_ && (unsigned)ww < W_) ? xb[(long)ci * HW + hh * W_ + ww] : 0.f;
        }
        {
            int k1 = k0 + 1;
            int ci = k1 / 9, tq = k1 - ci * 9;
            int hh = h + tq / 3 - 1, ww = w + tq % 3 - 1;
            f1 = ((unsigned)hh < H_ && (unsigned)ww < W_) ? xb[(long)ci * HW + hh * W_ + ww] : 0.f;
        }
        unsigned hi, lo;
        split2(f0, f1, hi, lo);
        int ph = posH(p);
        rr[ph]     = hi;
        rr[ph + 2] = lo;
    }
    unsigned* dst = colP + ((long)(z * NKT + kt) * NPAD + n) * 16;
    *(uint4*)(dst + 0)  = *(const uint4*)(rr + 0);
    *(uint4*)(dst + 4)  = *(const uint4*)(rr + 4);
    *(uint4*)(dst + 8)  = *(const uint4*)(rr + 8);
    *(uint4*)(dst + 12) = *(const uint4*)(rr + 12);
}

// generic pack: src [z][K][HW] fp32 -> packed [z][kt][n][16] (ktCount = K/16)
__global__ void pack_kernel(const float* __restrict__ src, unsigned* __restrict__ colP,
                            int ktCount, long srcStride)
{
    long idx = (long)blockIdx.x * blockDim.x + threadIdx.x;
    const long total = (long)B_SZ * ktCount * HW;
    if (idx >= total) return;
    int n  = (int)(idx % HW);
    long r = idx / HW;
    int kt = (int)(r % ktCount);
    int z  = (int)(r / ktCount);
    const float* s = src + (long)z * srcStride + (long)(kt * 16) * HW + n;

    unsigned rr[16];
    #pragma unroll
    for (int p = 0; p < 8; ++p) {
        float f0 = s[(long)(2 * p) * HW];
        float f1 = s[(long)(2 * p + 1) * HW];
        unsigned hi, lo;
        split2(f0, f1, hi, lo);
        int ph = posH(p);
        rr[ph]     = hi;
        rr[ph + 2] = lo;
    }
    unsigned* dst = colP + ((long)(z * ktCount + kt) * NPAD + n) * 16;
    *(uint4*)(dst + 0)  = *(const uint4*)(rr + 0);
    *(uint4*)(dst + 4)  = *(const uint4*)(rr + 4);
    *(uint4*)(dst + 8)  = *(const uint4*)(rr + 8);
    *(uint4*)(dst + 12) = *(const uint4*)(rr + 12);
}

// concat keyframe feat with x2 AND pack (K=512 -> 32 k-tiles), no fp32 cat
__global__ void concatpack_kernel(const float* __restrict__ kf,
                                  const float* __restrict__ x,
                                  unsigned* __restrict__ colP)
{
    const int KT = 32;
    long idx = (long)blockIdx.x * blockDim.x + threadIdx.x;
    const long total = (long)B_SZ * KT * HW;
    if (idx >= total) return;
    int n  = (int)(idx % HW);
    long r = idx / HW;
    int kt = (int)(r % KT);
    int z  = (int)(r / KT);
    const float* s = (kt < 16 ? kf + (long)z * COUT * HW + (long)(kt * 16) * HW
                              : x  + (long)z * COUT * HW + (long)((kt - 16) * 16) * HW) + n;

    unsigned rr[16];
    #pragma unroll
    for (int p = 0; p < 8; ++p) {
        float f0 = s[(long)(2 * p) * HW];
        float f1 = s[(long)(2 * p + 1) * HW];
        unsigned hi, lo;
        split2(f0, f1, hi, lo);
        int ph = posH(p);
        rr[ph]     = hi;
        rr[ph + 2] = lo;
    }
    unsigned* dst = colP + ((long)(z * KT + kt) * NPAD + n) * 16;
    *(uint4*)(dst + 0)  = *(const uint4*)(rr + 0);
    *(uint4*)(dst + 4)  = *(const uint4*)(rr + 4);
    *(uint4*)(dst + 8)  = *(const uint4*)(rr + 8);
    *(uint4*)(dst + 12) = *(const uint4*)(rr + 12);
}

__global__ void softmax_kernel(float* __restrict__ S, int len, float scale)
{
    float* p = S + (long)blockIdx.x * len;
    __shared__ float red[256];
    int tid = threadIdx.x;
    float mx = -1e30f;
    for (int j = tid; j < len; j += 256) mx = fmaxf(mx, p[j] * scale);
    red[tid] = mx; __syncthreads();
    for (int s = 128; s > 0; s >>= 1) {
        if (tid < s) red[tid] = fmaxf(red[tid], red[tid + s]);
        __syncthreads();
    }
    mx = red[0]; __syncthreads();
    float sum = 0.f;
    for (int j = tid; j < len; j += 256) {
        float e = expf(p[j] * scale - mx);
        p[j] = e; sum += e;
    }
    red[tid] = sum; __syncthreads();
    for (int s = 128; s > 0; s >>= 1) {
        if (tid < s) red[tid] += red[tid + s];
        __syncthreads();
    }
    float inv = 1.f / red[0];
    for (int j = tid; j < len; j += 256) p[j] *= inv;
}

// ---------------- host-side helpers -----------------------------------------
static const int SMB_BIG        = (2 * 128 * RSTR + 2 * 128 * RSTR) * 4;   // 40960
static const int SMB_SMALL      = (2 * 64 * RSTR + 2 * 128 * RSTR) * 4;    // 30720
static const int SMB_CONVP      = (2 * 64 * RSTR + 2 * 128 * 16) * 4;      // 26624
static const int SMB_CONVP_BIG  = (2 * 128 * RSTR + 2 * 128 * 16) * 4;     // 36864

// big: 128x128 tile (1 CTA); small: 64x128 tile (2 CTAs)
// mode: 0 = NN, 1 = TN (A transposed), 2 = NT (B transposed), 3 = packed B
static void launch_gemm(int big, int mode,
                        const float* A, const float* B, float* C,
                        int M, int N, int Kd, int lda, int ldb,
                        long aS, int aDiv, long bS, long cS,
                        const float* sc, const float* bi, long biS,
                        int relu, const float* gp,
                        const float* res, long rS, int Z)
{
    dim3 block(256);
    if (mode == 3) {
        if (big) {
            dim3 grid((N + 127) / 128, (M + 127) / 128, Z);
            cudaFuncSetAttribute(gemm_bf<128,false,false,1,true>,
                                 cudaFuncAttributeMaxDynamicSharedMemorySize, SMB_CONVP_BIG);
            gemm_bf<128,false,false,1,true><<<grid, block, SMB_CONVP_BIG>>>(A, B, C, M, N, Kd, lda, ldb,
                aS, aDiv, bS, cS, sc, bi, biS, relu, gp, res, rS);
        } else {
            dim3 grid((N + 127) / 128, (M + 63) / 64, Z);
            cudaFuncSetAttribute(gemm_bf<64,false,false,2,true>,
                                 cudaFuncAttributeMaxDynamicSharedMemorySize, SMB_CONVP);
            gemm_bf<64,false,false,2,true><<<grid, block, SMB_CONVP>>>(A, B, C, M, N, Kd, lda, ldb,
                aS, aDiv, bS, cS, sc, bi, biS, relu, gp, res, rS);
        }
        return;
    }
    if (big) {
        dim3 grid((N + 127) / 128, (M + 127) / 128, Z);
        if (mode == 0) {
            cudaFuncSetAttribute(gemm_bf<128,false,false,1,false>,
                                 cudaFuncAttributeMaxDynamicSharedMemorySize, SMB_BIG);
            gemm_bf<128,false,false,1,false><<<grid, block, SMB_BIG>>>(A, B, C, M, N, Kd, lda, ldb,
                aS, aDiv, bS, cS, sc, bi, biS, relu, gp, res, rS);
        } else {  // mode 1
            cudaFuncSetAttribute(gemm_bf<128,true,false,1,false>,
                                 cudaFuncAttributeMaxDynamicSharedMemorySize, SMB_BIG);
            gemm_bf<128,true,false,1,false><<<grid, block, SMB_BIG>>>(A, B, C, M, N, Kd, lda, ldb,
                aS, aDiv, bS, cS, sc, bi, biS, relu, gp, res, rS);
        }
    } else {
        dim3 grid((N + 127) / 128, (M + 63) / 64, Z);
        if (mode == 0) {
            cudaFuncSetAttribute(gemm_bf<64,false,false,2,false>,
                                 cudaFuncAttributeMaxDynamicSharedMemorySize, SMB_SMALL);
            gemm_bf<64,false,false,2,false><<<grid, block, SMB_SMALL>>>(A, B, C, M, N, Kd, lda, ldb,
                aS, aDiv, bS, cS, sc, bi, biS, relu, gp, res, rS);
        } else {  // mode 2
            cudaFuncSetAttribute(gemm_bf<64,false,true,2,false>,
                                 cudaFuncAttributeMaxDynamicSharedMemorySize, SMB_SMALL);
            gemm_bf<64,false,true,2,false><<<grid, block, SMB_SMALL>>>(A, B, C, M, N, Kd, lda, ldb,
                aS, aDiv, bS, cS, sc, bi, biS, relu, gp, res, rS);
        }
    }
}

extern "C" void kernel_launch(void* const* d_in, const int* in_sizes, int n_in,
                              void* d_out, int out_size)
{
    const float* feats    = (const float*)d_in[0];
    const float* proj_w   = (const float*)d_in[1];
    const float* proj_b   = (const float*)d_in[2];
    const float* ts_gw    = (const float*)d_in[3];
    const float* ts_gb    = (const float*)d_in[4];
    const float* ts_w3    = (const float*)d_in[5];
    const float* ts_bn    = (const float*)d_in[6];
    const float* ssam_w1  = (const float*)d_in[7];
    const float* ssam_b1  = (const float*)d_in[8];
    const float* ssam_w2  = (const float*)d_in[9];
    const float* ssam_b2  = (const float*)d_in[10];
    const float* ssam_g   = (const float*)d_in[11];
    const float* csam_w1  = (const float*)d_in[12];
    const float* csam_b1  = (const float*)d_in[13];
    const float* csam_w2  = (const float*)d_in[14];
    const float* csam_b2  = (const float*)d_in[15];
    const float* fuse_w1  = (const float*)d_in[16];
    const float* fuse_bn1 = (const float*)d_in[17];
    const float* fuse_w2  = (const float*)d_in[18];
    const float* fuse_bn2 = (const float*)d_in[19];
    const float* fcsam_w1 = (const float*)d_in[20];
    const float* fcsam_b1 = (const float*)d_in[21];
    const float* fcsam_w2 = (const float*)d_in[22];
    const float* fcsam_b2 = (const float*)d_in[23];
    const float* fuse_w4  = (const float*)d_in[24];
    const float* fuse_bn4 = (const float*)d_in[25];
    float* out = (float*)d_out;

    float *pf, *x, *x2, *o1, *h, *aS_, *aC_, *bnA, *bnB;
    unsigned* colP;
    cudaGetSymbolAddress((void**)&pf,   g_pf);
    cudaGetSymbolAddress((void**)&x,    g_x);
    cudaGetSymbolAddress((void**)&x2,   g_x2);
    cudaGetSymbolAddress((void**)&o1,   g_o1);
    cudaGetSymbolAddress((void**)&h,    g_h);
    cudaGetSymbolAddress((void**)&aS_,  g_aS);
    cudaGetSymbolAddress((void**)&aC_,  g_aC);
    cudaGetSymbolAddress((void**)&colP, g_colP);
    cudaGetSymbolAddress((void**)&bnA,  g_bnA);
    cudaGetSymbolAddress((void**)&bnB,  g_bnB);

    const long SP  = (long)COUT * HW;
    const long SPH = (long)C4V * HW;
    const long SPS = (long)HW * HW;
    const long SPC = (long)COUT * COUT;
    const long SPP16  = (long)16 * NPAD * 16;    // packed plane, K=256
    const long SPP32  = (long)32 * NPAD * 16;    // packed plane, K=512
    const long SPP64  = (long)64 * NPAD * 16;    // packed plane, K=1024
    const long SPP144 = (long)NKT * NPAD * 16;   // packed plane, K=2304
    const long PACKC  = (long)B_SZ * NKT * HW;   // conv pack total

    // 0. all BN scale/bias pairs up front (slots: 0=ts, 1=fuse1, 2=fuse2, 3=fuse4)
    bnprep4_kernel<<<4, 256>>>(ts_bn, fuse_bn1, fuse_bn2, fuse_bn4, bnA, bnB);

    // 1. per-frame 1x1 projection
    launch_gemm(1, 0, proj_w, feats, pf, COUT, HW, CIN, CIN, HW,
                (long)COUT * CIN, B_SZ, (long)CIN * HW, SP,
                nullptr, proj_b, COUT, 0, nullptr, nullptr, 0, K_FR * B_SZ);

    // 2. temporal shuffle + grouped 1x1 -> x
    {
        int total = B_SZ * COUT * HW;
        tshuffle_kernel<<<(total + 255) / 256, 256>>>(pf, ts_gw, ts_gb, x);
    }

    // 3. 3x3 conv + BN -> x2  (packed im2col)
    im2colpack_kernel<<<(int)((PACKC + 255) / 256), 256>>>(x, colP);
    launch_gemm(0, 3, ts_w3, (const float*)colP, x2, COUT, HW, COUT * 9, COUT * 9, 0,
                0, 1, SPP144, SP, bnA + 0 * COUT, bnB + 0 * COUT, 0, 0, nullptr, nullptr, 0, B_SZ);

    // 4. spatial self-attention (input x2, output x)
    launch_gemm(1, 1, x2, x2, aS_, HW, HW, COUT, HW, HW,
                SP, 1, SP, SPS, nullptr, nullptr, 0, 0, nullptr, nullptr, 0, B_SZ);
    softmax_kernel<<<B_SZ * HW, 256>>>(aS_, HW, 0.0625f);
    launch_gemm(0, 2, x2, aS_, o1, COUT, HW, HW, HW, HW,
                SP, 1, SPS, SP, nullptr, nullptr, 0, 0, nullptr, nullptr, 0, B_SZ);
    pack_kernel<<<(int)(((long)B_SZ * 16 * HW + 255) / 256), 256>>>(o1, colP, 16, SP);
    launch_gemm(1, 3, ssam_w1, (const float*)colP, h, C4V, HW, COUT, COUT, 0,
                0, 1, SPP16, SPH, nullptr, ssam_b1, 0, 1, nullptr, nullptr, 0, B_SZ);
    pack_kernel<<<(int)(((long)B_SZ * 64 * HW + 255) / 256), 256>>>(h, colP, 64, SPH);
    launch_gemm(0, 3, ssam_w2, (const float*)colP, x, COUT, HW, C4V, C4V, 0,
                0, 1, SPP64, SP, nullptr, ssam_b2, 0, 0, ssam_g, x2, SP, B_SZ);

    // 5. channel self-attention (input x, output x2)
    launch_gemm(0, 2, x, x, aC_, COUT, COUT, HW, HW, HW,
                SP, 1, SP, SPC, nullptr, nullptr, 0, 0, nullptr, nullptr, 0, B_SZ);
    softmax_kernel<<<B_SZ * COUT, 256>>>(aC_, COUT, 0.0625f);
    launch_gemm(0, 0, aC_, x, o1, COUT, HW, COUT, COUT, HW,
                SPC, 1, SP, SP, nullptr, nullptr, 0, 0, nullptr, nullptr, 0, B_SZ);
    pack_kernel<<<(int)(((long)B_SZ * 16 * HW + 255) / 256), 256>>>(o1, colP, 16, SP);
    launch_gemm(1, 3, csam_w1, (const float*)colP, h, C4V, HW, COUT, COUT, 0,
                0, 1, SPP16, SPH, nullptr, csam_b1, 0, 1, nullptr, nullptr, 0, B_SZ);
    pack_kernel<<<(int)(((long)B_SZ * 64 * HW + 255) / 256), 256>>>(h, colP, 64, SPH);
    launch_gemm(0, 3, csam_w2, (const float*)colP, x2, COUT, HW, C4V, C4V, 0,
                0, 1, SPP64, SP, nullptr, csam_b2, 0, 0, nullptr, x, SP, B_SZ);

    // 6. fuse: concat keyframe feat (pf[K-1]) with x2 -> packed directly
    {
        long total = (long)B_SZ * 32 * HW;
        concatpack_kernel<<<(int)((total + 255) / 256), 256>>>(
            pf + (long)(K_FR - 1) * B_SZ * SP, x2, colP);
    }
    launch_gemm(0, 3, fuse_w1, (const float*)colP, x, COUT, HW, 2 * COUT, 2 * COUT, 0,
                0, 1, SPP32, SP, bnA + 1 * COUT, bnB + 1 * COUT, 0, 1, nullptr, nullptr, 0, B_SZ);

    // 7. 3x3 conv + BN + relu -> x2  (packed im2col)
    im2colpack_kernel<<<(int)((PACKC + 255) / 256), 256>>>(x, colP);
    launch_gemm(0, 3, fuse_w2, (const float*)colP, x2, COUT, HW, COUT * 9, COUT * 9, 0,
                0, 1, SPP144, SP, bnA + 2 * COUT, bnB + 2 * COUT, 0, 1, nullptr, nullptr, 0, B_SZ);

    // 8. channel self-attention (input x2, output x)
    launch_gemm(0, 2, x2, x2, aC_, COUT, COUT, HW, HW, HW,
                SP, 1, SP, SPC, nullptr, nullptr, 0, 0, nullptr, nullptr, 0, B_SZ);
    softmax_kernel<<<B_SZ * COUT, 256>>>(aC_, COUT, 0.0625f);
    launch_gemm(0, 0, aC_, x2, o1, COUT, HW, COUT, COUT, HW,
                SPC, 1, SP, SP, nullptr, nullptr, 0, 0, nullptr, nullptr, 0, B_SZ);
    pack_kernel<<<(int)(((long)B_SZ * 16 * HW + 255) / 256), 256>>>(o1, colP, 16, SP);
    launch_gemm(1, 3, fcsam_w1, (const float*)colP, h, C4V, HW, COUT, COUT, 0,
                0, 1, SPP16, SPH, nullptr, fcsam_b1, 0, 1, nullptr, nullptr, 0, B_SZ);
    pack_kernel<<<(int)(((long)B_SZ * 64 * HW + 255) / 256), 256>>>(h, colP, 64, SPH);
    launch_gemm(0, 3, fcsam_w2, (const float*)colP, x, COUT, HW, C4V, C4V, 0,
                0, 1, SPP64, SP, nullptr, fcsam_b2, 0, 0, nullptr, x2, SP, B_SZ);

    // 9. final 3x3 conv + BN + relu -> d_out  (packed im2col)
    im2colpack_kernel<<<(int)((PACKC + 255) / 256), 256>>>(x, colP);
    launch_gemm(0, 3, fuse_w4, (const float*)colP, out, COUT, HW, COUT * 9, COUT * 9, 0,
                0, 1, SPP144, SP, bnA + 3 * COUT, bnB + 3 * COUT, 0, 1, nullptr, nullptr, 0, B_SZ);
}

// round 14
// speedup vs baseline: 2.1038x; 1.0794x over previous
#include <cuda_runtime.h>
#include <cuda_bf16.h>
#include <math.h>

#define K_FR 8
#define B_SZ 8
#define CIN  512
#define COUT 256
#define H_   28
#define W_   28
#define HW   784
#define C4V  1024
#define NKT  144          // max k-tiles (conv: 2304/16)
#define NPAD 896          // padded pixel rows per k-tile (7*128)

// packed-weight buffer offsets (uints)
#define OFF_PROJ   0L
#define OFF_CONV1  1048576L
#define OFF_CONV2  1638400L
#define OFF_CONV3  2228224L
#define OFF_MLP1A  2818048L
#define OFF_MLP1B  3080192L
#define OFF_MLP1C  3342336L
#define OFF_MLP2A  3604480L
#define OFF_MLP2B  3866624L
#define OFF_MLP2C  4128768L
#define OFF_FUSE1  4390912L
#define WP_TOTAL   4521984L

// ---------------- scratch (device globals; no allocation at runtime) --------
__device__ __align__(16) float g_pf  [K_FR * B_SZ * COUT * HW];
__device__ __align__(16) float g_x   [B_SZ * COUT * HW];
__device__ __align__(16) float g_x2  [B_SZ * COUT * HW];
__device__ __align__(16) float g_o1  [B_SZ * COUT * HW];
__device__ __align__(16) float g_h   [B_SZ * C4V * HW];
__device__ __align__(16) float g_aS  [B_SZ * HW * HW];
__device__ __align__(16) float g_aC  [B_SZ * COUT * COUT];
__device__ __align__(16) unsigned g_colP [(long)B_SZ * NKT * NPAD * 16];  // 66MB, zero-init
__device__ __align__(16) unsigned g_wP   [WP_TOTAL];                      // 18MB packed weights
__device__ float g_bnA [4 * COUT];
__device__ float g_bnB [4 * COUT];

// ---------------- 3xBF16 tensor-core GEMM -----------------------------------
// a*b ~= aH*bH + aH*bL + aL*bH with bf16 hi/lo split (residual ~2^-16), fp32 acc.
// mma.m16n8k16.bf16; smem row: 8 k-pairs as bf16x2 words, group 4p =
// {hi(p), hi(p+4), lo(p), lo(p+4)} -> fragment = one LDS.128.
// APK: A pre-packed [kt][row][16 uints] with row-stride 'lda' rows per kt
//      -> loadA/storeA pure vector copy, smem stride 16 (conflict-free).
// BPK: B pre-packed [kt][row<NPAD][16 uints] -> same.
// Unpacked A: [M,K] fp32. Unpacked B: [K,N] (TB=0) or [N,K] (TB=1) fp32.
// epilogue: v = acc*scale[m]+bias[m]; relu; v = v*gamma + resid[m,n]
// Requires Kd % 16 == 0.

__device__ __forceinline__ unsigned pack2(float f0, float f1) {   // f0->low, f1->high
    unsigned r;
    asm("cvt.rn.bf16x2.f32 %0, %1, %2;" : "=r"(r) : "f"(f1), "f"(f0));
    return r;
}
__device__ __forceinline__ void split2(float f0, float f1, unsigned& hi, unsigned& lo) {
    hi = pack2(f0, f1);
    float h0 = __uint_as_float(hi << 16);
    float h1 = __uint_as_float(hi & 0xffff0000u);
    lo = pack2(f0 - h0, f1 - h1);
}
__device__ __forceinline__ void mma_bf16(float4& d, const unsigned a[4], const unsigned b[2]) {
    asm volatile(
        "mma.sync.aligned.m16n8k16.row.col.f32.bf16.bf16.f32 "
        "{%0,%1,%2,%3}, {%4,%5,%6,%7}, {%8,%9}, {%0,%1,%2,%3};"
        : "+f"(d.x), "+f"(d.y), "+f"(d.z), "+f"(d.w)
        : "r"(a[0]), "r"(a[1]), "r"(a[2]), "r"(a[3]), "r"(b[0]), "r"(b[1]));
}

#define RSTR 20   // smem row stride in uints (fp32-staged tiles)
#define BN   128

__device__ __forceinline__ int posH(int p) { return 4 * (p & 3) + (p >> 2); }

template <int TBM, bool TB, int MAXB, bool APK, bool BPK>
__global__ void __launch_bounds__(256, MAXB) gemm_bf(
    const float* __restrict__ A, const float* __restrict__ Bm, float* __restrict__ C,
    int M, int N, int Kd, int lda, int ldb,
    long aS, int aDiv, long bS, long cS,
    const float* __restrict__ scaleC, const float* __restrict__ biasC, long biS,
    int relu, const float* __restrict__ gammaPtr,
    const float* __restrict__ resid, long rS)
{
    constexpr int RSA = APK ? 16 : RSTR;
    constexpr int RSB = BPK ? 16 : RSTR;
    extern __shared__ unsigned sm[];
    unsigned* As = sm;                       // [2][TBM][RSA]
    unsigned* Bs = sm + 2 * TBM * RSA;       // [2][BN ][RSB]

    const int z = blockIdx.z;
    A  += (long)(z / aDiv) * aS;
    Bm += (long)z * bS;
    C  += (long)z * cS;
    if (biasC) biasC += (long)(z / aDiv) * biS;
    if (resid) resid += (long)z * rS;

    const int tid  = threadIdx.x;
    const int lane = tid & 31, warp = tid >> 5;
    constexpr int MI = TBM / 32;            // 2 or 4
    constexpr int NJ = 4;
    constexpr int UA = TBM / 32;            // A pairs/thread (fp32) or uint4/thread (packed: TBM/64)
    constexpr int UAP = TBM / 64;           // packed A uint4 per thread
    constexpr int UB = 4;
    const int wm = (warp >> 2) * (TBM / 2);
    const int wn = (warp & 3) * 32;
    const int m0 = blockIdx.y * TBM, n0 = blockIdx.x * BN;

    float4 acc[MI][NJ];
    #pragma unroll
    for (int i = 0; i < MI; ++i)
        #pragma unroll
        for (int j = 0; j < NJ; ++j)
            acc[i][j] = make_float4(0.f, 0.f, 0.f, 0.f);

    float2 va[UA], vb[UB];
    uint4 vaP[UAP], vbP[2];

    auto loadA = [&](int k0) {
        if (APK) {
            const uint4* ap = reinterpret_cast<const uint4*>(A);
            long base = ((long)(k0 >> 4) * lda + m0) * 4;
            #pragma unroll
            for (int t = 0; t < UAP; ++t)
                vaP[t] = ap[base + tid + t * 256];
        } else {   // A [M,K]: 8 threads per row, float2 per k-pair
            #pragma unroll
            for (int t = 0; t < UA; ++t) {
                int i = tid + t * 256;
                int p = i & 7, m = i >> 3;
                int gm = m0 + m;
                va[t] = (gm < M) ? *(const float2*)&A[(long)gm * lda + k0 + 2 * p]
                                 : make_float2(0.f, 0.f);
            }
        }
    };
    auto loadB = [&](int k0) {
        if (BPK) {
            const uint4* bp = reinterpret_cast<const uint4*>(Bm);
            long base = ((long)(k0 >> 4) * NPAD + n0) * 4;
            vbP[0] = bp[base + tid];
            vbP[1] = bp[base + tid + 256];
        } else if (TB) {    // B [N,K]
            #pragma unroll
            for (int t = 0; t < UB; ++t) {
                int i = tid + t * 256;
                int p = i & 7, n = i >> 3;
                int gn = n0 + n;
                vb[t] = (gn < N) ? *(const float2*)&Bm[(long)gn * ldb + k0 + 2 * p]
                                 : make_float2(0.f, 0.f);
            }
        } else {     // B [K,N]
            int n = tid & 127, psel = tid >> 7;
            int gn = n0 + n;
            #pragma unroll
            for (int t = 0; t < UB; ++t) {
                int p = psel * UB + t;
                float f0 = 0.f, f1 = 0.f;
                if (gn < N) {
                    f0 = Bm[(long)(k0 + 2 * p) * ldb + gn];
                    f1 = Bm[(long)(k0 + 2 * p + 1) * ldb + gn];
                }
                vb[t] = make_float2(f0, f1);
            }
        }
    };
    auto storeA = [&](int buf) {
        if (APK) {
            #pragma unroll
            for (int t = 0; t < UAP; ++t)
                *(uint4*)&As[(long)(buf * TBM + (tid >> 2) + t * 64) * 16 + (tid & 3) * 4] = vaP[t];
        } else {
            #pragma unroll
            for (int t = 0; t < UA; ++t) {
                int i = tid + t * 256;
                int p = i & 7, m = i >> 3;
                unsigned hi, lo;
                split2(va[t].x, va[t].y, hi, lo);
                unsigned* base = &As[(long)(buf * TBM + m) * RSA];
                int ph = posH(p);
                base[ph]     = hi;
                base[ph + 2] = lo;
            }
        }
    };
    auto storeB = [&](int buf) {
        if (BPK) {
            *(uint4*)&Bs[(long)(buf * BN + (tid >> 2)) * RSB + (tid & 3) * 4] = vbP[0];
            *(uint4*)&Bs[(long)(buf * BN + (tid >> 2) + 64) * RSB + (tid & 3) * 4] = vbP[1];
        } else if (TB) {
            #pragma unroll
            for (int t = 0; t < UB; ++t) {
                int i = tid + t * 256;
                int p = i & 7, n = i >> 3;
                unsigned hi, lo;
                split2(vb[t].x, vb[t].y, hi, lo);
                unsigned* base = &Bs[(long)(buf * BN + n) * RSB];
                int ph = posH(p);
                base[ph]     = hi;
                base[ph + 2] = lo;
            }
        } else {
            int n = tid & 127, psel = tid >> 7;
            #pragma unroll
            for (int t = 0; t < UB; ++t) {
                int p = psel * UB + t;
                unsigned hi, lo;
                split2(vb[t].x, vb[t].y, hi, lo);
                unsigned* base = &Bs[(long)(buf * BN + n) * RSB];
                int ph = posH(p);
                base[ph]     = hi;
                base[ph + 2] = lo;
            }
        }
    };
    auto compute = [&](int buf) {
        uint4 a0[MI], a1[MI], bv[NJ];
        #pragma unroll
        for (int i = 0; i < MI; ++i) {
            int r = wm + i * 16 + (lane >> 2);
            a0[i] = *(const uint4*)&As[(long)(buf * TBM + r) * RSA + ((lane & 3) << 2)];
            a1[i] = *(const uint4*)&As[(long)(buf * TBM + r + 8) * RSA + ((lane & 3) << 2)];
        }
        #pragma unroll
        for (int j = 0; j < NJ; ++j) {
            int c = wn + j * 8 + (lane >> 2);
            bv[j] = *(const uint4*)&Bs[(long)(buf * BN + c) * RSB + ((lane & 3) << 2)];
        }
        unsigned aH[MI][4], aL[MI][4], bH[NJ][2], bL[NJ][2];
        #pragma unroll
        for (int i = 0; i < MI; ++i) {
            aH[i][0] = a0[i].x; aH[i][1] = a1[i].x; aH[i][2] = a0[i].y; aH[i][3] = a1[i].y;
            aL[i][0] = a0[i].z; aL[i][1] = a1[i].z; aL[i][2] = a0[i].w; aL[i][3] = a1[i].w;
        }
        #pragma unroll
        for (int j = 0; j < NJ; ++j) {
            bH[j][0] = bv[j].x; bH[j][1] = bv[j].y;
            bL[j][0] = bv[j].z; bL[j][1] = bv[j].w;
        }
        #pragma unroll
        for (int j = 0; j < NJ; ++j)
            #pragma unroll
            for (int i = 0; i < MI; ++i)
                mma_bf16(acc[i][j], aH[i], bH[j]);   // hi*hi
        #pragma unroll
        for (int j = 0; j < NJ; ++j)
            #pragma unroll
            for (int i = 0; i < MI; ++i)
                mma_bf16(acc[i][j], aH[i], bL[j]);   // hi*lo
        #pragma unroll
        for (int j = 0; j < NJ; ++j)
            #pragma unroll
            for (int i = 0; i < MI; ++i)
                mma_bf16(acc[i][j], aL[i], bH[j]);   // lo*hi
    };

    // -------- mainloop: next-tile loads issued before compute --------
    int buf = 0;
    loadA(0); loadB(0);
    storeA(0); storeB(0);
    __syncthreads();

    for (int k0 = 0; k0 < Kd; k0 += 16) {
        bool more = (k0 + 16) < Kd;
        if (more) { loadA(k0 + 16); loadB(k0 + 16); }
        compute(buf);
        if (more) {
            storeA(buf ^ 1); storeB(buf ^ 1);
            __syncthreads();
            buf ^= 1;
        }
    }

    const float gmv = gammaPtr ? *gammaPtr : 1.f;
    #pragma unroll
    for (int i = 0; i < MI; ++i) {
        int r0 = m0 + wm + i * 16 + (lane >> 2);
        int r1 = r0 + 8;
        float sc0 = 1.f, bi0 = 0.f, sc1 = 1.f, bi1 = 0.f;
        if (scaleC) { if (r0 < M) sc0 = scaleC[r0]; if (r1 < M) sc1 = scaleC[r1]; }
        if (biasC)  { if (r0 < M) bi0 = biasC[r0];  if (r1 < M) bi1 = biasC[r1]; }
        #pragma unroll
        for (int j = 0; j < NJ; ++j) {
            int c = n0 + wn + j * 8 + ((lane & 3) << 1);
            float4 v = acc[i][j];
            if (r0 < M) {
                float x0 = v.x * sc0 + bi0, x1 = v.y * sc0 + bi0;
                if (relu) { x0 = fmaxf(x0, 0.f); x1 = fmaxf(x1, 0.f); }
                if (resid) {
                    if (c < N)     x0 = x0 * gmv + resid[(long)r0 * N + c];
                    if (c + 1 < N) x1 = x1 * gmv + resid[(long)r0 * N + c + 1];
                }
                if (c < N)     C[(long)r0 * N + c]     = x0;
                if (c + 1 < N) C[(long)r0 * N + c + 1] = x1;
            }
            if (r1 < M) {
                float y0 = v.z * sc1 + bi1, y1 = v.w * sc1 + bi1;
                if (relu) { y0 = fmaxf(y0, 0.f); y1 = fmaxf(y1, 0.f); }
                if (resid) {
                    if (c < N)     y0 = y0 * gmv + resid[(long)r1 * N + c];
                    if (c + 1 < N) y1 = y1 * gmv + resid[(long)r1 * N + c + 1];
                }
                if (c < N)     C[(long)r1 * N + c]     = y0;
                if (c + 1 < N) C[(long)r1 * N + c + 1] = y1;
            }
        }
    }
}

// ---------------- pointwise kernels -----------------------------------------
__global__ void tshuffle_kernel(const float* __restrict__ pf,
                                const float* __restrict__ gw,
                                const float* __restrict__ gb,
                                float* __restrict__ out)
{
    int idx = blockIdx.x * blockDim.x + threadIdx.x;
    if (idx >= B_SZ * COUT * HW) return;
    int c = (idx / HW) % COUT;
    float s = gb[c];
    #pragma unroll
    for (int k = 0; k < K_FR; ++k)
        s = fmaf(pf[(long)k * (B_SZ * COUT * HW) + idx], gw[c * K_FR + k], s);
    out[idx] = s;
}

__global__ void bnprep4_kernel(const float* __restrict__ p0,
                               const float* __restrict__ p1,
                               const float* __restrict__ p2,
                               const float* __restrict__ p3,
                               float* __restrict__ a, float* __restrict__ b)
{
    int c = threadIdx.x;
    int slot = blockIdx.x;
    const float* p = (slot == 0) ? p0 : (slot == 1) ? p1 : (slot == 2) ? p2 : p3;
    float g = p[c], be = p[COUT + c], m = p[2 * COUT + c], v = p[3 * COUT + c];
    float s = g * rsqrtf(v + 1e-5f);
    a[slot * COUT + c] = s;
    b[slot * COUT + c] = be - m * s;
}

// weight pack: src [M][K] fp32 -> dst [K/16][M][16 uints]
__global__ void packW_kernel(const float* __restrict__ src, unsigned* __restrict__ dst,
                             int M, int K)
{
    long idx = (long)blockIdx.x * blockDim.x + threadIdx.x;
    long total = (long)M * (K >> 4);
    if (idx >= total) return;
    int kt = (int)(idx / M);
    int m  = (int)(idx - (long)kt * M);
    const float* s = src + (long)m * K + kt * 16;
    unsigned rr[16];
    #pragma unroll
    for (int p = 0; p < 8; ++p) {
        float2 v = *(const float2*)&s[2 * p];
        unsigned hi, lo;
        split2(v.x, v.y, hi, lo);
        int ph = posH(p);
        rr[ph]     = hi;
        rr[ph + 2] = lo;
    }
    unsigned* d = dst + idx * 16;
    *(uint4*)(d + 0)  = *(const uint4*)(rr + 0);
    *(uint4*)(d + 4)  = *(const uint4*)(rr + 4);
    *(uint4*)(d + 8)  = *(const uint4*)(rr + 8);
    *(uint4*)(d + 12) = *(const uint4*)(rr + 12);
}

// im2col + bf16 split + pack into final smem-row format.
__global__ void im2colpack_kernel(const float* __restrict__ x, unsigned* __restrict__ colP)
{
    long idx = (long)blockIdx.x * blockDim.x + threadIdx.x;
    const long total = (long)B_SZ * NKT * HW;
    if (idx >= total) return;
    int n  = (int)(idx % HW);
    long r = idx / HW;
    int kt = (int)(r % NKT);
    int z  = (int)(r / NKT);
    const float* xb = x + (long)z * COUT * HW;
    int h = n / W_, w = n % W_;

    unsigned rr[16];
    #pragma unroll
    for (int p = 0; p < 8; ++p) {
        int k0 = kt * 16 + 2 * p;
        float f0, f1;
        {
            int ci = k0 / 9, tq = k0 - ci * 9;
            int hh = h + tq / 3 - 1, ww = w + tq % 3 - 1;
            f0 = ((unsigned)hh < H_ && (unsigned)ww < W_) ? xb[(long)ci * HW + hh * W_ + ww] : 0.f;
        }
        {
            int k1 = k0 + 1;
            int ci = k1 / 9, tq = k1 - ci * 9;
            int hh = h + tq / 3 - 1, ww = w + tq % 3 - 1;
            f1 = ((unsigned)hh < H_ && (unsigned)ww < W_) ? xb[(long)ci * HW + hh * W_ + ww] : 0.f;
        }
        unsigned hi, lo;
        split2(f0, f1, hi, lo);
        int ph = posH(p);
        rr[ph]     = hi;
        rr[ph + 2] = lo;
    }
    unsigned* dst = colP + ((long)(z * NKT + kt) * NPAD + n) * 16;
    *(uint4*)(dst + 0)  = *(const uint4*)(rr + 0);
    *(uint4*)(dst + 4)  = *(const uint4*)(rr + 4);
    *(uint4*)(dst + 8)  = *(const uint4*)(rr + 8);
    *(uint4*)(dst + 12) = *(const uint4*)(rr + 12);
}

// generic pack: src [z][K][HW] fp32 -> packed [z][kt][n][16] (ktCount = K/16)
__global__ void pack_kernel(const float* __restrict__ src, unsigned* __restrict__ colP,
                            int ktCount, long srcStride)
{
    long idx = (long)blockIdx.x * blockDim.x + threadIdx.x;
    const long total = (long)B_SZ * ktCount * HW;
    if (idx >= total) return;
    int n  = (int)(idx % HW);
    long r = idx / HW;
    int kt = (int)(r % ktCount);
    int z  = (int)(r / ktCount);
    const float* s = src + (long)z * srcStride + (long)(kt * 16) * HW + n;

    unsigned rr[16];
    #pragma unroll
    for (int p = 0; p < 8; ++p) {
        float f0 = s[(long)(2 * p) * HW];
        float f1 = s[(long)(2 * p + 1) * HW];
        unsigned hi, lo;
        split2(f0, f1, hi, lo);
        int ph = posH(p);
        rr[ph]     = hi;
        rr[ph + 2] = lo;
    }
    unsigned* dst = colP + ((long)(z * ktCount + kt) * NPAD + n) * 16;
    *(uint4*)(dst + 0)  = *(const uint4*)(rr + 0);
    *(uint4*)(dst + 4)  = *(const uint4*)(rr + 4);
    *(uint4*)(dst + 8)  = *(const uint4*)(rr + 8);
    *(uint4*)(dst + 12) = *(const uint4*)(rr + 12);
}

// concat keyframe feat with x2 AND pack (K=512 -> 32 k-tiles)
__global__ void concatpack_kernel(const float* __restrict__ kf,
                                  const float* __restrict__ x,
                                  unsigned* __restrict__ colP)
{
    const int KT = 32;
    long idx = (long)blockIdx.x * blockDim.x + threadIdx.x;
    const long total = (long)B_SZ * KT * HW;
    if (idx >= total) return;
    int n  = (int)(idx % HW);
    long r = idx / HW;
    int kt = (int)(r % KT);
    int z  = (int)(r / KT);
    const float* s = (kt < 16 ? kf + (long)z * COUT * HW + (long)(kt * 16) * HW
                              : x  + (long)z * COUT * HW + (long)((kt - 16) * 16) * HW) + n;

    unsigned rr[16];
    #pragma unroll
    for (int p = 0; p < 8; ++p) {
        float f0 = s[(long)(2 * p) * HW];
        float f1 = s[(long)(2 * p + 1) * HW];
        unsigned hi, lo;
        split2(f0, f1, hi, lo);
        int ph = posH(p);
        rr[ph]     = hi;
        rr[ph + 2] = lo;
    }
    unsigned* dst = colP + ((long)(z * KT + kt) * NPAD + n) * 16;
    *(uint4*)(dst + 0)  = *(const uint4*)(rr + 0);
    *(uint4*)(dst + 4)  = *(const uint4*)(rr + 4);
    *(uint4*)(dst + 8)  = *(const uint4*)(rr + 8);
    *(uint4*)(dst + 12) = *(const uint4*)(rr + 12);
}

__global__ void softmax_kernel(float* __restrict__ S, int len, float scale)
{
    float* p = S + (long)blockIdx.x * len;
    __shared__ float red[256];
    int tid = threadIdx.x;
    float mx = -1e30f;
    for (int j = tid; j < len; j += 256) mx = fmaxf(mx, p[j] * scale);
    red[tid] = mx; __syncthreads();
    for (int s = 128; s > 0; s >>= 1) {
        if (tid < s) red[tid] = fmaxf(red[tid], red[tid + s]);
        __syncthreads();
    }
    mx = red[0]; __syncthreads();
    float sum = 0.f;
    for (int j = tid; j < len; j += 256) {
        float e = expf(p[j] * scale - mx);
        p[j] = e; sum += e;
    }
    red[tid] = sum; __syncthreads();
    for (int s = 128; s > 0; s >>= 1) {
        if (tid < s) red[tid] += red[tid + s];
        __syncthreads();
    }
    float inv = 1.f / red[0];
    for (int j = tid; j < len; j += 256) p[j] *= inv;
}

// ---------------- host-side helpers -----------------------------------------
static const int SMB_SMALL     = (2 * 64 * RSTR + 2 * 128 * RSTR) * 4;  // 30720 (fp32 A,B)
static const int SMB_SMALL_PP  = (2 * 64 * 16 + 2 * 128 * 16) * 4;      // 24576 (packed A,B)
static const int SMB_BIG_PP    = (2 * 128 * 16 + 2 * 128 * 16) * 4;     // 32768
static const int SMB_BIG_PA    = (2 * 128 * 16 + 2 * 128 * RSTR) * 4;   // 36864 (proj)

// mode: 0 = small NN fp32;  2 = small NT fp32;  3 = small A+B packed;
//       4 = big  A+B packed; 5 = big A packed, B fp32 [K,N] (proj)
static void launch_gemm(int mode,
                        const float* A, const float* B, float* C,
                        int M, int N, int Kd, int lda, int ldb,
                        long aS, int aDiv, long bS, long cS,
                        const float* sc, const float* bi, long biS,
                        int relu, const float* gp,
                        const float* res, long rS, int Z)
{
    dim3 block(256);
    if (mode == 4 || mode == 5) {
        dim3 grid((N + 127) / 128, (M + 127) / 128, Z);
        if (mode == 4) {
            cudaFuncSetAttribute(gemm_bf<128,false,1,true,true>,
                                 cudaFuncAttributeMaxDynamicSharedMemorySize, SMB_BIG_PP);
            gemm_bf<128,false,1,true,true><<<grid, block, SMB_BIG_PP>>>(A, B, C, M, N, Kd, lda, ldb,
                aS, aDiv, bS, cS, sc, bi, biS, relu, gp, res, rS);
        } else {
            cudaFuncSetAttribute(gemm_bf<128,false,1,true,false>,
                                 cudaFuncAttributeMaxDynamicSharedMemorySize, SMB_BIG_PA);
            gemm_bf<128,false,1,true,false><<<grid, block, SMB_BIG_PA>>>(A, B, C, M, N, Kd, lda, ldb,
                aS, aDiv, bS, cS, sc, bi, biS, relu, gp, res, rS);
        }
        return;
    }
    dim3 grid((N + 127) / 128, (M + 63) / 64, Z);
    if (mode == 3) {
        cudaFuncSetAttribute(gemm_bf<64,false,2,true,true>,
                             cudaFuncAttributeMaxDynamicSharedMemorySize, SMB_SMALL_PP);
        gemm_bf<64,false,2,true,true><<<grid, block, SMB_SMALL_PP>>>(A, B, C, M, N, Kd, lda, ldb,
            aS, aDiv, bS, cS, sc, bi, biS, relu, gp, res, rS);
    } else if (mode == 0) {
        cudaFuncSetAttribute(gemm_bf<64,false,2,false,false>,
                             cudaFuncAttributeMaxDynamicSharedMemorySize, SMB_SMALL);
        gemm_bf<64,false,2,false,false><<<grid, block, SMB_SMALL>>>(A, B, C, M, N, Kd, lda, ldb,
            aS, aDiv, bS, cS, sc, bi, biS, relu, gp, res, rS);
    } else {  // mode 2
        cudaFuncSetAttribute(gemm_bf<64,true,2,false,false>,
                             cudaFuncAttributeMaxDynamicSharedMemorySize, SMB_SMALL);
        gemm_bf<64,true,2,false,false><<<grid, block, SMB_SMALL>>>(A, B, C, M, N, Kd, lda, ldb,
            aS, aDiv, bS, cS, sc, bi, biS, relu, gp, res, rS);
    }
}

static void packW(const float* src, unsigned* dst, int M, int K)
{
    long total = (long)M * (K >> 4);
    packW_kernel<<<(int)((total + 255) / 256), 256>>>(src, dst, M, K);
}

extern "C" void kernel_launch(void* const* d_in, const int* in_sizes, int n_in,
                              void* d_out, int out_size)
{
    const float* feats    = (const float*)d_in[0];
    const float* proj_w   = (const float*)d_in[1];
    const float* proj_b   = (const float*)d_in[2];
    const float* ts_gw    = (const float*)d_in[3];
    const float* ts_gb    = (const float*)d_in[4];
    const float* ts_w3    = (const float*)d_in[5];
    const float* ts_bn    = (const float*)d_in[6];
    const float* ssam_w1  = (const float*)d_in[7];
    const float* ssam_b1  = (const float*)d_in[8];
    const float* ssam_w2  = (const float*)d_in[9];
    const float* ssam_b2  = (const float*)d_in[10];
    const float* ssam_g   = (const float*)d_in[11];
    const float* csam_w1  = (const float*)d_in[12];
    const float* csam_b1  = (const float*)d_in[13];
    const float* csam_w2  = (const float*)d_in[14];
    const float* csam_b2  = (const float*)d_in[15];
    const float* fuse_w1  = (const float*)d_in[16];
    const float* fuse_bn1 = (const float*)d_in[17];
    const float* fuse_w2  = (const float*)d_in[18];
    const float* fuse_bn2 = (const float*)d_in[19];
    const float* fcsam_w1 = (const float*)d_in[20];
    const float* fcsam_b1 = (const float*)d_in[21];
    const float* fcsam_w2 = (const float*)d_in[22];
    const float* fcsam_b2 = (const float*)d_in[23];
    const float* fuse_w4  = (const float*)d_in[24];
    const float* fuse_bn4 = (const float*)d_in[25];
    float* out = (float*)d_out;

    float *pf, *x, *x2, *o1, *h, *aS_, *aC_, *bnA, *bnB;
    unsigned *colP, *wP;
    cudaGetSymbolAddress((void**)&pf,   g_pf);
    cudaGetSymbolAddress((void**)&x,    g_x);
    cudaGetSymbolAddress((void**)&x2,   g_x2);
    cudaGetSymbolAddress((void**)&o1,   g_o1);
    cudaGetSymbolAddress((void**)&h,    g_h);
    cudaGetSymbolAddress((void**)&aS_,  g_aS);
    cudaGetSymbolAddress((void**)&aC_,  g_aC);
    cudaGetSymbolAddress((void**)&colP, g_colP);
    cudaGetSymbolAddress((void**)&wP,   g_wP);
    cudaGetSymbolAddress((void**)&bnA,  g_bnA);
    cudaGetSymbolAddress((void**)&bnB,  g_bnB);

    const long SP  = (long)COUT * HW;
    const long SPH = (long)C4V * HW;
    const long SPS = (long)HW * HW;
    const long SPC = (long)COUT * COUT;
    const long SPP16  = (long)16 * NPAD * 16;    // packed plane, K=256
    const long SPP32  = (long)32 * NPAD * 16;
    const long SPP64  = (long)64 * NPAD * 16;
    const long SPP144 = (long)NKT * NPAD * 16;
    const long PACKC  = (long)B_SZ * NKT * HW;

    // 0. constants: BN prep + weight packs (all up front)
    bnprep4_kernel<<<4, 256>>>(ts_bn, fuse_bn1, fuse_bn2, fuse_bn4, bnA, bnB);
    packW(proj_w,   wP + OFF_PROJ,  K_FR * COUT, CIN);   // combined [2048][512]
    packW(ts_w3,    wP + OFF_CONV1, COUT, COUT * 9);
    packW(fuse_w2,  wP + OFF_CONV2, COUT, COUT * 9);
    packW(fuse_w4,  wP + OFF_CONV3, COUT, COUT * 9);
    packW(ssam_w1,  wP + OFF_MLP1A, C4V, COUT);
    packW(csam_w1,  wP + OFF_MLP1B, C4V, COUT);
    packW(fcsam_w1, wP + OFF_MLP1C, C4V, COUT);
    packW(ssam_w2,  wP + OFF_MLP2A, COUT, C4V);
    packW(csam_w2,  wP + OFF_MLP2B, COUT, C4V);
    packW(fcsam_w2, wP + OFF_MLP2C, COUT, C4V);
    packW(fuse_w1,  wP + OFF_FUSE1, COUT, 2 * COUT);

    // 1. per-frame 1x1 projection (A packed: rows/kt = 2048, frame offset 4096 uints)
    launch_gemm(5, (const float*)(wP + OFF_PROJ), feats, pf, COUT, HW, CIN,
                K_FR * COUT, HW, 4096, B_SZ, (long)CIN * HW, SP,
                nullptr, proj_b, COUT, 0, nullptr, nullptr, 0, K_FR * B_SZ);

    // 2. temporal shuffle + grouped 1x1 -> x
    {
        int total = B_SZ * COUT * HW;
        tshuffle_kernel<<<(total + 255) / 256, 256>>>(pf, ts_gw, ts_gb, x);
    }

    // 3. 3x3 conv + BN -> x2
    im2colpack_kernel<<<(int)((PACKC + 255) / 256), 256>>>(x, colP);
    launch_gemm(3, (const float*)(wP + OFF_CONV1), (const float*)colP, x2,
                COUT, HW, COUT * 9, COUT, 0,
                0, 1, SPP144, SP, bnA + 0 * COUT, bnB + 0 * COUT, 0, 0, nullptr, nullptr, 0, B_SZ);

    // 4. spatial self-attention (input x2, output x)
    pack_kernel<<<(int)(((long)B_SZ * 16 * HW + 255) / 256), 256>>>(x2, colP, 16, SP);
    launch_gemm(4, (const float*)colP, (const float*)colP, aS_, HW, HW, COUT,
                NPAD, 0, SPP16, 1, SPP16, SPS,
                nullptr, nullptr, 0, 0, nullptr, nullptr, 0, B_SZ);
    softmax_kernel<<<B_SZ * HW, 256>>>(aS_, HW, 0.0625f);
    launch_gemm(2, x2, aS_, o1, COUT, HW, HW, HW, HW,
                SP, 1, SPS, SP, nullptr, nullptr, 0, 0, nullptr, nullptr, 0, B_SZ);
    pack_kernel<<<(int)(((long)B_SZ * 16 * HW + 255) / 256), 256>>>(o1, colP, 16, SP);
    launch_gemm(4, (const float*)(wP + OFF_MLP1A), (const float*)colP, h,
                C4V, HW, COUT, C4V, 0,
                0, 1, SPP16, SPH, nullptr, ssam_b1, 0, 1, nullptr, nullptr, 0, B_SZ);
    pack_kernel<<<(int)(((long)B_SZ * 64 * HW + 255) / 256), 256>>>(h, colP, 64, SPH);
    launch_gemm(3, (const float*)(wP + OFF_MLP2A), (const float*)colP, x,
                COUT, HW, C4V, COUT, 0,
                0, 1, SPP64, SP, nullptr, ssam_b2, 0, 0, ssam_g, x2, SP, B_SZ);

    // 5. channel self-attention (input x, output x2)
    launch_gemm(2, x, x, aC_, COUT, COUT, HW, HW, HW,
                SP, 1, SP, SPC, nullptr, nullptr, 0, 0, nullptr, nullptr, 0, B_SZ);
    softmax_kernel<<<B_SZ * COUT, 256>>>(aC_, COUT, 0.0625f);
    launch_gemm(0, aC_, x, o1, COUT, HW, COUT, COUT, HW,
                SPC, 1, SP, SP, nullptr, nullptr, 0, 0, nullptr, nullptr, 0, B_SZ);
    pack_kernel<<<(int)(((long)B_SZ * 16 * HW + 255) / 256), 256>>>(o1, colP, 16, SP);
    launch_gemm(4, (const float*)(wP + OFF_MLP1B), (const float*)colP, h,
                C4V, HW, COUT, C4V, 0,
                0, 1, SPP16, SPH, nullptr, csam_b1, 0, 1, nullptr, nullptr, 0, B_SZ);
    pack_kernel<<<(int)(((long)B_SZ * 64 * HW + 255) / 256), 256>>>(h, colP, 64, SPH);
    launch_gemm(3, (const float*)(wP + OFF_MLP2B), (const float*)colP, x2,
                COUT, HW, C4V, COUT, 0,
                0, 1, SPP64, SP, nullptr, csam_b2, 0, 0, nullptr, x, SP, B_SZ);

    // 6. fuse: concat keyframe feat (pf[K-1]) with x2 -> packed directly
    {
        long total = (long)B_SZ * 32 * HW;
        concatpack_kernel<<<(int)((total + 255) / 256), 256>>>(
            pf + (long)(K_FR - 1) * B_SZ * SP, x2, colP);
    }
    launch_gemm(3, (const float*)(wP + OFF_FUSE1), (const float*)colP, x,
                COUT, HW, 2 * COUT, COUT, 0,
                0, 1, SPP32, SP, bnA + 1 * COUT, bnB + 1 * COUT, 0, 1, nullptr, nullptr, 0, B_SZ);

    // 7. 3x3 conv + BN + relu -> x2
    im2colpack_kernel<<<(int)((PACKC + 255) / 256), 256>>>(x, colP);
    launch_gemm(3, (const float*)(wP + OFF_CONV2), (const float*)colP, x2,
                COUT, HW, COUT * 9, COUT, 0,
                0, 1, SPP144, SP, bnA + 2 * COUT, bnB + 2 * COUT, 0, 1, nullptr, nullptr, 0, B_SZ);

    // 8. channel self-attention (input x2, output x)
    launch_gemm(2, x2, x2, aC_, COUT, COUT, HW, HW, HW,
                SP, 1, SP, SPC, nullptr, nullptr, 0, 0, nullptr, nullptr, 0, B_SZ);
    softmax_kernel<<<B_SZ * COUT, 256>>>(aC_, COUT, 0.0625f);
    launch_gemm(0, aC_, x2, o1, COUT, HW, COUT, COUT, HW,
                SPC, 1, SP, SP, nullptr, nullptr, 0, 0, nullptr, nullptr, 0, B_SZ);
    pack_kernel<<<(int)(((long)B_SZ * 16 * HW + 255) / 256), 256>>>(o1, colP, 16, SP);
    launch_gemm(4, (const float*)(wP + OFF_MLP1C), (const float*)colP, h,
                C4V, HW, COUT, C4V, 0,
                0, 1, SPP16, SPH, nullptr, fcsam_b1, 0, 1, nullptr, nullptr, 0, B_SZ);
    pack_kernel<<<(int)(((long)B_SZ * 64 * HW + 255) / 256), 256>>>(h, colP, 64, SPH);
    launch_gemm(3, (const float*)(wP + OFF_MLP2C), (const float*)colP, x,
                COUT, HW, C4V, COUT, 0,
                0, 1, SPP64, SP, nullptr, fcsam_b2, 0, 0, nullptr, x2, SP, B_SZ);

    // 9. final 3x3 conv + BN + relu -> d_out
    im2colpack_kernel<<<(int)((PACKC + 255) / 256), 256>>>(x, colP);
    launch_gemm(3, (const float*)(wP + OFF_CONV3), (const float*)colP, out,
                COUT, HW, COUT * 9, COUT, 0,
                0, 1, SPP144, SP, bnA + 3 * COUT, bnB + 3 * COUT, 0, 1, nullptr, nullptr, 0, B_SZ);
}

// round 15
// speedup vs baseline: 2.1732x; 1.0330x over previous
#include <cuda_runtime.h>
#include <cuda_bf16.h>
#include <math.h>

#define K_FR 8
#define B_SZ 8
#define CIN  512
#define COUT 256
#define H_   28
#define W_   28
#define HW   784
#define C4V  1024
#define NKT  144          // max k-tiles (conv: 2304/16)
#define NPAD 896          // padded pixel rows per k-tile (7*128)

// packed-weight buffer offsets (uints)
#define OFF_PROJ   0L
#define OFF_CONV1  1048576L
#define OFF_CONV2  1638400L
#define OFF_CONV3  2228224L
#define OFF_MLP1A  2818048L
#define OFF_MLP1B  3080192L
#define OFF_MLP1C  3342336L
#define OFF_MLP2A  3604480L
#define OFF_MLP2B  3866624L
#define OFF_MLP2C  4128768L
#define OFF_FUSE1  4390912L
#define WP_TOTAL   4521984L

// activation-pack regions (uints)
#define OFFa 0L
#define OFFb 2097152L
#define OFFc 4194304L

// ---------------- scratch (device globals; no allocation at runtime) --------
__device__ __align__(16) float g_pf  [K_FR * B_SZ * COUT * HW];
__device__ __align__(16) float g_x   [B_SZ * COUT * HW];
__device__ __align__(16) float g_x2  [B_SZ * COUT * HW];
__device__ __align__(16) float g_o1  [B_SZ * COUT * HW];
__device__ __align__(16) float g_h   [B_SZ * C4V * HW];
__device__ __align__(16) float g_aS  [B_SZ * HW * HW];
__device__ __align__(16) float g_aC  [B_SZ * COUT * COUT];
__device__ __align__(16) unsigned g_colP [(long)B_SZ * NKT * NPAD * 16];  // 66MB
__device__ __align__(16) unsigned g_wP   [WP_TOTAL];                      // 18MB packed weights
__device__ float g_bnA [4 * COUT];
__device__ float g_bnB [4 * COUT];

// ---------------- 3xBF16 tensor-core GEMM -----------------------------------
// a*b ~= aH*bH + aH*bL + aL*bH, bf16 hi/lo split, fp32 acc. mma.m16n8k16.
// A ALWAYS pre-packed: [kt][row(lda rows per kt)][16 uints].
// B: BPK -> pre-packed [kt][row(ldb rows per kt)][16]; else fp32 [K,N] (proj).
// smem strides: A 16 uints, B 16 (packed) / 20 (fp32-staged).
// epilogue: v = acc*scale[m]+bias[m]; relu; v = v*gamma + resid[m,n]

__device__ __forceinline__ unsigned pack2(float f0, float f1) {   // f0->low, f1->high
    unsigned r;
    asm("cvt.rn.bf16x2.f32 %0, %1, %2;" : "=r"(r) : "f"(f1), "f"(f0));
    return r;
}
__device__ __forceinline__ void split2(float f0, float f1, unsigned& hi, unsigned& lo) {
    hi = pack2(f0, f1);
    float h0 = __uint_as_float(hi << 16);
    float h1 = __uint_as_float(hi & 0xffff0000u);
    lo = pack2(f0 - h0, f1 - h1);
}
__device__ __forceinline__ void mma_bf16(float4& d, const unsigned a[4], const unsigned b[2]) {
    asm volatile(
        "mma.sync.aligned.m16n8k16.row.col.f32.bf16.bf16.f32 "
        "{%0,%1,%2,%3}, {%4,%5,%6,%7}, {%8,%9}, {%0,%1,%2,%3};"
        : "+f"(d.x), "+f"(d.y), "+f"(d.z), "+f"(d.w)
        : "r"(a[0]), "r"(a[1]), "r"(a[2]), "r"(a[3]), "r"(b[0]), "r"(b[1]));
}

#define RSTR 20
#define BN   128

__device__ __forceinline__ int posH(int p) { return 4 * (p & 3) + (p >> 2); }

template <int TBM, int MAXB, bool BPK>
__global__ void __launch_bounds__(256, MAXB) gemm_bf(
    const unsigned* __restrict__ A, const float* __restrict__ Bm, float* __restrict__ C,
    int M, int N, int Kd, int lda, int ldb,
    long aS, int aDiv, long bS, long cS,
    const float* __restrict__ scaleC, const float* __restrict__ biasC, long biS,
    int relu, const float* __restrict__ gammaPtr,
    const float* __restrict__ resid, long rS)
{
    constexpr int RSB = BPK ? 16 : RSTR;
    extern __shared__ unsigned sm[];
    unsigned* As = sm;                       // [2][TBM][16]
    unsigned* Bs = sm + 2 * TBM * 16;        // [2][BN ][RSB]

    const int z = blockIdx.z;
    A  += (long)(z / aDiv) * aS;
    Bm += (long)z * bS;
    C  += (long)z * cS;
    if (biasC) biasC += (long)(z / aDiv) * biS;
    if (resid) resid += (long)z * rS;

    const int tid  = threadIdx.x;
    const int lane = tid & 31, warp = tid >> 5;
    constexpr int MI = TBM / 32;
    constexpr int NJ = 4;
    constexpr int UAP = TBM / 64;
    constexpr int UB = 4;
    const int wm = (warp >> 2) * (TBM / 2);
    const int wn = (warp & 3) * 32;
    const int m0 = blockIdx.y * TBM, n0 = blockIdx.x * BN;

    float4 acc[MI][NJ];
    #pragma unroll
    for (int i = 0; i < MI; ++i)
        #pragma unroll
        for (int j = 0; j < NJ; ++j)
            acc[i][j] = make_float4(0.f, 0.f, 0.f, 0.f);

    uint4 vaP[UAP], vbP[2];
    float2 vb[UB];

    auto loadA = [&](int k0) {
        const uint4* ap = reinterpret_cast<const uint4*>(A);
        long base = ((long)(k0 >> 4) * lda + m0) * 4;
        #pragma unroll
        for (int t = 0; t < UAP; ++t)
            vaP[t] = ap[base + tid + t * 256];
    };
    auto loadB = [&](int k0) {
        if (BPK) {
            const uint4* bp = reinterpret_cast<const uint4*>(Bm);
            long base = ((long)(k0 >> 4) * ldb + n0) * 4;
            vbP[0] = bp[base + tid];
            vbP[1] = bp[base + tid + 256];
        } else {     // B [K,N] fp32
            int n = tid & 127, psel = tid >> 7;
            int gn = n0 + n;
            #pragma unroll
            for (int t = 0; t < UB; ++t) {
                int p = psel * UB + t;
                float f0 = 0.f, f1 = 0.f;
                if (gn < N) {
                    f0 = Bm[(long)(k0 + 2 * p) * ldb + gn];
                    f1 = Bm[(long)(k0 + 2 * p + 1) * ldb + gn];
                }
                vb[t] = make_float2(f0, f1);
            }
        }
    };
    auto storeA = [&](int buf) {
        #pragma unroll
        for (int t = 0; t < UAP; ++t)
            *(uint4*)&As[(long)(buf * TBM + (tid >> 2) + t * 64) * 16 + (tid & 3) * 4] = vaP[t];
    };
    auto storeB = [&](int buf) {
        if (BPK) {
            *(uint4*)&Bs[(long)(buf * BN + (tid >> 2)) * RSB + (tid & 3) * 4] = vbP[0];
            *(uint4*)&Bs[(long)(buf * BN + (tid >> 2) + 64) * RSB + (tid & 3) * 4] = vbP[1];
        } else {
            int n = tid & 127, psel = tid >> 7;
            #pragma unroll
            for (int t = 0; t < UB; ++t) {
                int p = psel * UB + t;
                unsigned hi, lo;
                split2(vb[t].x, vb[t].y, hi, lo);
                unsigned* base = &Bs[(long)(buf * BN + n) * RSB];
                int ph = posH(p);
                base[ph]     = hi;
                base[ph + 2] = lo;
            }
        }
    };
    auto compute = [&](int buf) {
        uint4 a0[MI], a1[MI], bv[NJ];
        #pragma unroll
        for (int i = 0; i < MI; ++i) {
            int r = wm + i * 16 + (lane >> 2);
            a0[i] = *(const uint4*)&As[(long)(buf * TBM + r) * 16 + ((lane & 3) << 2)];
            a1[i] = *(const uint4*)&As[(long)(buf * TBM + r + 8) * 16 + ((lane & 3) << 2)];
        }
        #pragma unroll
        for (int j = 0; j < NJ; ++j) {
            int c = wn + j * 8 + (lane >> 2);
            bv[j] = *(const uint4*)&Bs[(long)(buf * BN + c) * RSB + ((lane & 3) << 2)];
        }
        unsigned aH[MI][4], aL[MI][4], bH[NJ][2], bL[NJ][2];
        #pragma unroll
        for (int i = 0; i < MI; ++i) {
            aH[i][0] = a0[i].x; aH[i][1] = a1[i].x; aH[i][2] = a0[i].y; aH[i][3] = a1[i].y;
            aL[i][0] = a0[i].z; aL[i][1] = a1[i].z; aL[i][2] = a0[i].w; aL[i][3] = a1[i].w;
        }
        #pragma unroll
        for (int j = 0; j < NJ; ++j) {
            bH[j][0] = bv[j].x; bH[j][1] = bv[j].y;
            bL[j][0] = bv[j].z; bL[j][1] = bv[j].w;
        }
        #pragma unroll
        for (int j = 0; j < NJ; ++j)
            #pragma unroll
            for (int i = 0; i < MI; ++i)
                mma_bf16(acc[i][j], aH[i], bH[j]);
        #pragma unroll
        for (int j = 0; j < NJ; ++j)
            #pragma unroll
            for (int i = 0; i < MI; ++i)
                mma_bf16(acc[i][j], aH[i], bL[j]);
        #pragma unroll
        for (int j = 0; j < NJ; ++j)
            #pragma unroll
            for (int i = 0; i < MI; ++i)
                mma_bf16(acc[i][j], aL[i], bH[j]);
    };

    int buf = 0;
    loadA(0); loadB(0);
    storeA(0); storeB(0);
    __syncthreads();

    for (int k0 = 0; k0 < Kd; k0 += 16) {
        bool more = (k0 + 16) < Kd;
        if (more) { loadA(k0 + 16); loadB(k0 + 16); }
        compute(buf);
        if (more) {
            storeA(buf ^ 1); storeB(buf ^ 1);
            __syncthreads();
            buf ^= 1;
        }
    }

    const float gmv = gammaPtr ? *gammaPtr : 1.f;
    #pragma unroll
    for (int i = 0; i < MI; ++i) {
        int r0 = m0 + wm + i * 16 + (lane >> 2);
        int r1 = r0 + 8;
        float sc0 = 1.f, bi0 = 0.f, sc1 = 1.f, bi1 = 0.f;
        if (scaleC) { if (r0 < M) sc0 = scaleC[r0]; if (r1 < M) sc1 = scaleC[r1]; }
        if (biasC)  { if (r0 < M) bi0 = biasC[r0];  if (r1 < M) bi1 = biasC[r1]; }
        #pragma unroll
        for (int j = 0; j < NJ; ++j) {
            int c = n0 + wn + j * 8 + ((lane & 3) << 1);
            float4 v = acc[i][j];
            if (r0 < M) {
                float x0 = v.x * sc0 + bi0, x1 = v.y * sc0 + bi0;
                if (relu) { x0 = fmaxf(x0, 0.f); x1 = fmaxf(x1, 0.f); }
                if (resid) {
                    if (c < N)     x0 = x0 * gmv + resid[(long)r0 * N + c];
                    if (c + 1 < N) x1 = x1 * gmv + resid[(long)r0 * N + c + 1];
                }
                if (c < N)     C[(long)r0 * N + c]     = x0;
                if (c + 1 < N) C[(long)r0 * N + c + 1] = x1;
            }
            if (r1 < M) {
                float y0 = v.z * sc1 + bi1, y1 = v.w * sc1 + bi1;
                if (relu) { y0 = fmaxf(y0, 0.f); y1 = fmaxf(y1, 0.f); }
                if (resid) {
                    if (c < N)     y0 = y0 * gmv + resid[(long)r1 * N + c];
                    if (c + 1 < N) y1 = y1 * gmv + resid[(long)r1 * N + c + 1];
                }
                if (c < N)     C[(long)r1 * N + c]     = y0;
                if (c + 1 < N) C[(long)r1 * N + c + 1] = y1;
            }
        }
    }
}

// ---------------- pointwise / pack kernels ----------------------------------
__global__ void tshuffle_kernel(const float* __restrict__ pf,
                                const float* __restrict__ gw,
                                const float* __restrict__ gb,
                                float* __restrict__ out)
{
    int idx = blockIdx.x * blockDim.x + threadIdx.x;
    if (idx >= B_SZ * COUT * HW) return;
    int c = (idx / HW) % COUT;
    float s = gb[c];
    #pragma unroll
    for (int k = 0; k < K_FR; ++k)
        s = fmaf(pf[(long)k * (B_SZ * COUT * HW) + idx], gw[c * K_FR + k], s);
    out[idx] = s;
}

__global__ void bnprep4_kernel(const float* __restrict__ p0,
                               const float* __restrict__ p1,
                               const float* __restrict__ p2,
                               const float* __restrict__ p3,
                               float* __restrict__ a, float* __restrict__ b)
{
    int c = threadIdx.x;
    int slot = blockIdx.x;
    const float* p = (slot == 0) ? p0 : (slot == 1) ? p1 : (slot == 2) ? p2 : p3;
    float g = p[c], be = p[COUT + c], m = p[2 * COUT + c], v = p[3 * COUT + c];
    float s = g * rsqrtf(v + 1e-5f);
    a[slot * COUT + c] = s;
    b[slot * COUT + c] = be - m * s;
}

// weight pack: src [M][K] fp32 -> dst [K/16][M][16 uints]
__global__ void packW_kernel(const float* __restrict__ src, unsigned* __restrict__ dst,
                             int M, int K)
{
    long idx = (long)blockIdx.x * blockDim.x + threadIdx.x;
    long total = (long)M * (K >> 4);
    if (idx >= total) return;
    int kt = (int)(idx / M);
    int m  = (int)(idx - (long)kt * M);
    const float* s = src + (long)m * K + kt * 16;
    unsigned rr[16];
    #pragma unroll
    for (int p = 0; p < 8; ++p) {
        float2 v = *(const float2*)&s[2 * p];
        unsigned hi, lo;
        split2(v.x, v.y, hi, lo);
        int ph = posH(p);
        rr[ph]     = hi;
        rr[ph + 2] = lo;
    }
    unsigned* d = dst + idx * 16;
    *(uint4*)(d + 0)  = *(const uint4*)(rr + 0);
    *(uint4*)(d + 4)  = *(const uint4*)(rr + 4);
    *(uint4*)(d + 8)  = *(const uint4*)(rr + 8);
    *(uint4*)(d + 12) = *(const uint4*)(rr + 12);
}

// batched row-major pack: src [z][M][K] -> dst [z][K/16][M][16]
__global__ void packWz_kernel(const float* __restrict__ src, unsigned* __restrict__ dst,
                              int M, int K, long srcZ, long dstZ)
{
    long idx = (long)blockIdx.x * blockDim.x + threadIdx.x;
    long per = (long)M * (K >> 4);
    long total = (long)B_SZ * per;
    if (idx >= total) return;
    int z = (int)(idx / per);
    long rem = idx - (long)z * per;
    int kt = (int)(rem / M);
    int m  = (int)(rem - (long)kt * M);
    const float* s = src + (long)z * srcZ + (long)m * K + kt * 16;
    unsigned rr[16];
    #pragma unroll
    for (int p = 0; p < 8; ++p) {
        float2 v = *(const float2*)&s[2 * p];
        unsigned hi, lo;
        split2(v.x, v.y, hi, lo);
        int ph = posH(p);
        rr[ph]     = hi;
        rr[ph + 2] = lo;
    }
    unsigned* d = dst + (long)z * dstZ + rem * 16;
    *(uint4*)(d + 0)  = *(const uint4*)(rr + 0);
    *(uint4*)(d + 4)  = *(const uint4*)(rr + 4);
    *(uint4*)(d + 8)  = *(const uint4*)(rr + 8);
    *(uint4*)(d + 12) = *(const uint4*)(rr + 12);
}

// im2col + split + pack
__global__ void im2colpack_kernel(const float* __restrict__ x, unsigned* __restrict__ colP)
{
    long idx = (long)blockIdx.x * blockDim.x + threadIdx.x;
    const long total = (long)B_SZ * NKT * HW;
    if (idx >= total) return;
    int n  = (int)(idx % HW);
    long r = idx / HW;
    int kt = (int)(r % NKT);
    int z  = (int)(r / NKT);
    const float* xb = x + (long)z * COUT * HW;
    int h = n / W_, w = n % W_;

    unsigned rr[16];
    #pragma unroll
    for (int p = 0; p < 8; ++p) {
        int k0 = kt * 16 + 2 * p;
        float f0, f1;
        {
            int ci = k0 / 9, tq = k0 - ci * 9;
            int hh = h + tq / 3 - 1, ww = w + tq % 3 - 1;
            f0 = ((unsigned)hh < H_ && (unsigned)ww < W_) ? xb[(long)ci * HW + hh * W_ + ww] : 0.f;
        }
        {
            int k1 = k0 + 1;
            int ci = k1 / 9, tq = k1 - ci * 9;
            int hh = h + tq / 3 - 1, ww = w + tq % 3 - 1;
            f1 = ((unsigned)hh < H_ && (unsigned)ww < W_) ? xb[(long)ci * HW + hh * W_ + ww] : 0.f;
        }
        unsigned hi, lo;
        split2(f0, f1, hi, lo);
        int ph = posH(p);
        rr[ph]     = hi;
        rr[ph + 2] = lo;
    }
    unsigned* dst = colP + ((long)(z * NKT + kt) * NPAD + n) * 16;
    *(uint4*)(dst + 0)  = *(const uint4*)(rr + 0);
    *(uint4*)(dst + 4)  = *(const uint4*)(rr + 4);
    *(uint4*)(dst + 8)  = *(const uint4*)(rr + 8);
    *(uint4*)(dst + 12) = *(const uint4*)(rr + 12);
}

// generic pack: src [z][K][HW] -> [z][kt][n<NPAD][16]
__global__ void pack_kernel(const float* __restrict__ src, unsigned* __restrict__ colP,
                            int ktCount, long srcStride)
{
    long idx = (long)blockIdx.x * blockDim.x + threadIdx.x;
    const long total = (long)B_SZ * ktCount * HW;
    if (idx >= total) return;
    int n  = (int)(idx % HW);
    long r = idx / HW;
    int kt = (int)(r % ktCount);
    int z  = (int)(r / ktCount);
    const float* s = src + (long)z * srcStride + (long)(kt * 16) * HW + n;

    unsigned rr[16];
    #pragma unroll
    for (int p = 0; p < 8; ++p) {
        float f0 = s[(long)(2 * p) * HW];
        float f1 = s[(long)(2 * p + 1) * HW];
        unsigned hi, lo;
        split2(f0, f1, hi, lo);
        int ph = posH(p);
        rr[ph]     = hi;
        rr[ph + 2] = lo;
    }
    unsigned* dst = colP + ((long)(z * ktCount + kt) * NPAD + n) * 16;
    *(uint4*)(dst + 0)  = *(const uint4*)(rr + 0);
    *(uint4*)(dst + 4)  = *(const uint4*)(rr + 4);
    *(uint4*)(dst + 8)  = *(const uint4*)(rr + 8);
    *(uint4*)(dst + 12) = *(const uint4*)(rr + 12);
}

// concat keyframe feat with x2 AND pack (K=512 -> 32 k-tiles)
__global__ void concatpack_kernel(const float* __restrict__ kf,
                                  const float* __restrict__ x,
                                  unsigned* __restrict__ colP)
{
    const int KT = 32;
    long idx = (long)blockIdx.x * blockDim.x + threadIdx.x;
    const long total = (long)B_SZ * KT * HW;
    if (idx >= total) return;
    int n  = (int)(idx % HW);
    long r = idx / HW;
    int kt = (int)(r % KT);
    int z  = (int)(r / KT);
    const float* s = (kt < 16 ? kf + (long)z * COUT * HW + (long)(kt * 16) * HW
                              : x  + (long)z * COUT * HW + (long)((kt - 16) * 16) * HW) + n;

    unsigned rr[16];
    #pragma unroll
    for (int p = 0; p < 8; ++p) {
        float f0 = s[(long)(2 * p) * HW];
        float f1 = s[(long)(2 * p + 1) * HW];
        unsigned hi, lo;
        split2(f0, f1, hi, lo);
        int ph = posH(p);
        rr[ph]     = hi;
        rr[ph + 2] = lo;
    }
    unsigned* dst = colP + ((long)(z * KT + kt) * NPAD + n) * 16;
    *(uint4*)(dst + 0)  = *(const uint4*)(rr + 0);
    *(uint4*)(dst + 4)  = *(const uint4*)(rr + 4);
    *(uint4*)(dst + 8)  = *(const uint4*)(rr + 8);
    *(uint4*)(dst + 12) = *(const uint4*)(rr + 12);
}

// fused softmax + pack as B rows (spatial attn, len 784 -> 49 kt, rows < NPAD)
__global__ void softmax_packB784_kernel(const float* __restrict__ S,
                                        unsigned* __restrict__ dst, float scale)
{
    const float* p = S + (long)blockIdx.x * HW;
    int z = blockIdx.x / HW;
    int n = blockIdx.x % HW;
    __shared__ float red[256];
    int tid = threadIdx.x;
    float mx = -1e30f;
    for (int j = tid; j < HW; j += 256) mx = fmaxf(mx, p[j] * scale);
    red[tid] = mx; __syncthreads();
    for (int s = 128; s > 0; s >>= 1) {
        if (tid < s) red[tid] = fmaxf(red[tid], red[tid + s]);
        __syncthreads();
    }
    mx = red[0]; __syncthreads();
    float sum = 0.f;
    for (int j = tid; j < HW; j += 256) sum += expf(p[j] * scale - mx);
    red[tid] = sum; __syncthreads();
    for (int s = 128; s > 0; s >>= 1) {
        if (tid < s) red[tid] += red[tid + s];
        __syncthreads();
    }
    float inv = 1.f / red[0];
    unsigned* base = dst + (long)z * (49L * NPAD * 16);
    for (int pp = tid; pp < 392; pp += 256) {
        float v0 = expf(p[2 * pp] * scale - mx) * inv;
        float v1 = expf(p[2 * pp + 1] * scale - mx) * inv;
        unsigned hi, lo;
        split2(v0, v1, hi, lo);
        int kt = pp >> 3, pr = pp & 7;
        unsigned* d = base + ((long)kt * NPAD + n) * 16;
        int ph = posH(pr);
        d[ph]     = hi;
        d[ph + 2] = lo;
    }
}

// fused softmax + pack as A rows (channel attn, len 256 -> 16 kt, 256 rows)
__global__ void softmax_packA256_kernel(const float* __restrict__ S,
                                        unsigned* __restrict__ dst, float scale)
{
    const float* p = S + (long)blockIdx.x * COUT;
    int z = blockIdx.x / COUT;
    int i = blockIdx.x % COUT;
    __shared__ float red[256];
    int tid = threadIdx.x;
    float v = (tid < COUT) ? p[tid] * scale : -1e30f;
    red[tid] = v; __syncthreads();
    for (int s = 128; s > 0; s >>= 1) {
        if (tid < s) red[tid] = fmaxf(red[tid], red[tid + s]);
        __syncthreads();
    }
    float mx = red[0]; __syncthreads();
    float e = (tid < COUT) ? expf(p[tid] * scale - mx) : 0.f;
    red[tid] = e; __syncthreads();
    for (int s = 128; s > 0; s >>= 1) {
        if (tid < s) red[tid] += red[tid + s];
        __syncthreads();
    }
    float inv = 1.f / red[0];
    unsigned* base = dst + (long)z * (16L * 256 * 16);
    if (tid < 128) {
        int pp = tid;
        float v0 = expf(p[2 * pp] * scale - mx) * inv;
        float v1 = expf(p[2 * pp + 1] * scale - mx) * inv;
        unsigned hi, lo;
        split2(v0, v1, hi, lo);
        int kt = pp >> 3, pr = pp & 7;
        unsigned* d = base + ((long)kt * 256 + i) * 16;
        int ph = posH(pr);
        d[ph]     = hi;
        d[ph + 2] = lo;
    }
}

// ---------------- host-side helpers -----------------------------------------
static const int SMB_SMALL_PP  = (2 * 64 * 16 + 2 * 128 * 16) * 4;      // 24576
static const int SMB_BIG_PP    = (2 * 128 * 16 + 2 * 128 * 16) * 4;     // 32768
static const int SMB_BIG_PA    = (2 * 128 * 16 + 2 * 128 * RSTR) * 4;   // 36864

// mode: 3 = small A+B packed; 4 = big A+B packed; 5 = big A packed, B fp32 [K,N]
static void launch_gemm(int mode,
                        const unsigned* A, const float* B, float* C,
                        int M, int N, int Kd, int lda, int ldb,
                        long aS, int aDiv, long bS, long cS,
                        const float* sc, const float* bi, long biS,
                        int relu, const float* gp,
                        const float* res, long rS, int Z)
{
    dim3 block(256);
    if (mode == 4 || mode == 5) {
        dim3 grid((N + 127) / 128, (M + 127) / 128, Z);
        if (mode == 4) {
            cudaFuncSetAttribute(gemm_bf<128,1,true>,
                                 cudaFuncAttributeMaxDynamicSharedMemorySize, SMB_BIG_PP);
            gemm_bf<128,1,true><<<grid, block, SMB_BIG_PP>>>(A, B, C, M, N, Kd, lda, ldb,
                aS, aDiv, bS, cS, sc, bi, biS, relu, gp, res, rS);
        } else {
            cudaFuncSetAttribute(gemm_bf<128,1,false>,
                                 cudaFuncAttributeMaxDynamicSharedMemorySize, SMB_BIG_PA);
            gemm_bf<128,1,false><<<grid, block, SMB_BIG_PA>>>(A, B, C, M, N, Kd, lda, ldb,
                aS, aDiv, bS, cS, sc, bi, biS, relu, gp, res, rS);
        }
        return;
    }
    dim3 grid((N + 127) / 128, (M + 63) / 64, Z);
    cudaFuncSetAttribute(gemm_bf<64,2,true>,
                         cudaFuncAttributeMaxDynamicSharedMemorySize, SMB_SMALL_PP);
    gemm_bf<64,2,true><<<grid, block, SMB_SMALL_PP>>>(A, B, C, M, N, Kd, lda, ldb,
        aS, aDiv, bS, cS, sc, bi, biS, relu, gp, res, rS);
}

static void packW(const float* src, unsigned* dst, int M, int K)
{
    long total = (long)M * (K >> 4);
    packW_kernel<<<(int)((total + 255) / 256), 256>>>(src, dst, M, K);
}

extern "C" void kernel_launch(void* const* d_in, const int* in_sizes, int n_in,
                              void* d_out, int out_size)
{
    const float* feats    = (const float*)d_in[0];
    const float* proj_w   = (const float*)d_in[1];
    const float* proj_b   = (const float*)d_in[2];
    const float* ts_gw    = (const float*)d_in[3];
    const float* ts_gb    = (const float*)d_in[4];
    const float* ts_w3    = (const float*)d_in[5];
    const float* ts_bn    = (const float*)d_in[6];
    const float* ssam_w1  = (const float*)d_in[7];
    const float* ssam_b1  = (const float*)d_in[8];
    const float* ssam_w2  = (const float*)d_in[9];
    const float* ssam_b2  = (const float*)d_in[10];
    const float* ssam_g   = (const float*)d_in[11];
    const float* csam_w1  = (const float*)d_in[12];
    const float* csam_b1  = (const float*)d_in[13];
    const float* csam_w2  = (const float*)d_in[14];
    const float* csam_b2  = (const float*)d_in[15];
    const float* fuse_w1  = (const float*)d_in[16];
    const float* fuse_bn1 = (const float*)d_in[17];
    const float* fuse_w2  = (const float*)d_in[18];
    const float* fuse_bn2 = (const float*)d_in[19];
    const float* fcsam_w1 = (const float*)d_in[20];
    const float* fcsam_b1 = (const float*)d_in[21];
    const float* fcsam_w2 = (const float*)d_in[22];
    const float* fcsam_b2 = (const float*)d_in[23];
    const float* fuse_w4  = (const float*)d_in[24];
    const float* fuse_bn4 = (const float*)d_in[25];
    float* out = (float*)d_out;

    float *pf, *x, *x2, *o1, *h, *aS_, *aC_, *bnA, *bnB;
    unsigned *colP, *wP;
    cudaGetSymbolAddress((void**)&pf,   g_pf);
    cudaGetSymbolAddress((void**)&x,    g_x);
    cudaGetSymbolAddress((void**)&x2,   g_x2);
    cudaGetSymbolAddress((void**)&o1,   g_o1);
    cudaGetSymbolAddress((void**)&h,    g_h);
    cudaGetSymbolAddress((void**)&aS_,  g_aS);
    cudaGetSymbolAddress((void**)&aC_,  g_aC);
    cudaGetSymbolAddress((void**)&colP, g_colP);
    cudaGetSymbolAddress((void**)&wP,   g_wP);
    cudaGetSymbolAddress((void**)&bnA,  g_bnA);
    cudaGetSymbolAddress((void**)&bnB,  g_bnB);

    const long SP  = (long)COUT * HW;
    const long SPH = (long)C4V * HW;
    const long SPS = (long)HW * HW;
    const long SPC = (long)COUT * COUT;
    const long SPP16  = 16L * NPAD * 16;     // packed plane K=256 (pixel rows)
    const long SPP32  = 32L * NPAD * 16;
    const long SPP64  = 64L * NPAD * 16;
    const long SPP144 = (long)NKT * NPAD * 16;
    const long SPA49  = 49L * 256 * 16;      // packWz plane K=784, 256 rows
    const long SPB49  = 49L * NPAD * 16;     // softmax-packed spatial attn
    const long SPA16  = 16L * 256 * 16;      // packed aC
    const long PACKC  = (long)B_SZ * NKT * HW;

    // 0. constants
    bnprep4_kernel<<<4, 256>>>(ts_bn, fuse_bn1, fuse_bn2, fuse_bn4, bnA, bnB);
    packW(proj_w,   wP + OFF_PROJ,  K_FR * COUT, CIN);
    packW(ts_w3,    wP + OFF_CONV1, COUT, COUT * 9);
    packW(fuse_w2,  wP + OFF_CONV2, COUT, COUT * 9);
    packW(fuse_w4,  wP + OFF_CONV3, COUT, COUT * 9);
    packW(ssam_w1,  wP + OFF_MLP1A, C4V, COUT);
    packW(csam_w1,  wP + OFF_MLP1B, C4V, COUT);
    packW(fcsam_w1, wP + OFF_MLP1C, C4V, COUT);
    packW(ssam_w2,  wP + OFF_MLP2A, COUT, C4V);
    packW(csam_w2,  wP + OFF_MLP2B, COUT, C4V);
    packW(fcsam_w2, wP + OFF_MLP2C, COUT, C4V);
    packW(fuse_w1,  wP + OFF_FUSE1, COUT, 2 * COUT);

    // 1. per-frame 1x1 projection
    launch_gemm(5, wP + OFF_PROJ, feats, pf, COUT, HW, CIN,
                K_FR * COUT, HW, 4096, B_SZ, (long)CIN * HW, SP,
                nullptr, proj_b, COUT, 0, nullptr, nullptr, 0, K_FR * B_SZ);

    // 2. temporal shuffle + grouped 1x1 -> x
    {
        int total = B_SZ * COUT * HW;
        tshuffle_kernel<<<(total + 255) / 256, 256>>>(pf, ts_gw, ts_gb, x);
    }

    // 3. 3x3 conv + BN -> x2
    im2colpack_kernel<<<(int)((PACKC + 255) / 256), 256>>>(x, colP);
    launch_gemm(3, wP + OFF_CONV1, (const float*)colP, x2, COUT, HW, COUT * 9,
                COUT, NPAD, 0, 1, SPP144, SP,
                bnA + 0 * COUT, bnB + 0 * COUT, 0, 0, nullptr, nullptr, 0, B_SZ);

    // 4. spatial self-attention (input x2, output x)
    pack_kernel<<<(int)(((long)B_SZ * 16 * HW + 255) / 256), 256>>>(x2, colP + OFFa, 16, SP);
    packWz_kernel<<<(int)(((long)B_SZ * 256 * 49 + 255) / 256), 256>>>(x2, colP + OFFb, 256, HW, SP, SPA49);
    launch_gemm(4, colP + OFFa, (const float*)(colP + OFFa), aS_, HW, HW, COUT,
                NPAD, NPAD, SPP16, 1, SPP16, SPS,
                nullptr, nullptr, 0, 0, nullptr, nullptr, 0, B_SZ);
    softmax_packB784_kernel<<<B_SZ * HW, 256>>>(aS_, colP + OFFc, 0.0625f);
    launch_gemm(3, colP + OFFb, (const float*)(colP + OFFc), o1, COUT, HW, HW,
                256, NPAD, SPA49, 1, SPB49, SP,
                nullptr, nullptr, 0, 0, nullptr, nullptr, 0, B_SZ);
    pack_kernel<<<(int)(((long)B_SZ * 16 * HW + 255) / 256), 256>>>(o1, colP + OFFa, 16, SP);
    launch_gemm(4, wP + OFF_MLP1A, (const float*)(colP + OFFa), h, C4V, HW, COUT,
                C4V, NPAD, 0, 1, SPP16, SPH,
                nullptr, ssam_b1, 0, 1, nullptr, nullptr, 0, B_SZ);
    pack_kernel<<<(int)(((long)B_SZ * 64 * HW + 255) / 256), 256>>>(h, colP + OFFa, 64, SPH);
    launch_gemm(3, wP + OFF_MLP2A, (const float*)(colP + OFFa), x, COUT, HW, C4V,
                COUT, NPAD, 0, 1, SPP64, SP,
                nullptr, ssam_b2, 0, 0, ssam_g, x2, SP, B_SZ);

    // 5. channel self-attention (input x, output x2)
    packWz_kernel<<<(int)(((long)B_SZ * 256 * 49 + 255) / 256), 256>>>(x, colP + OFFa, 256, HW, SP, SPA49);
    launch_gemm(3, colP + OFFa, (const float*)(colP + OFFa), aC_, COUT, COUT, HW,
                256, 256, SPA49, 1, SPA49, SPC,
                nullptr, nullptr, 0, 0, nullptr, nullptr, 0, B_SZ);
    softmax_packA256_kernel<<<B_SZ * COUT, 256>>>(aC_, colP + OFFb, 0.0625f);
    pack_kernel<<<(int)(((long)B_SZ * 16 * HW + 255) / 256), 256>>>(x, colP + OFFc, 16, SP);
    launch_gemm(3, colP + OFFb, (const float*)(colP + OFFc), o1, COUT, HW, COUT,
                256, NPAD, SPA16, 1, SPP16, SP,
                nullptr, nullptr, 0, 0, nullptr, nullptr, 0, B_SZ);
    pack_kernel<<<(int)(((long)B_SZ * 16 * HW + 255) / 256), 256>>>(o1, colP + OFFa, 16, SP);
    launch_gemm(4, wP + OFF_MLP1B, (const float*)(colP + OFFa), h, C4V, HW, COUT,
                C4V, NPAD, 0, 1, SPP16, SPH,
                nullptr, csam_b1, 0, 1, nullptr, nullptr, 0, B_SZ);
    pack_kernel<<<(int)(((long)B_SZ * 64 * HW + 255) / 256), 256>>>(h, colP + OFFa, 64, SPH);
    launch_gemm(3, wP + OFF_MLP2B, (const float*)(colP + OFFa), x2, COUT, HW, C4V,
                COUT, NPAD, 0, 1, SPP64, SP,
                nullptr, csam_b2, 0, 0, nullptr, x, SP, B_SZ);

    // 6. fuse: concat keyframe feat (pf[K-1]) with x2 -> packed directly
    {
        long total = (long)B_SZ * 32 * HW;
        concatpack_kernel<<<(int)((total + 255) / 256), 256>>>(
            pf + (long)(K_FR - 1) * B_SZ * SP, x2, colP);
    }
    launch_gemm(3, wP + OFF_FUSE1, (const float*)colP, x, COUT, HW, 2 * COUT,
                COUT, NPAD, 0, 1, SPP32, SP,
                bnA + 1 * COUT, bnB + 1 * COUT, 0, 1, nullptr, nullptr, 0, B_SZ);

    // 7. 3x3 conv + BN + relu -> x2
    im2colpack_kernel<<<(int)((PACKC + 255) / 256), 256>>>(x, colP);
    launch_gemm(3, wP + OFF_CONV2, (const float*)colP, x2, COUT, HW, COUT * 9,
                COUT, NPAD, 0, 1, SPP144, SP,
                bnA + 2 * COUT, bnB + 2 * COUT, 0, 1, nullptr, nullptr, 0, B_SZ);

    // 8. channel self-attention (input x2, output x)
    packWz_kernel<<<(int)(((long)B_SZ * 256 * 49 + 255) / 256), 256>>>(x2, colP + OFFa, 256, HW, SP, SPA49);
    launch_gemm(3, colP + OFFa, (const float*)(colP + OFFa), aC_, COUT, COUT, HW,
                256, 256, SPA49, 1, SPA49, SPC,
                nullptr, nullptr, 0, 0, nullptr, nullptr, 0, B_SZ);
    softmax_packA256_kernel<<<B_SZ * COUT, 256>>>(aC_, colP + OFFb, 0.0625f);
    pack_kernel<<<(int)(((long)B_SZ * 16 * HW + 255) / 256), 256>>>(x2, colP + OFFc, 16, SP);
    launch_gemm(3, colP + OFFb, (const float*)(colP + OFFc), o1, COUT, HW, COUT,
                256, NPAD, SPA16, 1, SPP16, SP,
                nullptr, nullptr, 0, 0, nullptr, nullptr, 0, B_SZ);
    pack_kernel<<<(int)(((long)B_SZ * 16 * HW + 255) / 256), 256>>>(o1, colP + OFFa, 16, SP);
    launch_gemm(4, wP + OFF_MLP1C, (const float*)(colP + OFFa), h, C4V, HW, COUT,
                C4V, NPAD, 0, 1, SPP16, SPH,
                nullptr, fcsam_b1, 0, 1, nullptr, nullptr, 0, B_SZ);
    pack_kernel<<<(int)(((long)B_SZ * 64 * HW + 255) / 256), 256>>>(h, colP + OFFa, 64, SPH);
    launch_gemm(3, wP + OFF_MLP2C, (const float*)(colP + OFFa), x, COUT, HW, C4V,
                COUT, NPAD, 0, 1, SPP64, SP,
                nullptr, fcsam_b2, 0, 0, nullptr, x2, SP, B_SZ);

    // 9. final 3x3 conv + BN + relu -> d_out
    im2colpack_kernel<<<(int)((PACKC + 255) / 256), 256>>>(x, colP);
    launch_gemm(3, wP + OFF_CONV3, (const float*)colP, out, COUT, HW, COUT * 9,
                COUT, NPAD, 0, 1, SPP144, SP,
                bnA + 3 * COUT, bnB + 3 * COUT, 0, 1, nullptr, nullptr, 0, B_SZ);
}

// round 16
// speedup vs baseline: 2.2435x; 1.0323x over previous
#include <cuda_runtime.h>
#include <cuda_bf16.h>
#include <math.h>

#define K_FR 8
#define B_SZ 8
#define CIN  512
#define COUT 256
#define H_   28
#define W_   28
#define HW   784
#define C4V  1024
#define NKT  144          // max k-tiles (conv: 2304/16)
#define NPAD 896          // padded pixel rows per k-tile (7*128)

// packed-weight buffer offsets (uints)
#define OFF_PROJ   0L
#define OFF_CONV1  1048576L
#define OFF_CONV2  1638400L
#define OFF_CONV3  2228224L
#define OFF_MLP1A  2818048L
#define OFF_MLP1B  3080192L
#define OFF_MLP1C  3342336L
#define OFF_MLP2A  3604480L
#define OFF_MLP2B  3866624L
#define OFF_MLP2C  4128768L
#define OFF_FUSE1  4390912L
#define WP_TOTAL   4521984L
#define WP_ROWS    282624L   // WP_TOTAL / 16

// activation-pack regions (uints)
#define OFFa 0L
#define OFFb 2097152L
#define OFFc 4194304L

// ---------------- scratch (device globals; no allocation at runtime) --------
__device__ __align__(16) float g_pf  [K_FR * B_SZ * COUT * HW];
__device__ __align__(16) float g_x   [B_SZ * COUT * HW];
__device__ __align__(16) float g_x2  [B_SZ * COUT * HW];
__device__ __align__(16) float g_o1  [B_SZ * COUT * HW];
__device__ __align__(16) float g_h   [B_SZ * C4V * HW];
__device__ __align__(16) float g_aS  [B_SZ * HW * HW];
__device__ __align__(16) float g_aC  [B_SZ * COUT * COUT];
__device__ __align__(16) unsigned g_colP [(long)B_SZ * NKT * NPAD * 16];  // 66MB
__device__ __align__(16) unsigned g_wP   [WP_TOTAL];                      // 18MB packed weights
__device__ float g_bnA [4 * COUT];
__device__ float g_bnB [4 * COUT];

// ---------------- 3xBF16 tensor-core GEMM -----------------------------------
// a*b ~= aH*bH + aH*bL + aL*bH, bf16 hi/lo split, fp32 acc. mma.m16n8k16.
// A ALWAYS pre-packed: [kt][row(lda rows per kt)][16 uints].
// B: BPK -> pre-packed [kt][row(ldb rows per kt)][16]; else fp32 [K,N] (proj).
// epilogue: v = acc*scale[m]+bias[m]; relu; v = v*gamma + resid[m,n]

__device__ __forceinline__ unsigned pack2(float f0, float f1) {   // f0->low, f1->high
    unsigned r;
    asm("cvt.rn.bf16x2.f32 %0, %1, %2;" : "=r"(r) : "f"(f1), "f"(f0));
    return r;
}
__device__ __forceinline__ void split2(float f0, float f1, unsigned& hi, unsigned& lo) {
    hi = pack2(f0, f1);
    float h0 = __uint_as_float(hi << 16);
    float h1 = __uint_as_float(hi & 0xffff0000u);
    lo = pack2(f0 - h0, f1 - h1);
}
__device__ __forceinline__ void mma_bf16(float4& d, const unsigned a[4], const unsigned b[2]) {
    asm volatile(
        "mma.sync.aligned.m16n8k16.row.col.f32.bf16.bf16.f32 "
        "{%0,%1,%2,%3}, {%4,%5,%6,%7}, {%8,%9}, {%0,%1,%2,%3};"
        : "+f"(d.x), "+f"(d.y), "+f"(d.z), "+f"(d.w)
        : "r"(a[0]), "r"(a[1]), "r"(a[2]), "r"(a[3]), "r"(b[0]), "r"(b[1]));
}

#define RSTR 20
#define BN   128

__device__ __forceinline__ int posH(int p) { return 4 * (p & 3) + (p >> 2); }

template <int TBM, int MAXB, bool BPK>
__global__ void __launch_bounds__(256, MAXB) gemm_bf(
    const unsigned* __restrict__ A, const float* __restrict__ Bm, float* __restrict__ C,
    int M, int N, int Kd, int lda, int ldb,
    long aS, int aDiv, long bS, long cS,
    const float* __restrict__ scaleC, const float* __restrict__ biasC, long biS,
    int relu, const float* __restrict__ gammaPtr,
    const float* __restrict__ resid, long rS)
{
    constexpr int RSB = BPK ? 16 : RSTR;
    extern __shared__ unsigned sm[];
    unsigned* As = sm;                       // [2][TBM][16]
    unsigned* Bs = sm + 2 * TBM * 16;        // [2][BN ][RSB]

    const int z = blockIdx.z;
    A  += (long)(z / aDiv) * aS;
    Bm += (long)z * bS;
    C  += (long)z * cS;
    if (biasC) biasC += (long)(z / aDiv) * biS;
    if (resid) resid += (long)z * rS;

    const int tid  = threadIdx.x;
    const int lane = tid & 31, warp = tid >> 5;
    constexpr int MI = TBM / 32;
    constexpr int NJ = 4;
    constexpr int UAP = TBM / 64;
    constexpr int UB = 4;
    const int wm = (warp >> 2) * (TBM / 2);
    const int wn = (warp & 3) * 32;
    const int m0 = blockIdx.y * TBM, n0 = blockIdx.x * BN;

    float4 acc[MI][NJ];
    #pragma unroll
    for (int i = 0; i < MI; ++i)
        #pragma unroll
        for (int j = 0; j < NJ; ++j)
            acc[i][j] = make_float4(0.f, 0.f, 0.f, 0.f);

    uint4 vaP[UAP], vbP[2];
    float2 vb[UB];

    auto loadA = [&](int k0) {
        const uint4* ap = reinterpret_cast<const uint4*>(A);
        long base = ((long)(k0 >> 4) * lda + m0) * 4;
        #pragma unroll
        for (int t = 0; t < UAP; ++t)
            vaP[t] = ap[base + tid + t * 256];
    };
    auto loadB = [&](int k0) {
        if (BPK) {
            const uint4* bp = reinterpret_cast<const uint4*>(Bm);
            long base = ((long)(k0 >> 4) * ldb + n0) * 4;
            vbP[0] = bp[base + tid];
            vbP[1] = bp[base + tid + 256];
        } else {     // B [K,N] fp32
            int n = tid & 127, psel = tid >> 7;
            int gn = n0 + n;
            #pragma unroll
            for (int t = 0; t < UB; ++t) {
                int p = psel * UB + t;
                float f0 = 0.f, f1 = 0.f;
                if (gn < N) {
                    f0 = Bm[(long)(k0 + 2 * p) * ldb + gn];
                    f1 = Bm[(long)(k0 + 2 * p + 1) * ldb + gn];
                }
                vb[t] = make_float2(f0, f1);
            }
        }
    };
    auto storeA = [&](int buf) {
        #pragma unroll
        for (int t = 0; t < UAP; ++t)
            *(uint4*)&As[(long)(buf * TBM + (tid >> 2) + t * 64) * 16 + (tid & 3) * 4] = vaP[t];
    };
    auto storeB = [&](int buf) {
        if (BPK) {
            *(uint4*)&Bs[(long)(buf * BN + (tid >> 2)) * RSB + (tid & 3) * 4] = vbP[0];
            *(uint4*)&Bs[(long)(buf * BN + (tid >> 2) + 64) * RSB + (tid & 3) * 4] = vbP[1];
        } else {
            int n = tid & 127, psel = tid >> 7;
            #pragma unroll
            for (int t = 0; t < UB; ++t) {
                int p = psel * UB + t;
                unsigned hi, lo;
                split2(vb[t].x, vb[t].y, hi, lo);
                unsigned* base = &Bs[(long)(buf * BN + n) * RSB];
                int ph = posH(p);
                base[ph]     = hi;
                base[ph + 2] = lo;
            }
        }
    };
    auto compute = [&](int buf) {
        uint4 a0[MI], a1[MI], bv[NJ];
        #pragma unroll
        for (int i = 0; i < MI; ++i) {
            int r = wm + i * 16 + (lane >> 2);
            a0[i] = *(const uint4*)&As[(long)(buf * TBM + r) * 16 + ((lane & 3) << 2)];
            a1[i] = *(const uint4*)&As[(long)(buf * TBM + r + 8) * 16 + ((lane & 3) << 2)];
        }
        #pragma unroll
        for (int j = 0; j < NJ; ++j) {
            int c = wn + j * 8 + (lane >> 2);
            bv[j] = *(const uint4*)&Bs[(long)(buf * BN + c) * RSB + ((lane & 3) << 2)];
        }
        unsigned aH[MI][4], aL[MI][4], bH[NJ][2], bL[NJ][2];
        #pragma unroll
        for (int i = 0; i < MI; ++i) {
            aH[i][0] = a0[i].x; aH[i][1] = a1[i].x; aH[i][2] = a0[i].y; aH[i][3] = a1[i].y;
            aL[i][0] = a0[i].z; aL[i][1] = a1[i].z; aL[i][2] = a0[i].w; aL[i][3] = a1[i].w;
        }
        #pragma unroll
        for (int j = 0; j < NJ; ++j) {
            bH[j][0] = bv[j].x; bH[j][1] = bv[j].y;
            bL[j][0] = bv[j].z; bL[j][1] = bv[j].w;
        }
        #pragma unroll
        for (int j = 0; j < NJ; ++j)
            #pragma unroll
            for (int i = 0; i < MI; ++i)
                mma_bf16(acc[i][j], aH[i], bH[j]);
        #pragma unroll
        for (int j = 0; j < NJ; ++j)
            #pragma unroll
            for (int i = 0; i < MI; ++i)
                mma_bf16(acc[i][j], aH[i], bL[j]);
        #pragma unroll
        for (int j = 0; j < NJ; ++j)
            #pragma unroll
            for (int i = 0; i < MI; ++i)
                mma_bf16(acc[i][j], aL[i], bH[j]);
    };

    int buf = 0;
    loadA(0); loadB(0);
    storeA(0); storeB(0);
    __syncthreads();

    for (int k0 = 0; k0 < Kd; k0 += 16) {
        bool more = (k0 + 16) < Kd;
        if (more) { loadA(k0 + 16); loadB(k0 + 16); }
        compute(buf);
        if (more) {
            storeA(buf ^ 1); storeB(buf ^ 1);
            __syncthreads();
            buf ^= 1;
        }
    }

    const float gmv = gammaPtr ? *gammaPtr : 1.f;
    #pragma unroll
    for (int i = 0; i < MI; ++i) {
        int r0 = m0 + wm + i * 16 + (lane >> 2);
        int r1 = r0 + 8;
        float sc0 = 1.f, bi0 = 0.f, sc1 = 1.f, bi1 = 0.f;
        if (scaleC) { if (r0 < M) sc0 = scaleC[r0]; if (r1 < M) sc1 = scaleC[r1]; }
        if (biasC)  { if (r0 < M) bi0 = biasC[r0];  if (r1 < M) bi1 = biasC[r1]; }
        #pragma unroll
        for (int j = 0; j < NJ; ++j) {
            int c = n0 + wn + j * 8 + ((lane & 3) << 1);
            float4 v = acc[i][j];
            if (r0 < M) {
                float x0 = v.x * sc0 + bi0, x1 = v.y * sc0 + bi0;
                if (relu) { x0 = fmaxf(x0, 0.f); x1 = fmaxf(x1, 0.f); }
                if (resid) {
                    if (c < N)     x0 = x0 * gmv + resid[(long)r0 * N + c];
                    if (c + 1 < N) x1 = x1 * gmv + resid[(long)r0 * N + c + 1];
                }
                if (c < N)     C[(long)r0 * N + c]     = x0;
                if (c + 1 < N) C[(long)r0 * N + c + 1] = x1;
            }
            if (r1 < M) {
                float y0 = v.z * sc1 + bi1, y1 = v.w * sc1 + bi1;
                if (relu) { y0 = fmaxf(y0, 0.f); y1 = fmaxf(y1, 0.f); }
                if (resid) {
                    if (c < N)     y0 = y0 * gmv + resid[(long)r1 * N + c];
                    if (c + 1 < N) y1 = y1 * gmv + resid[(long)r1 * N + c + 1];
                }
                if (c < N)     C[(long)r1 * N + c]     = y0;
                if (c + 1 < N) C[(long)r1 * N + c + 1] = y1;
            }
        }
    }
}

// ---------------- pointwise / pack kernels ----------------------------------
__global__ void tshuffle_kernel(const float* __restrict__ pf,
                                const float* __restrict__ gw,
                                const float* __restrict__ gb,
                                float* __restrict__ out)
{
    int idx = blockIdx.x * blockDim.x + threadIdx.x;
    if (idx >= B_SZ * COUT * HW) return;
    int c = (idx / HW) % COUT;
    float s = gb[c];
    #pragma unroll
    for (int k = 0; k < K_FR; ++k)
        s = fmaf(pf[(long)k * (B_SZ * COUT * HW) + idx], gw[c * K_FR + k], s);
    out[idx] = s;
}

__global__ void bnprep4_kernel(const float* __restrict__ p0,
                               const float* __restrict__ p1,
                               const float* __restrict__ p2,
                               const float* __restrict__ p3,
                               float* __restrict__ a, float* __restrict__ b)
{
    int c = threadIdx.x;
    int slot = blockIdx.x;
    const float* p = (slot == 0) ? p0 : (slot == 1) ? p1 : (slot == 2) ? p2 : p3;
    float g = p[c], be = p[COUT + c], m = p[2 * COUT + c], v = p[3 * COUT + c];
    float s = g * rsqrtf(v + 1e-5f);
    a[slot * COUT + c] = s;
    b[slot * COUT + c] = be - m * s;
}

// ALL 11 weight packs in one launch. Row layout in g_wP is the concatenation
// of per-matrix [K/16][M][16] blocks; dst = wP + row*16 globally.
__global__ void packWall_kernel(
    const float* __restrict__ w0,  // proj     [2048][512]
    const float* __restrict__ w1,  // conv1    [256][2304]
    const float* __restrict__ w2,  // conv2
    const float* __restrict__ w3,  // conv3
    const float* __restrict__ w4,  // mlp1A    [1024][256]
    const float* __restrict__ w5,  // mlp1B
    const float* __restrict__ w6,  // mlp1C
    const float* __restrict__ w7,  // mlp2A    [256][1024]
    const float* __restrict__ w8,  // mlp2B
    const float* __restrict__ w9,  // mlp2C
    const float* __restrict__ w10, // fuse1    [256][512]
    unsigned* __restrict__ dst)
{
    long idx = (long)blockIdx.x * blockDim.x + threadIdx.x;
    if (idx >= WP_ROWS) return;

    const float* src;
    long local;
    int M, K;
    if (idx < 65536L)        { src = w0;  local = idx;            M = 2048; K = 512;  }
    else if (idx < 102400L)  { src = w1;  local = idx - 65536L;   M = 256;  K = 2304; }
    else if (idx < 139264L)  { src = w2;  local = idx - 102400L;  M = 256;  K = 2304; }
    else if (idx < 176128L)  { src = w3;  local = idx - 139264L;  M = 256;  K = 2304; }
    else if (idx < 192512L)  { src = w4;  local = idx - 176128L;  M = 1024; K = 256;  }
    else if (idx < 208896L)  { src = w5;  local = idx - 192512L;  M = 1024; K = 256;  }
    else if (idx < 225280L)  { src = w6;  local = idx - 208896L;  M = 1024; K = 256;  }
    else if (idx < 241664L)  { src = w7;  local = idx - 225280L;  M = 256;  K = 1024; }
    else if (idx < 258048L)  { src = w8;  local = idx - 241664L;  M = 256;  K = 1024; }
    else if (idx < 274432L)  { src = w9;  local = idx - 258048L;  M = 256;  K = 1024; }
    else                     { src = w10; local = idx - 274432L;  M = 256;  K = 512;  }

    int kt = (int)(local / M);
    int m  = (int)(local - (long)kt * M);
    const float* s = src + (long)m * K + kt * 16;
    unsigned rr[16];
    #pragma unroll
    for (int p = 0; p < 8; ++p) {
        float2 v = *(const float2*)&s[2 * p];
        unsigned hi, lo;
        split2(v.x, v.y, hi, lo);
        int ph = posH(p);
        rr[ph]     = hi;
        rr[ph + 2] = lo;
    }
    unsigned* d = dst + idx * 16;
    *(uint4*)(d + 0)  = *(const uint4*)(rr + 0);
    *(uint4*)(d + 4)  = *(const uint4*)(rr + 4);
    *(uint4*)(d + 8)  = *(const uint4*)(rr + 8);
    *(uint4*)(d + 12) = *(const uint4*)(rr + 12);
}

// batched row-major pack: src [z][M][K] -> dst [z][K/16][M][16]
__global__ void packWz_kernel(const float* __restrict__ src, unsigned* __restrict__ dst,
                              int M, int K, long srcZ, long dstZ)
{
    long idx = (long)blockIdx.x * blockDim.x + threadIdx.x;
    long per = (long)M * (K >> 4);
    long total = (long)B_SZ * per;
    if (idx >= total) return;
    int z = (int)(idx / per);
    long rem = idx - (long)z * per;
    int kt = (int)(rem / M);
    int m  = (int)(rem - (long)kt * M);
    const float* s = src + (long)z * srcZ + (long)m * K + kt * 16;
    unsigned rr[16];
    #pragma unroll
    for (int p = 0; p < 8; ++p) {
        float2 v = *(const float2*)&s[2 * p];
        unsigned hi, lo;
        split2(v.x, v.y, hi, lo);
        int ph = posH(p);
        rr[ph]     = hi;
        rr[ph + 2] = lo;
    }
    unsigned* d = dst + (long)z * dstZ + rem * 16;
    *(uint4*)(d + 0)  = *(const uint4*)(rr + 0);
    *(uint4*)(d + 4)  = *(const uint4*)(rr + 4);
    *(uint4*)(d + 8)  = *(const uint4*)(rr + 8);
    *(uint4*)(d + 12) = *(const uint4*)(rr + 12);
}

// im2col + split + pack
__global__ void im2colpack_kernel(const float* __restrict__ x, unsigned* __restrict__ colP)
{
    long idx = (long)blockIdx.x * blockDim.x + threadIdx.x;
    const long total = (long)B_SZ * NKT * HW;
    if (idx >= total) return;
    int n  = (int)(idx % HW);
    long r = idx / HW;
    int kt = (int)(r % NKT);
    int z  = (int)(r / NKT);
    const float* xb = x + (long)z * COUT * HW;
    int h = n / W_, w = n % W_;

    unsigned rr[16];
    #pragma unroll
    for (int p = 0; p < 8; ++p) {
        int k0 = kt * 16 + 2 * p;
        float f0, f1;
        {
            int ci = k0 / 9, tq = k0 - ci * 9;
            int hh = h + tq / 3 - 1, ww = w + tq % 3 - 1;
            f0 = ((unsigned)hh < H_ && (unsigned)ww < W_) ? xb[(long)ci * HW + hh * W_ + ww] : 0.f;
        }
        {
            int k1 = k0 + 1;
            int ci = k1 / 9, tq = k1 - ci * 9;
            int hh = h + tq / 3 - 1, ww = w + tq % 3 - 1;
            f1 = ((unsigned)hh < H_ && (unsigned)ww < W_) ? xb[(long)ci * HW + hh * W_ + ww] : 0.f;
        }
        unsigned hi, lo;
        split2(f0, f1, hi, lo);
        int ph = posH(p);
        rr[ph]     = hi;
        rr[ph + 2] = lo;
    }
    unsigned* dst = colP + ((long)(z * NKT + kt) * NPAD + n) * 16;
    *(uint4*)(dst + 0)  = *(const uint4*)(rr + 0);
    *(uint4*)(dst + 4)  = *(const uint4*)(rr + 4);
    *(uint4*)(dst + 8)  = *(const uint4*)(rr + 8);
    *(uint4*)(dst + 12) = *(const uint4*)(rr + 12);
}

// generic pack: src [z][K][HW] -> [z][kt][n<NPAD][16]
__global__ void pack_kernel(const float* __restrict__ src, unsigned* __restrict__ colP,
                            int ktCount, long srcStride)
{
    long idx = (long)blockIdx.x * blockDim.x + threadIdx.x;
    const long total = (long)B_SZ * ktCount * HW;
    if (idx >= total) return;
    int n  = (int)(idx % HW);
    long r = idx / HW;
    int kt = (int)(r % ktCount);
    int z  = (int)(r / ktCount);
    const float* s = src + (long)z * srcStride + (long)(kt * 16) * HW + n;

    unsigned rr[16];
    #pragma unroll
    for (int p = 0; p < 8; ++p) {
        float f0 = s[(long)(2 * p) * HW];
        float f1 = s[(long)(2 * p + 1) * HW];
        unsigned hi, lo;
        split2(f0, f1, hi, lo);
        int ph = posH(p);
        rr[ph]     = hi;
        rr[ph + 2] = lo;
    }
    unsigned* dst = colP + ((long)(z * ktCount + kt) * NPAD + n) * 16;
    *(uint4*)(dst + 0)  = *(const uint4*)(rr + 0);
    *(uint4*)(dst + 4)  = *(const uint4*)(rr + 4);
    *(uint4*)(dst + 8)  = *(const uint4*)(rr + 8);
    *(uint4*)(dst + 12) = *(const uint4*)(rr + 12);
}

// concat keyframe feat with x2 AND pack (K=512 -> 32 k-tiles)
__global__ void concatpack_kernel(const float* __restrict__ kf,
                                  const float* __restrict__ x,
                                  unsigned* __restrict__ colP)
{
    const int KT = 32;
    long idx = (long)blockIdx.x * blockDim.x + threadIdx.x;
    const long total = (long)B_SZ * KT * HW;
    if (idx >= total) return;
    int n  = (int)(idx % HW);
    long r = idx / HW;
    int kt = (int)(r % KT);
    int z  = (int)(r / KT);
    const float* s = (kt < 16 ? kf + (long)z * COUT * HW + (long)(kt * 16) * HW
                              : x  + (long)z * COUT * HW + (long)((kt - 16) * 16) * HW) + n;

    unsigned rr[16];
    #pragma unroll
    for (int p = 0; p < 8; ++p) {
        float f0 = s[(long)(2 * p) * HW];
        float f1 = s[(long)(2 * p + 1) * HW];
        unsigned hi, lo;
        split2(f0, f1, hi, lo);
        int ph = posH(p);
        rr[ph]     = hi;
        rr[ph + 2] = lo;
    }
    unsigned* dst = colP + ((long)(z * KT + kt) * NPAD + n) * 16;
    *(uint4*)(dst + 0)  = *(const uint4*)(rr + 0);
    *(uint4*)(dst + 4)  = *(const uint4*)(rr + 4);
    *(uint4*)(dst + 8)  = *(const uint4*)(rr + 8);
    *(uint4*)(dst + 12) = *(const uint4*)(rr + 12);
}

// fused softmax + pack as B rows (spatial attn, len 784 -> 49 kt, rows < NPAD)
__global__ void softmax_packB784_kernel(const float* __restrict__ S,
                                        unsigned* __restrict__ dst, float scale)
{
    const float* p = S + (long)blockIdx.x * HW;
    int z = blockIdx.x / HW;
    int n = blockIdx.x % HW;
    __shared__ float red[256];
    int tid = threadIdx.x;
    float mx = -1e30f;
    for (int j = tid; j < HW; j += 256) mx = fmaxf(mx, p[j] * scale);
    red[tid] = mx; __syncthreads();
    for (int s = 128; s > 0; s >>= 1) {
        if (tid < s) red[tid] = fmaxf(red[tid], red[tid + s]);
        __syncthreads();
    }
    mx = red[0]; __syncthreads();
    float sum = 0.f;
    for (int j = tid; j < HW; j += 256) sum += expf(p[j] * scale - mx);
    red[tid] = sum; __syncthreads();
    for (int s = 128; s > 0; s >>= 1) {
        if (tid < s) red[tid] += red[tid + s];
        __syncthreads();
    }
    float inv = 1.f / red[0];
    unsigned* base = dst + (long)z * (49L * NPAD * 16);
    for (int pp = tid; pp < 392; pp += 256) {
        float v0 = expf(p[2 * pp] * scale - mx) * inv;
        float v1 = expf(p[2 * pp + 1] * scale - mx) * inv;
        unsigned hi, lo;
        split2(v0, v1, hi, lo);
        int kt = pp >> 3, pr = pp & 7;
        unsigned* d = base + ((long)kt * NPAD + n) * 16;
        int ph = posH(pr);
        d[ph]     = hi;
        d[ph + 2] = lo;
    }
}

// fused softmax + pack as A rows (channel attn, len 256 -> 16 kt, 256 rows)
__global__ void softmax_packA256_kernel(const float* __restrict__ S,
                                        unsigned* __restrict__ dst, float scale)
{
    const float* p = S + (long)blockIdx.x * COUT;
    int z = blockIdx.x / COUT;
    int i = blockIdx.x % COUT;
    __shared__ float red[256];
    int tid = threadIdx.x;
    float v = (tid < COUT) ? p[tid] * scale : -1e30f;
    red[tid] = v; __syncthreads();
    for (int s = 128; s > 0; s >>= 1) {
        if (tid < s) red[tid] = fmaxf(red[tid], red[tid + s]);
        __syncthreads();
    }
    float mx = red[0]; __syncthreads();
    float e = (tid < COUT) ? expf(p[tid] * scale - mx) : 0.f;
    red[tid] = e; __syncthreads();
    for (int s = 128; s > 0; s >>= 1) {
        if (tid < s) red[tid] += red[tid + s];
        __syncthreads();
    }
    float inv = 1.f / red[0];
    unsigned* base = dst + (long)z * (16L * 256 * 16);
    if (tid < 128) {
        int pp = tid;
        float v0 = expf(p[2 * pp] * scale - mx) * inv;
        float v1 = expf(p[2 * pp + 1] * scale - mx) * inv;
        unsigned hi, lo;
        split2(v0, v1, hi, lo);
        int kt = pp >> 3, pr = pp & 7;
        unsigned* d = base + ((long)kt * 256 + i) * 16;
        int ph = posH(pr);
        d[ph]     = hi;
        d[ph + 2] = lo;
    }
}

// ---------------- host-side helpers -----------------------------------------
static const int SMB_SMALL_PP  = (2 * 64 * 16 + 2 * 128 * 16) * 4;      // 24576
static const int SMB_BIG_PP    = (2 * 128 * 16 + 2 * 128 * 16) * 4;     // 32768
static const int SMB_BIG_PA    = (2 * 128 * 16 + 2 * 128 * RSTR) * 4;   // 36864

// mode: 3 = small A+B packed; 4 = big A+B packed; 5 = big A packed, B fp32 [K,N]
static void launch_gemm(int mode,
                        const unsigned* A, const float* B, float* C,
                        int M, int N, int Kd, int lda, int ldb,
                        long aS, int aDiv, long bS, long cS,
                        const float* sc, const float* bi, long biS,
                        int relu, const float* gp,
                        const float* res, long rS, int Z)
{
    dim3 block(256);
    if (mode == 4 || mode == 5) {
        dim3 grid((N + 127) / 128, (M + 127) / 128, Z);
        if (mode == 4) {
            cudaFuncSetAttribute(gemm_bf<128,1,true>,
                                 cudaFuncAttributeMaxDynamicSharedMemorySize, SMB_BIG_PP);
            gemm_bf<128,1,true><<<grid, block, SMB_BIG_PP>>>(A, B, C, M, N, Kd, lda, ldb,
                aS, aDiv, bS, cS, sc, bi, biS, relu, gp, res, rS);
        } else {
            cudaFuncSetAttribute(gemm_bf<128,1,false>,
                                 cudaFuncAttributeMaxDynamicSharedMemorySize, SMB_BIG_PA);
            gemm_bf<128,1,false><<<grid, block, SMB_BIG_PA>>>(A, B, C, M, N, Kd, lda, ldb,
                aS, aDiv, bS, cS, sc, bi, biS, relu, gp, res, rS);
        }
        return;
    }
    dim3 grid((N + 127) / 128, (M + 63) / 64, Z);
    cudaFuncSetAttribute(gemm_bf<64,2,true>,
                         cudaFuncAttributeMaxDynamicSharedMemorySize, SMB_SMALL_PP);
    gemm_bf<64,2,true><<<grid, block, SMB_SMALL_PP>>>(A, B, C, M, N, Kd, lda, ldb,
        aS, aDiv, bS, cS, sc, bi, biS, relu, gp, res, rS);
}

extern "C" void kernel_launch(void* const* d_in, const int* in_sizes, int n_in,
                              void* d_out, int out_size)
{
    const float* feats    = (const float*)d_in[0];
    const float* proj_w   = (const float*)d_in[1];
    const float* proj_b   = (const float*)d_in[2];
    const float* ts_gw    = (const float*)d_in[3];
    const float* ts_gb    = (const float*)d_in[4];
    const float* ts_w3    = (const float*)d_in[5];
    const float* ts_bn    = (const float*)d_in[6];
    const float* ssam_w1  = (const float*)d_in[7];
    const float* ssam_b1  = (const float*)d_in[8];
    const float* ssam_w2  = (const float*)d_in[9];
    const float* ssam_b2  = (const float*)d_in[10];
    const float* ssam_g   = (const float*)d_in[11];
    const float* csam_w1  = (const float*)d_in[12];
    const float* csam_b1  = (const float*)d_in[13];
    const float* csam_w2  = (const float*)d_in[14];
    const float* csam_b2  = (const float*)d_in[15];
    const float* fuse_w1  = (const float*)d_in[16];
    const float* fuse_bn1 = (const float*)d_in[17];
    const float* fuse_w2  = (const float*)d_in[18];
    const float* fuse_bn2 = (const float*)d_in[19];
    const float* fcsam_w1 = (const float*)d_in[20];
    const float* fcsam_b1 = (const float*)d_in[21];
    const float* fcsam_w2 = (const float*)d_in[22];
    const float* fcsam_b2 = (const float*)d_in[23];
    const float* fuse_w4  = (const float*)d_in[24];
    const float* fuse_bn4 = (const float*)d_in[25];
    float* out = (float*)d_out;

    float *pf, *x, *x2, *o1, *h, *aS_, *aC_, *bnA, *bnB;
    unsigned *colP, *wP;
    cudaGetSymbolAddress((void**)&pf,   g_pf);
    cudaGetSymbolAddress((void**)&x,    g_x);
    cudaGetSymbolAddress((void**)&x2,   g_x2);
    cudaGetSymbolAddress((void**)&o1,   g_o1);
    cudaGetSymbolAddress((void**)&h,    g_h);
    cudaGetSymbolAddress((void**)&aS_,  g_aS);
    cudaGetSymbolAddress((void**)&aC_,  g_aC);
    cudaGetSymbolAddress((void**)&colP, g_colP);
    cudaGetSymbolAddress((void**)&wP,   g_wP);
    cudaGetSymbolAddress((void**)&bnA,  g_bnA);
    cudaGetSymbolAddress((void**)&bnB,  g_bnB);

    const long SP  = (long)COUT * HW;
    const long SPH = (long)C4V * HW;
    const long SPS = (long)HW * HW;
    const long SPC = (long)COUT * COUT;
    const long SPP16  = 16L * NPAD * 16;     // packed plane K=256 (pixel rows)
    const long SPP32  = 32L * NPAD * 16;
    const long SPP64  = 64L * NPAD * 16;
    const long SPP144 = (long)NKT * NPAD * 16;
    const long SPA49  = 49L * 256 * 16;      // packWz plane K=784, 256 rows
    const long SPB49  = 49L * NPAD * 16;     // softmax-packed spatial attn
    const long SPA16  = 16L * 256 * 16;      // packed aC
    const long PACKC  = (long)B_SZ * NKT * HW;

    // 0. constants: BN prep + ALL weight packs in ONE launch
    bnprep4_kernel<<<4, 256>>>(ts_bn, fuse_bn1, fuse_bn2, fuse_bn4, bnA, bnB);
    packWall_kernel<<<(int)((WP_ROWS + 255) / 256), 256>>>(
        proj_w, ts_w3, fuse_w2, fuse_w4,
        ssam_w1, csam_w1, fcsam_w1,
        ssam_w2, csam_w2, fcsam_w2,
        fuse_w1, wP);

    // 1. per-frame 1x1 projection
    launch_gemm(5, wP + OFF_PROJ, feats, pf, COUT, HW, CIN,
                K_FR * COUT, HW, 4096, B_SZ, (long)CIN * HW, SP,
                nullptr, proj_b, COUT, 0, nullptr, nullptr, 0, K_FR * B_SZ);

    // 2. temporal shuffle + grouped 1x1 -> x
    {
        int total = B_SZ * COUT * HW;
        tshuffle_kernel<<<(total + 255) / 256, 256>>>(pf, ts_gw, ts_gb, x);
    }

    // 3. 3x3 conv + BN -> x2
    im2colpack_kernel<<<(int)((PACKC + 255) / 256), 256>>>(x, colP);
    launch_gemm(3, wP + OFF_CONV1, (const float*)colP, x2, COUT, HW, COUT * 9,
                COUT, NPAD, 0, 1, SPP144, SP,
                bnA + 0 * COUT, bnB + 0 * COUT, 0, 0, nullptr, nullptr, 0, B_SZ);

    // 4. spatial self-attention (input x2, output x)
    pack_kernel<<<(int)(((long)B_SZ * 16 * HW + 255) / 256), 256>>>(x2, colP + OFFa, 16, SP);
    packWz_kernel<<<(int)(((long)B_SZ * 256 * 49 + 255) / 256), 256>>>(x2, colP + OFFb, 256, HW, SP, SPA49);
    launch_gemm(4, colP + OFFa, (const float*)(colP + OFFa), aS_, HW, HW, COUT,
                NPAD, NPAD, SPP16, 1, SPP16, SPS,
                nullptr, nullptr, 0, 0, nullptr, nullptr, 0, B_SZ);
    softmax_packB784_kernel<<<B_SZ * HW, 256>>>(aS_, colP + OFFc, 0.0625f);
    launch_gemm(3, colP + OFFb, (const float*)(colP + OFFc), o1, COUT, HW, HW,
                256, NPAD, SPA49, 1, SPB49, SP,
                nullptr, nullptr, 0, 0, nullptr, nullptr, 0, B_SZ);
    pack_kernel<<<(int)(((long)B_SZ * 16 * HW + 255) / 256), 256>>>(o1, colP + OFFa, 16, SP);
    launch_gemm(4, wP + OFF_MLP1A, (const float*)(colP + OFFa), h, C4V, HW, COUT,
                C4V, NPAD, 0, 1, SPP16, SPH,
                nullptr, ssam_b1, 0, 1, nullptr, nullptr, 0, B_SZ);
    pack_kernel<<<(int)(((long)B_SZ * 64 * HW + 255) / 256), 256>>>(h, colP + OFFa, 64, SPH);
    launch_gemm(3, wP + OFF_MLP2A, (const float*)(colP + OFFa), x, COUT, HW, C4V,
                COUT, NPAD, 0, 1, SPP64, SP,
                nullptr, ssam_b2, 0, 0, ssam_g, x2, SP, B_SZ);

    // 5. channel self-attention (input x, output x2)
    packWz_kernel<<<(int)(((long)B_SZ * 256 * 49 + 255) / 256), 256>>>(x, colP + OFFa, 256, HW, SP, SPA49);
    launch_gemm(3, colP + OFFa, (const float*)(colP + OFFa), aC_, COUT, COUT, HW,
                256, 256, SPA49, 1, SPA49, SPC,
                nullptr, nullptr, 0, 0, nullptr, nullptr, 0, B_SZ);
    softmax_packA256_kernel<<<B_SZ * COUT, 256>>>(aC_, colP + OFFb, 0.0625f);
    pack_kernel<<<(int)(((long)B_SZ * 16 * HW + 255) / 256), 256>>>(x, colP + OFFc, 16, SP);
    launch_gemm(3, colP + OFFb, (const float*)(colP + OFFc), o1, COUT, HW, COUT,
                256, NPAD, SPA16, 1, SPP16, SP,
                nullptr, nullptr, 0, 0, nullptr, nullptr, 0, B_SZ);
    pack_kernel<<<(int)(((long)B_SZ * 16 * HW + 255) / 256), 256>>>(o1, colP + OFFa, 16, SP);
    launch_gemm(4, wP + OFF_MLP1B, (const float*)(colP + OFFa), h, C4V, HW, COUT,
                C4V, NPAD, 0, 1, SPP16, SPH,
                nullptr, csam_b1, 0, 1, nullptr, nullptr, 0, B_SZ);
    pack_kernel<<<(int)(((long)B_SZ * 64 * HW + 255) / 256), 256>>>(h, colP + OFFa, 64, SPH);
    launch_gemm(3, wP + OFF_MLP2B, (const float*)(colP + OFFa), x2, COUT, HW, C4V,
                COUT, NPAD, 0, 1, SPP64, SP,
                nullptr, csam_b2, 0, 0, nullptr, x, SP, B_SZ);

    // 6. fuse: concat keyframe feat (pf[K-1]) with x2 -> packed directly
    {
        long total = (long)B_SZ * 32 * HW;
        concatpack_kernel<<<(int)((total + 255) / 256), 256>>>(
            pf + (long)(K_FR - 1) * B_SZ * SP, x2, colP);
    }
    launch_gemm(3, wP + OFF_FUSE1, (const float*)colP, x, COUT, HW, 2 * COUT,
                COUT, NPAD, 0, 1, SPP32, SP,
                bnA + 1 * COUT, bnB + 1 * COUT, 0, 1, nullptr, nullptr, 0, B_SZ);

    // 7. 3x3 conv + BN + relu -> x2
    im2colpack_kernel<<<(int)((PACKC + 255) / 256), 256>>>(x, colP);
    launch_gemm(3, wP + OFF_CONV2, (const float*)colP, x2, COUT, HW, COUT * 9,
                COUT, NPAD, 0, 1, SPP144, SP,
                bnA + 2 * COUT, bnB + 2 * COUT, 0, 1, nullptr, nullptr, 0, B_SZ);

    // 8. channel self-attention (input x2, output x)
    packWz_kernel<<<(int)(((long)B_SZ * 256 * 49 + 255) / 256), 256>>>(x2, colP + OFFa, 256, HW, SP, SPA49);
    launch_gemm(3, colP + OFFa, (const float*)(colP + OFFa), aC_, COUT, COUT, HW,
                256, 256, SPA49, 1, SPA49, SPC,
                nullptr, nullptr, 0, 0, nullptr, nullptr, 0, B_SZ);
    softmax_packA256_kernel<<<B_SZ * COUT, 256>>>(aC_, colP + OFFb, 0.0625f);
    pack_kernel<<<(int)(((long)B_SZ * 16 * HW + 255) / 256), 256>>>(x2, colP + OFFc, 16, SP);
    launch_gemm(3, colP + OFFb, (const float*)(colP + OFFc), o1, COUT, HW, COUT,
                256, NPAD, SPA16, 1, SPP16, SP,
                nullptr, nullptr, 0, 0, nullptr, nullptr, 0, B_SZ);
    pack_kernel<<<(int)(((long)B_SZ * 16 * HW + 255) / 256), 256>>>(o1, colP + OFFa, 16, SP);
    launch_gemm(4, wP + OFF_MLP1C, (const float*)(colP + OFFa), h, C4V, HW, COUT,
                C4V, NPAD, 0, 1, SPP16, SPH,
                nullptr, fcsam_b1, 0, 1, nullptr, nullptr, 0, B_SZ);
    pack_kernel<<<(int)(((long)B_SZ * 64 * HW + 255) / 256), 256>>>(h, colP + OFFa, 64, SPH);
    launch_gemm(3, wP + OFF_MLP2C, (const float*)(colP + OFFa), x, COUT, HW, C4V,
                COUT, NPAD, 0, 1, SPP64, SP,
                nullptr, fcsam_b2, 0, 0, nullptr, x2, SP, B_SZ);

    // 9. final 3x3 conv + BN + relu -> d_out
    im2colpack_kernel<<<(int)((PACKC + 255) / 256), 256>>>(x, colP);
    launch_gemm(3, wP + OFF_CONV3, (const float*)colP, out, COUT, HW, COUT * 9,
                COUT, NPAD, 0, 1, SPP144, SP,
                bnA + 3 * COUT, bnB + 3 * COUT, 0, 1, nullptr, nullptr, 0, B_SZ);
}

// round 17
// speedup vs baseline: 2.4592x; 1.0962x over previous
#include <cuda_runtime.h>
#include <cuda_bf16.h>
#include <math.h>

#define K_FR 8
#define B_SZ 8
#define CIN  512
#define COUT 256
#define H_   28
#define W_   28
#define HW   784
#define C4V  1024
#define NKT  144          // max k-tiles (conv: 2304/16)
#define NPAD 896          // padded pixel rows per k-tile (7*128)

// packed-weight buffer offsets (uints)
#define OFF_PROJ   0L
#define OFF_CONV1  1048576L
#define OFF_CONV2  1638400L
#define OFF_CONV3  2228224L
#define OFF_MLP1A  2818048L
#define OFF_MLP1B  3080192L
#define OFF_MLP1C  3342336L
#define OFF_MLP2A  3604480L
#define OFF_MLP2B  3866624L
#define OFF_MLP2C  4128768L
#define OFF_FUSE1  4390912L
#define WP_TOTAL   4521984L
#define WP_ROWS    282624L   // WP_TOTAL / 16

// activation-pack regions (uints)
#define OFFa 0L
#define OFFb 2097152L
#define OFFc 4194304L

// ---------------- scratch (device globals; no allocation at runtime) --------
__device__ __align__(16) float g_pf  [K_FR * B_SZ * COUT * HW];
__device__ __align__(16) float g_x   [B_SZ * COUT * HW];
__device__ __align__(16) float g_x2  [B_SZ * COUT * HW];
__device__ __align__(16) float g_o1  [B_SZ * COUT * HW];
__device__ __align__(16) float g_h   [B_SZ * C4V * HW];
__device__ __align__(16) float g_aS  [B_SZ * HW * HW];
__device__ __align__(16) float g_aC  [B_SZ * COUT * COUT];
__device__ __align__(16) unsigned g_colP [(long)B_SZ * NKT * NPAD * 16];  // 66MB
__device__ __align__(16) unsigned g_wP   [WP_TOTAL];                      // 18MB packed weights
__device__ float g_bnA [4 * COUT];
__device__ float g_bnB [4 * COUT];

// ---------------- helpers ----------------------------------------------------
__device__ __forceinline__ unsigned pack2(float f0, float f1) {   // f0->low, f1->high
    unsigned r;
    asm("cvt.rn.bf16x2.f32 %0, %1, %2;" : "=r"(r) : "f"(f1), "f"(f0));
    return r;
}
__device__ __forceinline__ void split2(float f0, float f1, unsigned& hi, unsigned& lo) {
    hi = pack2(f0, f1);
    float h0 = __uint_as_float(hi << 16);
    float h1 = __uint_as_float(hi & 0xffff0000u);
    lo = pack2(f0 - h0, f1 - h1);
}
__device__ __forceinline__ void mma_bf16(float4& d, const unsigned a[4], const unsigned b[2]) {
    asm volatile(
        "mma.sync.aligned.m16n8k16.row.col.f32.bf16.bf16.f32 "
        "{%0,%1,%2,%3}, {%4,%5,%6,%7}, {%8,%9}, {%0,%1,%2,%3};"
        : "+f"(d.x), "+f"(d.y), "+f"(d.z), "+f"(d.w)
        : "r"(a[0]), "r"(a[1]), "r"(a[2]), "r"(a[3]), "r"(b[0]), "r"(b[1]));
}
__device__ __forceinline__ void cpasync16(unsigned saddr, const void* g) {
    asm volatile("cp.async.cg.shared.global [%0], [%1], 16;" :: "r"(saddr), "l"(g));
}
#define CP_COMMIT() asm volatile("cp.async.commit_group;" ::: "memory")
#define CP_WAIT2()  asm volatile("cp.async.wait_group 2;" ::: "memory")

#define RSTR 20
#define BN   128

__device__ __forceinline__ int posH(int p) { return 4 * (p & 3) + (p >> 2); }

// ---------------- fully-packed GEMM with cp.async 4-stage pipeline ----------
// A packed [kt][lda rows][16 uints], B packed [kt][ldb rows][16 uints].
// Requires Kd/16 >= 3 (all call sites: >=16).
template <int TBM, int MAXB>
__global__ void __launch_bounds__(256, MAXB) gemm_pk(
    const unsigned* __restrict__ A, const unsigned* __restrict__ Bm, float* __restrict__ C,
    int M, int N, int Kd, int lda, int ldb,
    long aS, int aDiv, long bS, long cS,
    const float* __restrict__ scaleC, const float* __restrict__ biasC, long biS,
    int relu, const float* __restrict__ gammaPtr,
    const float* __restrict__ resid, long rS)
{
    extern __shared__ unsigned sm[];
    unsigned* As = sm;                       // [4][TBM][16]
    unsigned* Bs = sm + 4 * TBM * 16;        // [4][BN ][16]

    const int z = blockIdx.z;
    A  += (long)(z / aDiv) * aS;
    Bm += (long)z * bS;
    C  += (long)z * cS;
    if (biasC) biasC += (long)(z / aDiv) * biS;
    if (resid) resid += (long)z * rS;

    const int tid  = threadIdx.x;
    const int lane = tid & 31, warp = tid >> 5;
    constexpr int MI = TBM / 32;
    constexpr int NJ = 4;
    constexpr int UAP = TBM / 64;
    const int wm = (warp >> 2) * (TBM / 2);
    const int wn = (warp & 3) * 32;
    const int m0 = blockIdx.y * TBM, n0 = blockIdx.x * BN;

    float4 acc[MI][NJ];
    #pragma unroll
    for (int i = 0; i < MI; ++i)
        #pragma unroll
        for (int j = 0; j < NJ; ++j)
            acc[i][j] = make_float4(0.f, 0.f, 0.f, 0.f);

    const uint4* ap = reinterpret_cast<const uint4*>(A);
    const uint4* bp = reinterpret_cast<const uint4*>(Bm);
    // per-thread smem dst (constant across stages up to stage offset)
    unsigned sA = (unsigned)__cvta_generic_to_shared(
        &As[(long)((tid >> 2)) * 16 + (tid & 3) * 4]);
    unsigned sB = (unsigned)__cvta_generic_to_shared(
        &Bs[(long)((tid >> 2)) * 16 + (tid & 3) * 4]);

    auto issue = [&](int t) {
        int stg = t & 3;
        long ab = ((long)t * lda + m0) * 4 + tid;
        #pragma unroll
        for (int i = 0; i < UAP; ++i)
            cpasync16(sA + (stg * TBM + i * 64) * 64, ap + ab + i * 256);
        long bb = ((long)t * ldb + n0) * 4 + tid;
        cpasync16(sB + (stg * BN) * 64, bp + bb);
        cpasync16(sB + (stg * BN + 64) * 64, bp + bb + 256);
    };
    auto compute = [&](int stg) {
        uint4 a0[MI], a1[MI], bv[NJ];
        #pragma unroll
        for (int i = 0; i < MI; ++i) {
            int r = wm + i * 16 + (lane >> 2);
            a0[i] = *(const uint4*)&As[(long)(stg * TBM + r) * 16 + ((lane & 3) << 2)];
            a1[i] = *(const uint4*)&As[(long)(stg * TBM + r + 8) * 16 + ((lane & 3) << 2)];
        }
        #pragma unroll
        for (int j = 0; j < NJ; ++j) {
            int c = wn + j * 8 + (lane >> 2);
            bv[j] = *(const uint4*)&Bs[(long)(stg * BN + c) * 16 + ((lane & 3) << 2)];
        }
        unsigned aH[MI][4], aL[MI][4], bH[NJ][2], bL[NJ][2];
        #pragma unroll
        for (int i = 0; i < MI; ++i) {
            aH[i][0] = a0[i].x; aH[i][1] = a1[i].x; aH[i][2] = a0[i].y; aH[i][3] = a1[i].y;
            aL[i][0] = a0[i].z; aL[i][1] = a1[i].z; aL[i][2] = a0[i].w; aL[i][3] = a1[i].w;
        }
        #pragma unroll
        for (int j = 0; j < NJ; ++j) {
            bH[j][0] = bv[j].x; bH[j][1] = bv[j].y;
            bL[j][0] = bv[j].z; bL[j][1] = bv[j].w;
        }
        #pragma unroll
        for (int j = 0; j < NJ; ++j)
            #pragma unroll
            for (int i = 0; i < MI; ++i)
                mma_bf16(acc[i][j], aH[i], bH[j]);
        #pragma unroll
        for (int j = 0; j < NJ; ++j)
            #pragma unroll
            for (int i = 0; i < MI; ++i)
                mma_bf16(acc[i][j], aH[i], bL[j]);
        #pragma unroll
        for (int j = 0; j < NJ; ++j)
            #pragma unroll
            for (int i = 0; i < MI; ++i)
                mma_bf16(acc[i][j], aL[i], bH[j]);
    };

    const int nt = Kd >> 4;   // >= 3 guaranteed
    issue(0); CP_COMMIT();
    issue(1); CP_COMMIT();
    issue(2); CP_COMMIT();

    for (int t = 0; t < nt; ++t) {
        CP_WAIT2();
        __syncthreads();
        if (t + 3 < nt) issue(t + 3);
        CP_COMMIT();          // empty group in tail keeps wait arithmetic exact
        compute(t & 3);
    }

    const float gmv = gammaPtr ? *gammaPtr : 1.f;
    #pragma unroll
    for (int i = 0; i < MI; ++i) {
        int r0 = m0 + wm + i * 16 + (lane >> 2);
        int r1 = r0 + 8;
        float sc0 = 1.f, bi0 = 0.f, sc1 = 1.f, bi1 = 0.f;
        if (scaleC) { if (r0 < M) sc0 = scaleC[r0]; if (r1 < M) sc1 = scaleC[r1]; }
        if (biasC)  { if (r0 < M) bi0 = biasC[r0];  if (r1 < M) bi1 = biasC[r1]; }
        #pragma unroll
        for (int j = 0; j < NJ; ++j) {
            int c = n0 + wn + j * 8 + ((lane & 3) << 1);
            float4 v = acc[i][j];
            if (r0 < M) {
                float x0 = v.x * sc0 + bi0, x1 = v.y * sc0 + bi0;
                if (relu) { x0 = fmaxf(x0, 0.f); x1 = fmaxf(x1, 0.f); }
                if (resid) {
                    if (c < N)     x0 = x0 * gmv + resid[(long)r0 * N + c];
                    if (c + 1 < N) x1 = x1 * gmv + resid[(long)r0 * N + c + 1];
                }
                if (c < N)     C[(long)r0 * N + c]     = x0;
                if (c + 1 < N) C[(long)r0 * N + c + 1] = x1;
            }
            if (r1 < M) {
                float y0 = v.z * sc1 + bi1, y1 = v.w * sc1 + bi1;
                if (relu) { y0 = fmaxf(y0, 0.f); y1 = fmaxf(y1, 0.f); }
                if (resid) {
                    if (c < N)     y0 = y0 * gmv + resid[(long)r1 * N + c];
                    if (c + 1 < N) y1 = y1 * gmv + resid[(long)r1 * N + c + 1];
                }
                if (c < N)     C[(long)r1 * N + c]     = y0;
                if (c + 1 < N) C[(long)r1 * N + c + 1] = y1;
            }
        }
    }
}

// ---------------- proj GEMM: A packed, B fp32 [K,N] (register staging) ------
__global__ void __launch_bounds__(256, 1) gemm_proj(
    const unsigned* __restrict__ A, const float* __restrict__ Bm, float* __restrict__ C,
    int M, int N, int Kd, int lda, int ldb,
    long aS, int aDiv, long bS, long cS,
    const float* __restrict__ biasC, long biS)
{
    constexpr int TBM = 128;
    constexpr int RSB = RSTR;
    extern __shared__ unsigned sm[];
    unsigned* As = sm;                       // [2][128][16]
    unsigned* Bs = sm + 2 * TBM * 16;        // [2][128][20]

    const int z = blockIdx.z;
    A  += (long)(z / aDiv) * aS;
    Bm += (long)z * bS;
    C  += (long)z * cS;
    if (biasC) biasC += (long)(z / aDiv) * biS;

    const int tid  = threadIdx.x;
    const int lane = tid & 31, warp = tid >> 5;
    constexpr int MI = 4, NJ = 4, UAP = 2, UB = 4;
    const int wm = (warp >> 2) * 64;
    const int wn = (warp & 3) * 32;
    const int m0 = blockIdx.y * TBM, n0 = blockIdx.x * BN;

    float4 acc[MI][NJ];
    #pragma unroll
    for (int i = 0; i < MI; ++i)
        #pragma unroll
        for (int j = 0; j < NJ; ++j)
            acc[i][j] = make_float4(0.f, 0.f, 0.f, 0.f);

    uint4 vaP[UAP];
    float2 vb[UB];

    auto loadA = [&](int k0) {
        const uint4* ap = reinterpret_cast<const uint4*>(A);
        long base = ((long)(k0 >> 4) * lda + m0) * 4;
        #pragma unroll
        for (int t = 0; t < UAP; ++t)
            vaP[t] = ap[base + tid + t * 256];
    };
    auto loadB = [&](int k0) {
        int n = tid & 127, psel = tid >> 7;
        int gn = n0 + n;
        #pragma unroll
        for (int t = 0; t < UB; ++t) {
            int p = psel * UB + t;
            float f0 = 0.f, f1 = 0.f;
            if (gn < N) {
                f0 = Bm[(long)(k0 + 2 * p) * ldb + gn];
                f1 = Bm[(long)(k0 + 2 * p + 1) * ldb + gn];
            }
            vb[t] = make_float2(f0, f1);
        }
    };
    auto storeA = [&](int buf) {
        #pragma unroll
        for (int t = 0; t < UAP; ++t)
            *(uint4*)&As[(long)(buf * TBM + (tid >> 2) + t * 64) * 16 + (tid & 3) * 4] = vaP[t];
    };
    auto storeB = [&](int buf) {
        int n = tid & 127, psel = tid >> 7;
        #pragma unroll
        for (int t = 0; t < UB; ++t) {
            int p = psel * UB + t;
            unsigned hi, lo;
            split2(vb[t].x, vb[t].y, hi, lo);
            unsigned* base = &Bs[(long)(buf * BN + n) * RSB];
            int ph = posH(p);
            base[ph]     = hi;
            base[ph + 2] = lo;
        }
    };
    auto compute = [&](int buf) {
        uint4 a0[MI], a1[MI], bv[NJ];
        #pragma unroll
        for (int i = 0; i < MI; ++i) {
            int r = wm + i * 16 + (lane >> 2);
            a0[i] = *(const uint4*)&As[(long)(buf * TBM + r) * 16 + ((lane & 3) << 2)];
            a1[i] = *(const uint4*)&As[(long)(buf * TBM + r + 8) * 16 + ((lane & 3) << 2)];
        }
        #pragma unroll
        for (int j = 0; j < NJ; ++j) {
            int c = wn + j * 8 + (lane >> 2);
            bv[j] = *(const uint4*)&Bs[(long)(buf * BN + c) * RSB + ((lane & 3) << 2)];
        }
        unsigned aH[MI][4], aL[MI][4], bH[NJ][2], bL[NJ][2];
        #pragma unroll
        for (int i = 0; i < MI; ++i) {
            aH[i][0] = a0[i].x; aH[i][1] = a1[i].x; aH[i][2] = a0[i].y; aH[i][3] = a1[i].y;
            aL[i][0] = a0[i].z; aL[i][1] = a1[i].z; aL[i][2] = a0[i].w; aL[i][3] = a1[i].w;
        }
        #pragma unroll
        for (int j = 0; j < NJ; ++j) {
            bH[j][0] = bv[j].x; bH[j][1] = bv[j].y;
            bL[j][0] = bv[j].z; bL[j][1] = bv[j].w;
        }
        #pragma unroll
        for (int j = 0; j < NJ; ++j)
            #pragma unroll
            for (int i = 0; i < MI; ++i)
                mma_bf16(acc[i][j], aH[i], bH[j]);
        #pragma unroll
        for (int j = 0; j < NJ; ++j)
            #pragma unroll
            for (int i = 0; i < MI; ++i)
                mma_bf16(acc[i][j], aH[i], bL[j]);
        #pragma unroll
        for (int j = 0; j < NJ; ++j)
            #pragma unroll
            for (int i = 0; i < MI; ++i)
                mma_bf16(acc[i][j], aL[i], bH[j]);
    };

    int buf = 0;
    loadA(0); loadB(0);
    storeA(0); storeB(0);
    __syncthreads();

    for (int k0 = 0; k0 < Kd; k0 += 16) {
        bool more = (k0 + 16) < Kd;
        if (more) { loadA(k0 + 16); loadB(k0 + 16); }
        compute(buf);
        if (more) {
            storeA(buf ^ 1); storeB(buf ^ 1);
            __syncthreads();
            buf ^= 1;
        }
    }

    #pragma unroll
    for (int i = 0; i < MI; ++i) {
        int r0 = m0 + wm + i * 16 + (lane >> 2);
        int r1 = r0 + 8;
        float bi0 = (biasC && r0 < M) ? biasC[r0] : 0.f;
        float bi1 = (biasC && r1 < M) ? biasC[r1] : 0.f;
        #pragma unroll
        for (int j = 0; j < NJ; ++j) {
            int c = n0 + wn + j * 8 + ((lane & 3) << 1);
            float4 v = acc[i][j];
            if (r0 < M) {
                if (c < N)     C[(long)r0 * N + c]     = v.x + bi0;
                if (c + 1 < N) C[(long)r0 * N + c + 1] = v.y + bi0;
            }
            if (r1 < M) {
                if (c < N)     C[(long)r1 * N + c]     = v.z + bi1;
                if (c + 1 < N) C[(long)r1 * N + c + 1] = v.w + bi1;
            }
        }
    }
}

// ---------------- pointwise / pack kernels ----------------------------------
__global__ void tshuffle_kernel(const float* __restrict__ pf,
                                const float* __restrict__ gw,
                                const float* __restrict__ gb,
                                float* __restrict__ out)
{
    int idx = blockIdx.x * blockDim.x + threadIdx.x;     // float4 units
    const int total4 = B_SZ * COUT * HW / 4;
    if (idx >= total4) return;
    int c = ((idx * 4) / HW) % COUT;
    float b = gb[c];
    float4 s = make_float4(b, b, b, b);
    #pragma unroll
    for (int k = 0; k < K_FR; ++k) {
        float w = gw[c * K_FR + k];
        float4 v = *(const float4*)&pf[(long)k * (B_SZ * COUT * HW) + (long)idx * 4];
        s.x = fmaf(v.x, w, s.x);
        s.y = fmaf(v.y, w, s.y);
        s.z = fmaf(v.z, w, s.z);
        s.w = fmaf(v.w, w, s.w);
    }
    *(float4*)&out[(long)idx * 4] = s;
}

__global__ void bnprep4_kernel(const float* __restrict__ p0,
                               const float* __restrict__ p1,
                               const float* __restrict__ p2,
                               const float* __restrict__ p3,
                               float* __restrict__ a, float* __restrict__ b)
{
    int c = threadIdx.x;
    int slot = blockIdx.x;
    const float* p = (slot == 0) ? p0 : (slot == 1) ? p1 : (slot == 2) ? p2 : p3;
    float g = p[c], be = p[COUT + c], m = p[2 * COUT + c], v = p[3 * COUT + c];
    float s = g * rsqrtf(v + 1e-5f);
    a[slot * COUT + c] = s;
    b[slot * COUT + c] = be - m * s;
}

// ALL 11 weight packs in one launch.
__global__ void packWall_kernel(
    const float* __restrict__ w0,  const float* __restrict__ w1,
    const float* __restrict__ w2,  const float* __restrict__ w3,
    const float* __restrict__ w4,  const float* __restrict__ w5,
    const float* __restrict__ w6,  const float* __restrict__ w7,
    const float* __restrict__ w8,  const float* __restrict__ w9,
    const float* __restrict__ w10, unsigned* __restrict__ dst)
{
    long idx = (long)blockIdx.x * blockDim.x + threadIdx.x;
    if (idx >= WP_ROWS) return;

    const float* src;
    long local;
    int M, K;
    if (idx < 65536L)        { src = w0;  local = idx;            M = 2048; K = 512;  }
    else if (idx < 102400L)  { src = w1;  local = idx - 65536L;   M = 256;  K = 2304; }
    else if (idx < 139264L)  { src = w2;  local = idx - 102400L;  M = 256;  K = 2304; }
    else if (idx < 176128L)  { src = w3;  local = idx - 139264L;  M = 256;  K = 2304; }
    else if (idx < 192512L)  { src = w4;  local = idx - 176128L;  M = 1024; K = 256;  }
    else if (idx < 208896L)  { src = w5;  local = idx - 192512L;  M = 1024; K = 256;  }
    else if (idx < 225280L)  { src = w6;  local = idx - 208896L;  M = 1024; K = 256;  }
    else if (idx < 241664L)  { src = w7;  local = idx - 225280L;  M = 256;  K = 1024; }
    else if (idx < 258048L)  { src = w8;  local = idx - 241664L;  M = 256;  K = 1024; }
    else if (idx < 274432L)  { src = w9;  local = idx - 258048L;  M = 256;  K = 1024; }
    else                     { src = w10; local = idx - 274432L;  M = 256;  K = 512;  }

    int kt = (int)(local / M);
    int m  = (int)(local - (long)kt * M);
    const float* s = src + (long)m * K + kt * 16;
    unsigned rr[16];
    #pragma unroll
    for (int p = 0; p < 8; ++p) {
        float2 v = *(const float2*)&s[2 * p];
        unsigned hi, lo;
        split2(v.x, v.y, hi, lo);
        int ph = posH(p);
        rr[ph]     = hi;
        rr[ph + 2] = lo;
    }
    unsigned* d = dst + idx * 16;
    *(uint4*)(d + 0)  = *(const uint4*)(rr + 0);
    *(uint4*)(d + 4)  = *(const uint4*)(rr + 4);
    *(uint4*)(d + 8)  = *(const uint4*)(rr + 8);
    *(uint4*)(d + 12) = *(const uint4*)(rr + 12);
}

// batched row-major pack: src [z][M][K] -> dst [z][K/16][M][16]
__global__ void packWz_kernel(const float* __restrict__ src, unsigned* __restrict__ dst,
                              int M, int K, long srcZ, long dstZ)
{
    long idx = (long)blockIdx.x * blockDim.x + threadIdx.x;
    long per = (long)M * (K >> 4);
    long total = (long)B_SZ * per;
    if (idx >= total) return;
    int z = (int)(idx / per);
    long rem = idx - (long)z * per;
    int kt = (int)(rem / M);
    int m  = (int)(rem - (long)kt * M);
    const float* s = src + (long)z * srcZ + (long)m * K + kt * 16;
    unsigned rr[16];
    #pragma unroll
    for (int p = 0; p < 8; ++p) {
        float2 v = *(const float2*)&s[2 * p];
        unsigned hi, lo;
        split2(v.x, v.y, hi, lo);
        int ph = posH(p);
        rr[ph]     = hi;
        rr[ph + 2] = lo;
    }
    unsigned* d = dst + (long)z * dstZ + rem * 16;
    *(uint4*)(d + 0)  = *(const uint4*)(rr + 0);
    *(uint4*)(d + 4)  = *(const uint4*)(rr + 4);
    *(uint4*)(d + 8)  = *(const uint4*)(rr + 8);
    *(uint4*)(d + 12) = *(const uint4*)(rr + 12);
}

// im2col + split + pack
__global__ void im2colpack_kernel(const float* __restrict__ x, unsigned* __restrict__ colP)
{
    long idx = (long)blockIdx.x * blockDim.x + threadIdx.x;
    const long total = (long)B_SZ * NKT * HW;
    if (idx >= total) return;
    int n  = (int)(idx % HW);
    long r = idx / HW;
    int kt = (int)(r % NKT);
    int z  = (int)(r / NKT);
    const float* xb = x + (long)z * COUT * HW;
    int h = n / W_, w = n % W_;

    unsigned rr[16];
    #pragma unroll
    for (int p = 0; p < 8; ++p) {
        int k0 = kt * 16 + 2 * p;
        float f0, f1;
        {
            int ci = k0 / 9, tq = k0 - ci * 9;
            int hh = h + tq / 3 - 1, ww = w + tq % 3 - 1;
            f0 = ((unsigned)hh < H_ && (unsigned)ww < W_) ? xb[(long)ci * HW + hh * W_ + ww] : 0.f;
        }
        {
            int k1 = k0 + 1;
            int ci = k1 / 9, tq = k1 - ci * 9;
            int hh = h + tq / 3 - 1, ww = w + tq % 3 - 1;
            f1 = ((unsigned)hh < H_ && (unsigned)ww < W_) ? xb[(long)ci * HW + hh * W_ + ww] : 0.f;
        }
        unsigned hi, lo;
        split2(f0, f1, hi, lo);
        int ph = posH(p);
        rr[ph]     = hi;
        rr[ph + 2] = lo;
    }
    unsigned* dst = colP + ((long)(z * NKT + kt) * NPAD + n) * 16;
    *(uint4*)(dst + 0)  = *(const uint4*)(rr + 0);
    *(uint4*)(dst + 4)  = *(const uint4*)(rr + 4);
    *(uint4*)(dst + 8)  = *(const uint4*)(rr + 8);
    *(uint4*)(dst + 12) = *(const uint4*)(rr + 12);
}

// generic pack: src [z][K][HW] -> [z][kt][n<NPAD][16]
__global__ void pack_kernel(const float* __restrict__ src, unsigned* __restrict__ colP,
                            int ktCount, long srcStride)
{
    long idx = (long)blockIdx.x * blockDim.x + threadIdx.x;
    const long total = (long)B_SZ * ktCount * HW;
    if (idx >= total) return;
    int n  = (int)(idx % HW);
    long r = idx / HW;
    int kt = (int)(r % ktCount);
    int z  = (int)(r / ktCount);
    const float* s = src + (long)z * srcStride + (long)(kt * 16) * HW + n;

    unsigned rr[16];
    #pragma unroll
    for (int p = 0; p < 8; ++p) {
        float f0 = s[(long)(2 * p) * HW];
        float f1 = s[(long)(2 * p + 1) * HW];
        unsigned hi, lo;
        split2(f0, f1, hi, lo);
        int ph = posH(p);
        rr[ph]     = hi;
        rr[ph + 2] = lo;
    }
    unsigned* dst = colP + ((long)(z * ktCount + kt) * NPAD + n) * 16;
    *(uint4*)(dst + 0)  = *(const uint4*)(rr + 0);
    *(uint4*)(dst + 4)  = *(const uint4*)(rr + 4);
    *(uint4*)(dst + 8)  = *(const uint4*)(rr + 8);
    *(uint4*)(dst + 12) = *(const uint4*)(rr + 12);
}

// concat keyframe feat with x2 AND pack (K=512 -> 32 k-tiles)
__global__ void concatpack_kernel(const float* __restrict__ kf,
                                  const float* __restrict__ x,
                                  unsigned* __restrict__ colP)
{
    const int KT = 32;
    long idx = (long)blockIdx.x * blockDim.x + threadIdx.x;
    const long total = (long)B_SZ * KT * HW;
    if (idx >= total) return;
    int n  = (int)(idx % HW);
    long r = idx / HW;
    int kt = (int)(r % KT);
    int z  = (int)(r / KT);
    const float* s = (kt < 16 ? kf + (long)z * COUT * HW + (long)(kt * 16) * HW
                              : x  + (long)z * COUT * HW + (long)((kt - 16) * 16) * HW) + n;

    unsigned rr[16];
    #pragma unroll
    for (int p = 0; p < 8; ++p) {
        float f0 = s[(long)(2 * p) * HW];
        float f1 = s[(long)(2 * p + 1) * HW];
        unsigned hi, lo;
        split2(f0, f1, hi, lo);
        int ph = posH(p);
        rr[ph]     = hi;
        rr[ph + 2] = lo;
    }
    unsigned* dst = colP + ((long)(z * KT + kt) * NPAD + n) * 16;
    *(uint4*)(dst + 0)  = *(const uint4*)(rr + 0);
    *(uint4*)(dst + 4)  = *(const uint4*)(rr + 4);
    *(uint4*)(dst + 8)  = *(const uint4*)(rr + 8);
    *(uint4*)(dst + 12) = *(const uint4*)(rr + 12);
}

// fused softmax + pack as B rows (spatial attn, len 784 -> 49 kt, rows < NPAD)
__global__ void softmax_packB784_kernel(const float* __restrict__ S,
                                        unsigned* __restrict__ dst, float scale)
{
    const float* p = S + (long)blockIdx.x * HW;
    int z = blockIdx.x / HW;
    int n = blockIdx.x % HW;
    __shared__ float red[256];
    int tid = threadIdx.x;
    float mx = -1e30f;
    for (int j = tid; j < HW; j += 256) mx = fmaxf(mx, p[j] * scale);
    red[tid] = mx; __syncthreads();
    for (int s = 128; s > 0; s >>= 1) {
        if (tid < s) red[tid] = fmaxf(red[tid], red[tid + s]);
        __syncthreads();
    }
    mx = red[0]; __syncthreads();
    float sum = 0.f;
    for (int j = tid; j < HW; j += 256) sum += expf(p[j] * scale - mx);
    red[tid] = sum; __syncthreads();
    for (int s = 128; s > 0; s >>= 1) {
        if (tid < s) red[tid] += red[tid + s];
        __syncthreads();
    }
    float inv = 1.f / red[0];
    unsigned* base = dst + (long)z * (49L * NPAD * 16);
    for (int pp = tid; pp < 392; pp += 256) {
        float v0 = expf(p[2 * pp] * scale - mx) * inv;
        float v1 = expf(p[2 * pp + 1] * scale - mx) * inv;
        unsigned hi, lo;
        split2(v0, v1, hi, lo);
        int kt = pp >> 3, pr = pp & 7;
        unsigned* d = base + ((long)kt * NPAD + n) * 16;
        int ph = posH(pr);
        d[ph]     = hi;
        d[ph + 2] = lo;
    }
}

// fused softmax + pack as A rows (channel attn, len 256 -> 16 kt, 256 rows)
__global__ void softmax_packA256_kernel(const float* __restrict__ S,
                                        unsigned* __restrict__ dst, float scale)
{
    const float* p = S + (long)blockIdx.x * COUT;
    int z = blockIdx.x / COUT;
    int i = blockIdx.x % COUT;
    __shared__ float red[256];
    int tid = threadIdx.x;
    float v = (tid < COUT) ? p[tid] * scale : -1e30f;
    red[tid] = v; __syncthreads();
    for (int s = 128; s > 0; s >>= 1) {
        if (tid < s) red[tid] = fmaxf(red[tid], red[tid + s]);
        __syncthreads();
    }
    float mx = red[0]; __syncthreads();
    float e = (tid < COUT) ? expf(p[tid] * scale - mx) : 0.f;
    red[tid] = e; __syncthreads();
    for (int s = 128; s > 0; s >>= 1) {
        if (tid < s) red[tid] += red[tid + s];
        __syncthreads();
    }
    float inv = 1.f / red[0];
    unsigned* base = dst + (long)z * (16L * 256 * 16);
    if (tid < 128) {
        int pp = tid;
        float v0 = expf(p[2 * pp] * scale - mx) * inv;
        float v1 = expf(p[2 * pp + 1] * scale - mx) * inv;
        unsigned hi, lo;
        split2(v0, v1, hi, lo);
        int kt = pp >> 3, pr = pp & 7;
        unsigned* d = base + ((long)kt * 256 + i) * 16;
        int ph = posH(pr);
        d[ph]     = hi;
        d[ph + 2] = lo;
    }
}

// ---------------- host-side helpers -----------------------------------------
static const int SMB_PK_SMALL = 4 * (64 + 128) * 16 * 4;        // 49152
static const int SMB_PK_BIG   = 4 * (128 + 128) * 16 * 4;       // 65536
static const int SMB_PROJ     = (2 * 128 * 16 + 2 * 128 * RSTR) * 4;  // 36864

// mode: 3 = small (64x128) packed; 4 = big (128x128) packed; 5 = proj
static void launch_gemm(int mode,
                        const unsigned* A, const float* B, float* C,
                        int M, int N, int Kd, int lda, int ldb,
                        long aS, int aDiv, long bS, long cS,
                        const float* sc, const float* bi, long biS,
                        int relu, const float* gp,
                        const float* res, long rS, int Z)
{
    dim3 block(256);
    if (mode == 5) {
        dim3 grid((N + 127) / 128, (M + 127) / 128, Z);
        cudaFuncSetAttribute(gemm_proj,
                             cudaFuncAttributeMaxDynamicSharedMemorySize, SMB_PROJ);
        gemm_proj<<<grid, block, SMB_PROJ>>>(A, B, C, M, N, Kd, lda, ldb,
            aS, aDiv, bS, cS, bi, biS);
        return;
    }
    if (mode == 4) {
        dim3 grid((N + 127) / 128, (M + 127) / 128, Z);
        cudaFuncSetAttribute(gemm_pk<128,1>,
                             cudaFuncAttributeMaxDynamicSharedMemorySize, SMB_PK_BIG);
        gemm_pk<128,1><<<grid, block, SMB_PK_BIG>>>(A, (const unsigned*)B, C, M, N, Kd, lda, ldb,
            aS, aDiv, bS, cS, sc, bi, biS, relu, gp, res, rS);
        return;
    }
    dim3 grid((N + 127) / 128, (M + 63) / 64, Z);
    cudaFuncSetAttribute(gemm_pk<64,2>,
                         cudaFuncAttributeMaxDynamicSharedMemorySize, SMB_PK_SMALL);
    gemm_pk<64,2><<<grid, block, SMB_PK_SMALL>>>(A, (const unsigned*)B, C, M, N, Kd, lda, ldb,
        aS, aDiv, bS, cS, sc, bi, biS, relu, gp, res, rS);
}

extern "C" void kernel_launch(void* const* d_in, const int* in_sizes, int n_in,
                              void* d_out, int out_size)
{
    const float* feats    = (const float*)d_in[0];
    const float* proj_w   = (const float*)d_in[1];
    const float* proj_b   = (const float*)d_in[2];
    const float* ts_gw    = (const float*)d_in[3];
    const float* ts_gb    = (const float*)d_in[4];
    const float* ts_w3    = (const float*)d_in[5];
    const float* ts_bn    = (const float*)d_in[6];
    const float* ssam_w1  = (const float*)d_in[7];
    const float* ssam_b1  = (const float*)d_in[8];
    const float* ssam_w2  = (const float*)d_in[9];
    const float* ssam_b2  = (const float*)d_in[10];
    const float* ssam_g   = (const float*)d_in[11];
    const float* csam_w1  = (const float*)d_in[12];
    const float* csam_b1  = (const float*)d_in[13];
    const float* csam_w2  = (const float*)d_in[14];
    const float* csam_b2  = (const float*)d_in[15];
    const float* fuse_w1  = (const float*)d_in[16];
    const float* fuse_bn1 = (const float*)d_in[17];
    const float* fuse_w2  = (const float*)d_in[18];
    const float* fuse_bn2 = (const float*)d_in[19];
    const float* fcsam_w1 = (const float*)d_in[20];
    const float* fcsam_b1 = (const float*)d_in[21];
    const float* fcsam_w2 = (const float*)d_in[22];
    const float* fcsam_b2 = (const float*)d_in[23];
    const float* fuse_w4  = (const float*)d_in[24];
    const float* fuse_bn4 = (const float*)d_in[25];
    float* out = (float*)d_out;

    float *pf, *x, *x2, *o1, *h, *aS_, *aC_, *bnA, *bnB;
    unsigned *colP, *wP;
    cudaGetSymbolAddress((void**)&pf,   g_pf);
    cudaGetSymbolAddress((void**)&x,    g_x);
    cudaGetSymbolAddress((void**)&x2,   g_x2);
    cudaGetSymbolAddress((void**)&o1,   g_o1);
    cudaGetSymbolAddress((void**)&h,    g_h);
    cudaGetSymbolAddress((void**)&aS_,  g_aS);
    cudaGetSymbolAddress((void**)&aC_,  g_aC);
    cudaGetSymbolAddress((void**)&colP, g_colP);
    cudaGetSymbolAddress((void**)&wP,   g_wP);
    cudaGetSymbolAddress((void**)&bnA,  g_bnA);
    cudaGetSymbolAddress((void**)&bnB,  g_bnB);

    const long SP  = (long)COUT * HW;
    const long SPH = (long)C4V * HW;
    const long SPS = (long)HW * HW;
    const long SPC = (long)COUT * COUT;
    const long SPP16  = 16L * NPAD * 16;
    const long SPP32  = 32L * NPAD * 16;
    const long SPP64  = 64L * NPAD * 16;
    const long SPP144 = (long)NKT * NPAD * 16;
    const long SPA49  = 49L * 256 * 16;
    const long SPB49  = 49L * NPAD * 16;
    const long SPA16  = 16L * 256 * 16;
    const long PACKC  = (long)B_SZ * NKT * HW;

    // 0. constants
    bnprep4_kernel<<<4, 256>>>(ts_bn, fuse_bn1, fuse_bn2, fuse_bn4, bnA, bnB);
    packWall_kernel<<<(int)((WP_ROWS + 255) / 256), 256>>>(
        proj_w, ts_w3, fuse_w2, fuse_w4,
        ssam_w1, csam_w1, fcsam_w1,
        ssam_w2, csam_w2, fcsam_w2,
        fuse_w1, wP);

    // 1. per-frame 1x1 projection
    launch_gemm(5, wP + OFF_PROJ, feats, pf, COUT, HW, CIN,
                K_FR * COUT, HW, 4096, B_SZ, (long)CIN * HW, SP,
                nullptr, proj_b, COUT, 0, nullptr, nullptr, 0, K_FR * B_SZ);

    // 2. temporal shuffle + grouped 1x1 -> x
    {
        int total4 = B_SZ * COUT * HW / 4;
        tshuffle_kernel<<<(total4 + 255) / 256, 256>>>(pf, ts_gw, ts_gb, x);
    }

    // 3. 3x3 conv + BN -> x2
    im2colpack_kernel<<<(int)((PACKC + 255) / 256), 256>>>(x, colP);
    launch_gemm(3, wP + OFF_CONV1, (const float*)colP, x2, COUT, HW, COUT * 9,
                COUT, NPAD, 0, 1, SPP144, SP,
                bnA + 0 * COUT, bnB + 0 * COUT, 0, 0, nullptr, nullptr, 0, B_SZ);

    // 4. spatial self-attention (input x2, output x)
    pack_kernel<<<(int)(((long)B_SZ * 16 * HW + 255) / 256), 256>>>(x2, colP + OFFa, 16, SP);
    packWz_kernel<<<(int)(((long)B_SZ * 256 * 49 + 255) / 256), 256>>>(x2, colP + OFFb, 256, HW, SP, SPA49);
    launch_gemm(4, colP + OFFa, (const float*)(colP + OFFa), aS_, HW, HW, COUT,
                NPAD, NPAD, SPP16, 1, SPP16, SPS,
                nullptr, nullptr, 0, 0, nullptr, nullptr, 0, B_SZ);
    softmax_packB784_kernel<<<B_SZ * HW, 256>>>(aS_, colP + OFFc, 0.0625f);
    launch_gemm(3, colP + OFFb, (const float*)(colP + OFFc), o1, COUT, HW, HW,
                256, NPAD, SPA49, 1, SPB49, SP,
                nullptr, nullptr, 0, 0, nullptr, nullptr, 0, B_SZ);
    pack_kernel<<<(int)(((long)B_SZ * 16 * HW + 255) / 256), 256>>>(o1, colP + OFFa, 16, SP);
    launch_gemm(4, wP + OFF_MLP1A, (const float*)(colP + OFFa), h, C4V, HW, COUT,
                C4V, NPAD, 0, 1, SPP16, SPH,
                nullptr, ssam_b1, 0, 1, nullptr, nullptr, 0, B_SZ);
    pack_kernel<<<(int)(((long)B_SZ * 64 * HW + 255) / 256), 256>>>(h, colP + OFFa, 64, SPH);
    launch_gemm(3, wP + OFF_MLP2A, (const float*)(colP + OFFa), x, COUT, HW, C4V,
                COUT, NPAD, 0, 1, SPP64, SP,
                nullptr, ssam_b2, 0, 0, ssam_g, x2, SP, B_SZ);

    // 5. channel self-attention (input x, output x2)
    packWz_kernel<<<(int)(((long)B_SZ * 256 * 49 + 255) / 256), 256>>>(x, colP + OFFa, 256, HW, SP, SPA49);
    launch_gemm(3, colP + OFFa, (const float*)(colP + OFFa), aC_, COUT, COUT, HW,
                256, 256, SPA49, 1, SPA49, SPC,
                nullptr, nullptr, 0, 0, nullptr, nullptr, 0, B_SZ);
    softmax_packA256_kernel<<<B_SZ * COUT, 256>>>(aC_, colP + OFFb, 0.0625f);
    pack_kernel<<<(int)(((long)B_SZ * 16 * HW + 255) / 256), 256>>>(x, colP + OFFc, 16, SP);
    launch_gemm(3, colP + OFFb, (const float*)(colP + OFFc), o1, COUT, HW, COUT,
                256, NPAD, SPA16, 1, SPP16, SP,
                nullptr, nullptr, 0, 0, nullptr, nullptr, 0, B_SZ);
    pack_kernel<<<(int)(((long)B_SZ * 16 * HW + 255) / 256), 256>>>(o1, colP + OFFa, 16, SP);
    launch_gemm(4, wP + OFF_MLP1B, (const float*)(colP + OFFa), h, C4V, HW, COUT,
                C4V, NPAD, 0, 1, SPP16, SPH,
                nullptr, csam_b1, 0, 1, nullptr, nullptr, 0, B_SZ);
    pack_kernel<<<(int)(((long)B_SZ * 64 * HW + 255) / 256), 256>>>(h, colP + OFFa, 64, SPH);
    launch_gemm(3, wP + OFF_MLP2B, (const float*)(colP + OFFa), x2, COUT, HW, C4V,
                COUT, NPAD, 0, 1, SPP64, SP,
                nullptr, csam_b2, 0, 0, nullptr, x, SP, B_SZ);

    // 6. fuse: concat keyframe feat (pf[K-1]) with x2 -> packed directly
    {
        long total = (long)B_SZ * 32 * HW;
        concatpack_kernel<<<(int)((total + 255) / 256), 256>>>(
            pf + (long)(K_FR - 1) * B_SZ * SP, x2, colP);
    }
    launch_gemm(3, wP + OFF_FUSE1, (const float*)colP, x, COUT, HW, 2 * COUT,
                COUT, NPAD, 0, 1, SPP32, SP,
                bnA + 1 * COUT, bnB + 1 * COUT, 0, 1, nullptr, nullptr, 0, B_SZ);

    // 7. 3x3 conv + BN + relu -> x2
    im2colpack_kernel<<<(int)((PACKC + 255) / 256), 256>>>(x, colP);
    launch_gemm(3, wP + OFF_CONV2, (const float*)colP, x2, COUT, HW, COUT * 9,
                COUT, NPAD, 0, 1, SPP144, SP,
                bnA + 2 * COUT, bnB + 2 * COUT, 0, 1, nullptr, nullptr, 0, B_SZ);

    // 8. channel self-attention (input x2, output x)
    packWz_kernel<<<(int)(((long)B_SZ * 256 * 49 + 255) / 256), 256>>>(x2, colP + OFFa, 256, HW, SP, SPA49);
    launch_gemm(3, colP + OFFa, (const float*)(colP + OFFa), aC_, COUT, COUT, HW,
                256, 256, SPA49, 1, SPA49, SPC,
                nullptr, nullptr, 0, 0, nullptr, nullptr, 0, B_SZ);
    softmax_packA256_kernel<<<B_SZ * COUT, 256>>>(aC_, colP + OFFb, 0.0625f);
    pack_kernel<<<(int)(((long)B_SZ * 16 * HW + 255) / 256), 256>>>(x2, colP + OFFc, 16, SP);
    launch_gemm(3, colP + OFFb, (const float*)(colP + OFFc), o1, COUT, HW, COUT,
                256, NPAD, SPA16, 1, SPP16, SP,
                nullptr, nullptr, 0, 0, nullptr, nullptr, 0, B_SZ);
    pack_kernel<<<(int)(((long)B_SZ * 16 * HW + 255) / 256), 256>>>(o1, colP + OFFa, 16, SP);
    launch_gemm(4, wP + OFF_MLP1C, (const float*)(colP + OFFa), h, C4V, HW, COUT,
                C4V, NPAD, 0, 1, SPP16, SPH,
                nullptr, fcsam_b1, 0, 1, nullptr, nullptr, 0, B_SZ);
    pack_kernel<<<(int)(((long)B_SZ * 64 * HW + 255) / 256), 256>>>(h, colP + OFFa, 64, SPH);
    launch_gemm(3, wP + OFF_MLP2C, (const float*)(colP + OFFa), x, COUT, HW, C4V,
                COUT, NPAD, 0, 1, SPP64, SP,
                nullptr, fcsam_b2, 0, 0, nullptr, x2, SP, B_SZ);

    // 9. final 3x3 conv + BN + relu -> d_out
    im2colpack_kernel<<<(int)((PACKC + 255) / 256), 256>>>(x, colP);
    launch_gemm(3, wP + OFF_CONV3, (const float*)colP, out, COUT, HW, COUT * 9,
                COUT, NPAD, 0, 1, SPP144, SP,
                bnA + 3 * COUT, bnB + 3 * COUT, 0, 1, nullptr, nullptr, 0, B_SZ);
}